// round 1
// baseline (speedup 1.0000x reference)
#include <cuda_runtime.h>
#include <math.h>

#define BB 8
#define CC 128
#define PP 96
#define DD 128
#define HH 8
#define GG 512
#define TPB (CC*PP)          // 12288 tokens per batch
#define NTOK (BB*TPB)        // 98304
#define NELEM (NTOK*DD)      // 12582912

// ---------------- scratch (device globals: allocation-free) ----------------
__device__ __align__(16) float g_qzn[NELEM];
__device__ __align__(16) float g_qut[NELEM];
__device__ __align__(16) float g_qvt[NELEM];
__device__ __align__(16) float g_quc[NELEM];
__device__ __align__(16) float g_qvc[NELEM];
__device__ __align__(16) float g_msg[NELEM];

// ---------------- K1: layernorm -> g_qzn ----------------
__global__ __launch_bounds__(256) void k_ln(const float* __restrict__ x,
                                            const float* __restrict__ gw,
                                            const float* __restrict__ gb) {
    int w = (blockIdx.x * 256 + threadIdx.x) >> 5;
    int lane = threadIdx.x & 31;
    if (w >= NTOK) return;
    const float* xr = x + (size_t)w * DD;
    float v[4];
#pragma unroll
    for (int j = 0; j < 4; j++) v[j] = xr[lane + 32*j];
    float s = v[0] + v[1] + v[2] + v[3];
#pragma unroll
    for (int o = 16; o; o >>= 1) s += __shfl_xor_sync(0xffffffffu, s, o);
    float mu = s * (1.0f/128.0f);
    float q = 0.0f;
#pragma unroll
    for (int j = 0; j < 4; j++) { float c = v[j] - mu; q += c * c; }
#pragma unroll
    for (int o = 16; o; o >>= 1) q += __shfl_xor_sync(0xffffffffu, q, o);
    float inv = rsqrtf(q * (1.0f/128.0f) + 1e-5f);
    float* yr = g_qzn + (size_t)w * DD;
#pragma unroll
    for (int j = 0; j < 4; j++) {
        int d = lane + 32*j;
        yr[d] = (v[j] - mu) * inv * gw[d] + gb[d];
    }
}

// ---------------- K2: per-batch projection y[t,o] = sum_d qzn[t,d]*W[b,o,d] ----
#define SM_PROJ ((64*129 + 128*129)*4)
__global__ __launch_bounds__(256) void k_proj(const float* __restrict__ w,
                                              float* __restrict__ y) {
    extern __shared__ float sm[];
    float* Xs = sm;               // 64 x 129
    float* Ws = sm + 64*129;      // 128 x 129
    int b = blockIdx.y;
    int t0 = blockIdx.x * 64;
    const float* xb = g_qzn + ((size_t)b * TPB + t0) * DD;
    const float* wb = w + (size_t)b * DD * DD;
    int tid = threadIdx.x, lane = tid & 31, wg = tid >> 5;
    for (int i = tid; i < 64*128; i += 256) Xs[(i>>7)*129 + (i&127)] = xb[i];
    for (int i = tid; i < 128*128; i += 256) Ws[(i>>7)*129 + (i&127)] = wb[i];
    __syncthreads();
    float acc[8][4];
#pragma unroll
    for (int k = 0; k < 8; k++)
#pragma unroll
        for (int j = 0; j < 4; j++) acc[k][j] = 0.f;
    for (int d = 0; d < 128; d++) {
        float wr[4];
#pragma unroll
        for (int j = 0; j < 4; j++) wr[j] = Ws[(lane + 32*j)*129 + d];
#pragma unroll
        for (int k = 0; k < 8; k++) {
            float xv = Xs[(wg + 8*k)*129 + d];
#pragma unroll
            for (int j = 0; j < 4; j++) acc[k][j] += xv * wr[j];
        }
    }
    float* yb = y + ((size_t)b * TPB + t0) * DD;
#pragma unroll
    for (int k = 0; k < 8; k++)
#pragma unroll
        for (int j = 0; j < 4; j++)
            yb[(size_t)(wg + 8*k)*DD + lane + 32*j] = acc[k][j];
}

// ---------------- K3: time attention -> g_msg (first writer) ----------------
#define SM_TATTN ((3*96*129 + 96*97)*4)
__global__ __launch_bounds__(256) void k_tattn() {
    extern __shared__ float sm[];
    float* Xs = sm;                 // 96 x 129
    float* Qu = Xs + 96*129;
    float* Qv = Qu + 96*129;
    float* As = Qv + 96*129;        // 96 x 97
    int tid = threadIdx.x, lane = tid & 31, wg = tid >> 5;
    size_t base = (size_t)blockIdx.x * PP * DD;
    for (int i = tid; i < PP*DD; i += 256) {
        int r = i >> 7, d = i & 127;
        Xs[r*129+d] = g_qzn[base + i];
        Qu[r*129+d] = g_qut[base + i];
        Qv[r*129+d] = g_qvt[base + i];
    }
    __syncthreads();
    float acc[12][4];
#pragma unroll
    for (int k = 0; k < 12; k++)
#pragma unroll
        for (int j = 0; j < 4; j++) acc[k][j] = 0.f;

    for (int h = 0; h < HH; h++) {
        int ho = h * 16;
#pragma unroll 1
        for (int pr = 0; pr < 12; pr++) {
            int p = wg + 8*pr;
            float qur[16];
#pragma unroll
            for (int r = 0; r < 16; r++) qur[r] = Qu[p*129 + ho + r];
            float lg[3];
#pragma unroll
            for (int qi = 0; qi < 3; qi++) {
                int q = lane + 32*qi;
                float s = 0.f;
#pragma unroll
                for (int r = 0; r < 16; r++) s += qur[r] * Qv[q*129 + ho + r];
                lg[qi] = s * 0.25f;
            }
            float mx = fmaxf(lg[0], fmaxf(lg[1], lg[2]));
#pragma unroll
            for (int o = 16; o; o >>= 1) mx = fmaxf(mx, __shfl_xor_sync(0xffffffffu, mx, o));
            float e0 = expf(lg[0]-mx), e1 = expf(lg[1]-mx), e2 = expf(lg[2]-mx);
            float ssum = e0 + e1 + e2;
#pragma unroll
            for (int o = 16; o; o >>= 1) ssum += __shfl_xor_sync(0xffffffffu, ssum, o);
            float inv = 0.125f / ssum;            // fold 1/H
            As[p*97 + lane]      = e0 * inv;
            As[p*97 + lane + 32] = e1 * inv;
            As[p*97 + lane + 64] = e2 * inv;
        }
        __syncthreads();
#pragma unroll 2
        for (int q = 0; q < PP; q++) {
            float xv[4];
#pragma unroll
            for (int j = 0; j < 4; j++) xv[j] = Xs[q*129 + lane + 32*j];
#pragma unroll
            for (int k = 0; k < 12; k++) {
                float a = As[(wg + 8*k)*97 + q];
#pragma unroll
                for (int j = 0; j < 4; j++) acc[k][j] += a * xv[j];
            }
        }
        __syncthreads();
    }
#pragma unroll
    for (int k = 0; k < 12; k++) {
        int p = wg + 8*k;
#pragma unroll
        for (int j = 0; j < 4; j++)
            g_msg[base + (size_t)p*DD + lane + 32*j] = acc[k][j];
    }
}

// ---------------- K4: channel attention -> g_msg += ----------------
#define SM_CATTN (3*128*129*4)
__global__ __launch_bounds__(256) void k_cattn() {
    extern __shared__ float sm[];
    float* Qu = sm;                 // 128 x 129
    float* Qv = Qu + 128*129;
    float* Ac = Qv + 128*129;
    int b = blockIdx.x / PP, p = blockIdx.x % PP;
    int tid = threadIdx.x, lane = tid & 31, wg = tid >> 5;
    for (int i = tid; i < CC*DD; i += 256) {
        int c = i >> 7, d = i & 127;
        size_t gi = (((size_t)b*CC + c)*PP + p)*DD + d;
        Qu[c*129+d] = g_quc[gi];
        Qv[c*129+d] = g_qvc[gi];
        Ac[c*129+d] = 0.f;
    }
    __syncthreads();
    for (int h = 0; h < HH; h++) {
        int ho = h*16;
#pragma unroll 1
        for (int cr = 0; cr < 16; cr++) {
            int c = wg + 8*cr;
            float qur[16];
#pragma unroll
            for (int r = 0; r < 16; r++) qur[r] = Qu[c*129 + ho + r];
            float lg[4];
#pragma unroll
            for (int j = 0; j < 4; j++) {
                int d = lane + 32*j;
                float s = 0.f;
#pragma unroll
                for (int r = 0; r < 16; r++) s += qur[r] * Qv[d*129 + ho + r];
                lg[j] = s * 0.25f;
            }
            float mx = fmaxf(fmaxf(lg[0], lg[1]), fmaxf(lg[2], lg[3]));
#pragma unroll
            for (int o = 16; o; o >>= 1) mx = fmaxf(mx, __shfl_xor_sync(0xffffffffu, mx, o));
            float e[4], ssum = 0.f;
#pragma unroll
            for (int j = 0; j < 4; j++) { e[j] = expf(lg[j] - mx); ssum += e[j]; }
#pragma unroll
            for (int o = 16; o; o >>= 1) ssum += __shfl_xor_sync(0xffffffffu, ssum, o);
            float inv = 0.125f / ssum;            // fold 1/H
#pragma unroll
            for (int j = 0; j < 4; j++) Ac[c*129 + lane + 32*j] += e[j] * inv;
        }
    }
    // each (c,d) is owned by the same thread that wrote Ac -> no sync needed
#pragma unroll
    for (int cr = 0; cr < 16; cr++) {
        int c = wg + 8*cr;
#pragma unroll
        for (int j = 0; j < 4; j++) {
            int d = lane + 32*j;
            size_t gi = (((size_t)b*CC + c)*PP + p)*DD + d;
            g_msg[gi] += Ac[c*129+d] * g_qzn[gi];
        }
    }
}

// ---------------- K5: topic messages -> g_msg += ----------------
#define SM_TOPIC ((32*129 + 32*516 + 64*129)*4)
__global__ __launch_bounds__(256) void k_topic(const float* __restrict__ bin) {
    extern __shared__ float sm[];
    float* Xs = sm;                 // 32 x 129
    float* S  = Xs + 32*129;        // 32 x 516
    float* Bs = S + 32*516;         // 64 x 129
    int b  = blockIdx.x / 384;
    int t0 = (blockIdx.x % 384) * 32;
    int tid = threadIdx.x, lane = tid & 31, wg = tid >> 5;
    const float* xb = g_qzn + ((size_t)b*TPB + t0)*DD;
    const float* binb = bin + (size_t)b * GG * DD;
    for (int i = tid; i < 32*128; i += 256) Xs[(i>>7)*129 + (i&127)] = xb[i];

    // pass 1: scores
    for (int gc = 0; gc < 8; gc++) {
        __syncthreads();
        for (int i = tid; i < 64*128; i += 256)
            Bs[(i>>7)*129 + (i&127)] = binb[(size_t)gc*64*128 + i];
        __syncthreads();
        float sacc[4][2];
#pragma unroll
        for (int k = 0; k < 4; k++) { sacc[k][0] = 0.f; sacc[k][1] = 0.f; }
        for (int d = 0; d < 128; d++) {
            float bv0 = Bs[lane*129 + d];
            float bv1 = Bs[(lane+32)*129 + d];
#pragma unroll
            for (int k = 0; k < 4; k++) {
                float xv = Xs[(wg + 8*k)*129 + d];
                sacc[k][0] += xv * bv0;
                sacc[k][1] += xv * bv1;
            }
        }
#pragma unroll
        for (int k = 0; k < 4; k++) {
            S[(wg+8*k)*516 + gc*64 + lane]      = fmaxf(sacc[k][0], 0.f);
            S[(wg+8*k)*516 + gc*64 + lane + 32] = fmaxf(sacc[k][1], 0.f);
        }
    }
    __syncthreads();
    // normalize rows (L1) in place
#pragma unroll 1
    for (int tt = 0; tt < 4; tt++) {
        int t = wg*4 + tt;
        float s = 0.f;
#pragma unroll
        for (int m = 0; m < 16; m++) s += S[t*516 + lane + 32*m];
#pragma unroll
        for (int o = 16; o; o >>= 1) s += __shfl_xor_sync(0xffffffffu, s, o);
        float inv = 1.0f / fmaxf(s, 1e-6f);
#pragma unroll
        for (int m = 0; m < 16; m++) S[t*516 + lane + 32*m] *= inv;
    }
    // pass 2: weighted sum
    float acc[4][4];
#pragma unroll
    for (int k = 0; k < 4; k++)
#pragma unroll
        for (int j = 0; j < 4; j++) acc[k][j] = 0.f;
    for (int gc = 0; gc < 8; gc++) {
        __syncthreads();
        for (int i = tid; i < 64*128; i += 256)
            Bs[(i>>7)*129 + (i&127)] = binb[(size_t)gc*64*128 + i];
        __syncthreads();
#pragma unroll 2
        for (int gl = 0; gl < 64; gl++) {
            float wv[4];
#pragma unroll
            for (int j = 0; j < 4; j++) wv[j] = Bs[gl*129 + lane + 32*j];
#pragma unroll
            for (int k = 0; k < 4; k++) {
                float sv = S[(wg+8*k)*516 + gc*64 + gl];
#pragma unroll
                for (int j = 0; j < 4; j++) acc[k][j] += sv * wv[j];
            }
        }
    }
    float* outb = g_msg + ((size_t)b*TPB + t0)*DD;
#pragma unroll
    for (int k = 0; k < 4; k++)
#pragma unroll
        for (int j = 0; j < 4; j++)
            outb[(size_t)(wg+8*k)*DD + lane + 32*j] += acc[k][j];
}

// ---------------- K6: combine -> d_out = 0.5*(unary + msg + old) ----------------
__global__ __launch_bounds__(256) void k_combine(const float4* __restrict__ un,
                                                 const float4* __restrict__ old,
                                                 float4* __restrict__ out) {
    int i = blockIdx.x * 256 + threadIdx.x;
    if (i >= NELEM/4) return;
    const float4* m4 = reinterpret_cast<const float4*>(g_msg);
    float4 u = un[i], o = old[i], m = m4[i];
    float4 r;
    r.x = 0.5f*(u.x + m.x + o.x);
    r.y = 0.5f*(u.y + m.y + o.y);
    r.z = 0.5f*(u.z + m.z + o.z);
    r.w = 0.5f*(u.w + m.w + o.w);
    out[i] = r;
}

// ---------------- K7: LN + MLP (gelu exact) + residual, in-place on d_out ------
#define SM_MLP ((2*128*129 + 2*64*129)*4)
__global__ __launch_bounds__(256) void k_mlp(float* __restrict__ io,
                                             const float* __restrict__ gw,
                                             const float* __restrict__ gb,
                                             const float* __restrict__ w1,
                                             const float* __restrict__ b1,
                                             const float* __restrict__ w2,
                                             const float* __restrict__ b2) {
    extern __shared__ float sm[];
    float* W1s = sm;                // 128 x 129
    float* W2s = W1s + 128*129;
    float* Hs  = W2s + 128*129;     // 64 x 129
    float* As  = Hs + 64*129;
    int tid = threadIdx.x, lane = tid & 31, wg = tid >> 5;
    size_t base = (size_t)blockIdx.x * 64 * DD;
    for (int i = tid; i < 128*128; i += 256) {
        int r = i >> 7, d = i & 127;
        W1s[r*129+d] = w1[i];
        W2s[r*129+d] = w2[i];
    }
    // LN: warp per token
#pragma unroll 1
    for (int it = 0; it < 8; it++) {
        int t = wg + 8*it;
        const float* xr = io + base + (size_t)t*DD;
        float v[4];
#pragma unroll
        for (int j = 0; j < 4; j++) v[j] = xr[lane + 32*j];
        float s = v[0]+v[1]+v[2]+v[3];
#pragma unroll
        for (int o = 16; o; o >>= 1) s += __shfl_xor_sync(0xffffffffu, s, o);
        float mu = s * (1.0f/128.0f);
        float q = 0.f;
#pragma unroll
        for (int j = 0; j < 4; j++) { float c = v[j]-mu; q += c*c; }
#pragma unroll
        for (int o = 16; o; o >>= 1) q += __shfl_xor_sync(0xffffffffu, q, o);
        float inv = rsqrtf(q * (1.0f/128.0f) + 1e-5f);
#pragma unroll
        for (int j = 0; j < 4; j++) {
            int d = lane + 32*j;
            Hs[t*129+d] = (v[j]-mu)*inv*gw[d] + gb[d];
        }
    }
    __syncthreads();
    // GEMM1 + bias + gelu(exact)
    float acc[8][4];
#pragma unroll
    for (int k = 0; k < 8; k++)
#pragma unroll
        for (int j = 0; j < 4; j++) acc[k][j] = 0.f;
    for (int d = 0; d < 128; d++) {
        float wr[4];
#pragma unroll
        for (int j = 0; j < 4; j++) wr[j] = W1s[(lane + 32*j)*129 + d];
#pragma unroll
        for (int k = 0; k < 8; k++) {
            float xv = Hs[(wg + 8*k)*129 + d];
#pragma unroll
            for (int j = 0; j < 4; j++) acc[k][j] += xv * wr[j];
        }
    }
#pragma unroll
    for (int k = 0; k < 8; k++)
#pragma unroll
        for (int j = 0; j < 4; j++) {
            int o = lane + 32*j;
            float x = acc[k][j] + b1[o];
            float g = 0.5f * x * (1.0f + erff(x * 0.70710678118654752f));
            As[(wg+8*k)*129 + o] = g;
        }
    __syncthreads();
    // GEMM2 + bias + residual
    float acc2[8][4];
#pragma unroll
    for (int k = 0; k < 8; k++)
#pragma unroll
        for (int j = 0; j < 4; j++) acc2[k][j] = 0.f;
    for (int d = 0; d < 128; d++) {
        float wr[4];
#pragma unroll
        for (int j = 0; j < 4; j++) wr[j] = W2s[(lane + 32*j)*129 + d];
#pragma unroll
        for (int k = 0; k < 8; k++) {
            float xv = As[(wg + 8*k)*129 + d];
#pragma unroll
            for (int j = 0; j < 4; j++) acc2[k][j] += xv * wr[j];
        }
    }
#pragma unroll
    for (int k = 0; k < 8; k++)
#pragma unroll
        for (int j = 0; j < 4; j++) {
            int o = lane + 32*j;
            size_t idx = base + (size_t)(wg+8*k)*DD + o;
            io[idx] = io[idx] + acc2[k][j] + b2[o];
        }
}

// ---------------- host launcher ----------------
extern "C" void kernel_launch(void* const* d_in, const int* in_sizes, int n_in,
                              void* d_out, int out_size) {
    (void)in_sizes; (void)n_in; (void)out_size;
    const float* qz  = (const float*)d_in[0];
    const float* un  = (const float*)d_in[1];
    const float* tu  = (const float*)d_in[2];
    const float* tv  = (const float*)d_in[3];
    const float* cu  = (const float*)d_in[4];
    const float* cv  = (const float*)d_in[5];
    const float* bin = (const float*)d_in[6];
    const float* lng = (const float*)d_in[7];
    const float* lnb = (const float*)d_in[8];
    const float* w1  = (const float*)d_in[9];
    const float* b1  = (const float*)d_in[10];
    const float* w2  = (const float*)d_in[11];
    const float* b2  = (const float*)d_in[12];
    float* out = (float*)d_out;

    float *qut, *qvt, *quc, *qvc;
    cudaGetSymbolAddress((void**)&qut, g_qut);
    cudaGetSymbolAddress((void**)&qvt, g_qvt);
    cudaGetSymbolAddress((void**)&quc, g_quc);
    cudaGetSymbolAddress((void**)&qvc, g_qvc);

    cudaFuncSetAttribute(k_proj,  cudaFuncAttributeMaxDynamicSharedMemorySize, SM_PROJ);
    cudaFuncSetAttribute(k_tattn, cudaFuncAttributeMaxDynamicSharedMemorySize, SM_TATTN);
    cudaFuncSetAttribute(k_cattn, cudaFuncAttributeMaxDynamicSharedMemorySize, SM_CATTN);
    cudaFuncSetAttribute(k_topic, cudaFuncAttributeMaxDynamicSharedMemorySize, SM_TOPIC);
    cudaFuncSetAttribute(k_mlp,   cudaFuncAttributeMaxDynamicSharedMemorySize, SM_MLP);

    k_ln<<<(NTOK*32)/256, 256>>>(qz, lng, lnb);

    dim3 pg(TPB/64, BB);
    k_proj<<<pg, 256, SM_PROJ>>>(tu, qut);
    k_proj<<<pg, 256, SM_PROJ>>>(tv, qvt);
    k_proj<<<pg, 256, SM_PROJ>>>(cu, quc);
    k_proj<<<pg, 256, SM_PROJ>>>(cv, qvc);

    k_tattn<<<BB*CC, 256, SM_TATTN>>>();
    k_cattn<<<BB*PP, 256, SM_CATTN>>>();
    k_topic<<<BB*384, 256, SM_TOPIC>>>(bin);

    k_combine<<<(NELEM/4 + 255)/256, 256>>>((const float4*)un, (const float4*)qz,
                                            (float4*)out);
    k_mlp<<<NTOK/64, 256, SM_MLP>>>(out, lng, lnb, w1, b1, w2, b2);
}

// round 2
// speedup vs baseline: 1.2144x; 1.2144x over previous
#include <cuda_runtime.h>
#include <math.h>

#define BB 8
#define CC 128
#define PP 96
#define DD 128
#define HH 8
#define GG 512
#define TPB (CC*PP)          // 12288 tokens per batch
#define NTOK (BB*TPB)        // 98304
#define NELEM (NTOK*DD)      // 12582912

#define PSTR 132             // padded row stride (16B-aligned quads, bank-spread)
#define ASTR 98              // attention prob row stride (even => 8B aligned pairs)

typedef unsigned long long u64;

__device__ __forceinline__ u64 pk2(float x) {
    u64 r; asm("mov.b64 %0,{%1,%1};" : "=l"(r) : "f"(x)); return r;
}
__device__ __forceinline__ u64 fma2(u64 a, u64 b, u64 c) {
    asm("fma.rn.f32x2 %0,%1,%2,%0;" : "+l"(c) : "l"(a), "l"(b)); return c;
}
__device__ __forceinline__ float2 up2(u64 v) {
    float2 f; asm("mov.b64 {%0,%1},%2;" : "=f"(f.x), "=f"(f.y) : "l"(v)); return f;
}

// ---------------- scratch (device globals: allocation-free) ----------------
__device__ __align__(16) float g_qzn[NELEM];
__device__ __align__(16) float g_qut[NELEM];
__device__ __align__(16) float g_qvt[NELEM];
__device__ __align__(16) float g_quc[NELEM];
__device__ __align__(16) float g_qvc[NELEM];
__device__ __align__(16) float g_msg[NELEM];
__device__ __align__(16) float g_S[(size_t)NTOK * GG];   // topic scores (relu'd)

// ---------------- K1: layernorm -> g_qzn ----------------
__global__ __launch_bounds__(256) void k_ln(const float* __restrict__ x,
                                            const float* __restrict__ gw,
                                            const float* __restrict__ gb) {
    int w = (blockIdx.x * 256 + threadIdx.x) >> 5;
    int lane = threadIdx.x & 31;
    if (w >= NTOK) return;
    const float* xr = x + (size_t)w * DD;
    float v[4];
#pragma unroll
    for (int j = 0; j < 4; j++) v[j] = xr[lane + 32*j];
    float s = v[0] + v[1] + v[2] + v[3];
#pragma unroll
    for (int o = 16; o; o >>= 1) s += __shfl_xor_sync(0xffffffffu, s, o);
    float mu = s * (1.0f/128.0f);
    float q = 0.0f;
#pragma unroll
    for (int j = 0; j < 4; j++) { float c = v[j] - mu; q += c * c; }
#pragma unroll
    for (int o = 16; o; o >>= 1) q += __shfl_xor_sync(0xffffffffu, q, o);
    float inv = rsqrtf(q * (1.0f/128.0f) + 1e-5f);
    float* yr = g_qzn + (size_t)w * DD;
#pragma unroll
    for (int j = 0; j < 4; j++) {
        int d = lane + 32*j;
        yr[d] = (v[j] - mu) * inv * gw[d] + gb[d];
    }
}

// ---------------- K2: per-batch projection (f32x2 GEMM) ----------------
// y[t,o] = sum_d X[t,d] * W[o,d].  Tile: 64 tokens x 128 o.
// smem: Xs [64][PSTR], Wt [128 d][PSTR o] (transposed weights).
#define SM_PROJ ((64*PSTR + 128*PSTR)*4)
__global__ __launch_bounds__(256) void k_proj(const float* __restrict__ w,
                                              float* __restrict__ y) {
    extern __shared__ float sm[];
    float* Xs = sm;               // 64 x PSTR
    float* Wt = sm + 64*PSTR;     // 128 x PSTR (indexed [d][o])
    int b = blockIdx.y;
    int t0 = blockIdx.x * 64;
    const float* xb = g_qzn + ((size_t)b * TPB + t0) * DD;
    const float* wb = w + (size_t)b * DD * DD;
    int tid = threadIdx.x, lane = tid & 31, wg = tid >> 5;
    for (int i = tid; i < 64*128; i += 256) Xs[(i>>7)*PSTR + (i&127)] = xb[i];
    for (int i = tid; i < 128*128; i += 256) Wt[(i&127)*PSTR + (i>>7)] = wb[i];
    __syncthreads();
    u64 acc[8][2];
#pragma unroll
    for (int k = 0; k < 8; k++) { acc[k][0] = 0ull; acc[k][1] = 0ull; }
#pragma unroll 2
    for (int d2 = 0; d2 < 64; d2++) {
        int d = 2*d2;
        ulonglong2 wA = *(const ulonglong2*)&Wt[d*PSTR + 4*lane];
        ulonglong2 wB = *(const ulonglong2*)&Wt[(d+1)*PSTR + 4*lane];
#pragma unroll
        for (int k = 0; k < 8; k++) {
            float2 xv = *(const float2*)&Xs[(wg + 8*k)*PSTR + d];
            u64 x0 = pk2(xv.x), x1 = pk2(xv.y);
            acc[k][0] = fma2(x0, wA.x, acc[k][0]);
            acc[k][1] = fma2(x0, wA.y, acc[k][1]);
            acc[k][0] = fma2(x1, wB.x, acc[k][0]);
            acc[k][1] = fma2(x1, wB.y, acc[k][1]);
        }
    }
    float* yb = y + ((size_t)b * TPB + t0) * DD;
#pragma unroll
    for (int k = 0; k < 8; k++) {
        float2 p0 = up2(acc[k][0]), p1 = up2(acc[k][1]);
        *(float4*)&yb[(size_t)(wg + 8*k)*DD + 4*lane] = make_float4(p0.x, p0.y, p1.x, p1.y);
    }
}

// ---------------- K3: topic scores S = relu(X B^T) (f32x2 GEMM) ----------------
// grid (192 token-tiles, 4 g-tiles, 8 b)
__global__ __launch_bounds__(256) void k_topicS(const float* __restrict__ bin) {
    extern __shared__ float sm[];
    float* Xs = sm;               // 64 x PSTR
    float* Bt = sm + 64*PSTR;     // 128 x PSTR  ([d][g])
    int b = blockIdx.z, gt = blockIdx.y;
    int t0 = blockIdx.x * 64;
    const float* xb = g_qzn + ((size_t)b * TPB + t0) * DD;
    const float* wb = bin + ((size_t)b * GG + gt*128) * DD;
    int tid = threadIdx.x, lane = tid & 31, wg = tid >> 5;
    for (int i = tid; i < 64*128; i += 256) Xs[(i>>7)*PSTR + (i&127)] = xb[i];
    for (int i = tid; i < 128*128; i += 256) Bt[(i&127)*PSTR + (i>>7)] = wb[i];
    __syncthreads();
    u64 acc[8][2];
#pragma unroll
    for (int k = 0; k < 8; k++) { acc[k][0] = 0ull; acc[k][1] = 0ull; }
#pragma unroll 2
    for (int d2 = 0; d2 < 64; d2++) {
        int d = 2*d2;
        ulonglong2 wA = *(const ulonglong2*)&Bt[d*PSTR + 4*lane];
        ulonglong2 wB = *(const ulonglong2*)&Bt[(d+1)*PSTR + 4*lane];
#pragma unroll
        for (int k = 0; k < 8; k++) {
            float2 xv = *(const float2*)&Xs[(wg + 8*k)*PSTR + d];
            u64 x0 = pk2(xv.x), x1 = pk2(xv.y);
            acc[k][0] = fma2(x0, wA.x, acc[k][0]);
            acc[k][1] = fma2(x0, wA.y, acc[k][1]);
            acc[k][0] = fma2(x1, wB.x, acc[k][0]);
            acc[k][1] = fma2(x1, wB.y, acc[k][1]);
        }
    }
#pragma unroll
    for (int k = 0; k < 8; k++) {
        float2 p0 = up2(acc[k][0]), p1 = up2(acc[k][1]);
        float4 v = make_float4(fmaxf(p0.x, 0.f), fmaxf(p0.y, 0.f),
                               fmaxf(p1.x, 0.f), fmaxf(p1.y, 0.f));
        size_t tg = (size_t)b * TPB + t0 + wg + 8*k;
        *(float4*)&g_S[tg * GG + gt*128 + 4*lane] = v;
    }
}

// ---------------- K4: topic out msg += (S/rowsum(S)) B (f32x2 GEMM, K=512) ----
// grid (192 token-tiles, 8 b). Streams B and S in 128-g chunks.
__global__ __launch_bounds__(256) void k_topicO(const float* __restrict__ bin) {
    extern __shared__ float sm[];
    float* Ss = sm;               // 64 x PSTR
    float* Bs = sm + 64*PSTR;     // 128 x PSTR  ([g][d], native layout)
    int b = blockIdx.y;
    int t0 = blockIdx.x * 64;
    const float* binb = bin + (size_t)b * GG * DD;
    size_t btok = (size_t)b * TPB + t0;
    int tid = threadIdx.x, lane = tid & 31, wg = tid >> 5;
    u64 acc[8][2];
    float rsum[8];
#pragma unroll
    for (int k = 0; k < 8; k++) { acc[k][0] = 0ull; acc[k][1] = 0ull; rsum[k] = 0.f; }
    for (int gc = 0; gc < 4; gc++) {
        __syncthreads();
        for (int i = tid; i < 64*128; i += 256)
            Ss[(i>>7)*PSTR + (i&127)] = g_S[(btok + (i>>7)) * GG + gc*128 + (i&127)];
        for (int i = tid; i < 128*128; i += 256)
            Bs[(i>>7)*PSTR + (i&127)] = binb[(size_t)gc*128*128 + i];
        __syncthreads();
        // row-sum partials (lane covers its g-quad)
#pragma unroll
        for (int k = 0; k < 8; k++) {
            float4 sv = *(const float4*)&Ss[(wg + 8*k)*PSTR + 4*lane];
            rsum[k] += sv.x + sv.y + sv.z + sv.w;
        }
#pragma unroll 2
        for (int g2 = 0; g2 < 64; g2++) {
            int g = 2*g2;
            ulonglong2 wA = *(const ulonglong2*)&Bs[g*PSTR + 4*lane];
            ulonglong2 wB = *(const ulonglong2*)&Bs[(g+1)*PSTR + 4*lane];
#pragma unroll
            for (int k = 0; k < 8; k++) {
                float2 sv = *(const float2*)&Ss[(wg + 8*k)*PSTR + g];
                u64 x0 = pk2(sv.x), x1 = pk2(sv.y);
                acc[k][0] = fma2(x0, wA.x, acc[k][0]);
                acc[k][1] = fma2(x0, wA.y, acc[k][1]);
                acc[k][0] = fma2(x1, wB.x, acc[k][0]);
                acc[k][1] = fma2(x1, wB.y, acc[k][1]);
            }
        }
    }
#pragma unroll
    for (int k = 0; k < 8; k++) {
        float r = rsum[k];
#pragma unroll
        for (int o = 16; o; o >>= 1) r += __shfl_xor_sync(0xffffffffu, r, o);
        float inv = 1.0f / fmaxf(r, 1e-6f);
        float2 p0 = up2(acc[k][0]), p1 = up2(acc[k][1]);
        size_t gi = (btok + wg + 8*k) * DD + 4*lane;
        float4 m = *(float4*)&g_msg[gi];
        m.x += p0.x * inv; m.y += p0.y * inv;
        m.z += p1.x * inv; m.w += p1.y * inv;
        *(float4*)&g_msg[gi] = m;
    }
}

// ---------------- K5: time attention -> g_msg (first writer) ----------------
#define SM_TATTN ((3*96*PSTR + 96*ASTR)*4)
__global__ __launch_bounds__(256) void k_tattn() {
    extern __shared__ float sm[];
    float* Xs = sm;                  // 96 x PSTR
    float* Qu = Xs + 96*PSTR;
    float* Qv = Qu + 96*PSTR;
    float* As = Qv + 96*PSTR;        // 96 x ASTR
    int tid = threadIdx.x, lane = tid & 31, wg = tid >> 5;
    size_t base = (size_t)blockIdx.x * PP * DD;
    for (int i = tid; i < PP*DD; i += 256) {
        int r = i >> 7, d = i & 127;
        Xs[r*PSTR+d] = g_qzn[base + i];
        Qu[r*PSTR+d] = g_qut[base + i];
        Qv[r*PSTR+d] = g_qvt[base + i];
    }
    __syncthreads();
    u64 acc[12][2];
#pragma unroll
    for (int k = 0; k < 12; k++) { acc[k][0] = 0ull; acc[k][1] = 0ull; }

    for (int h = 0; h < HH; h++) {
        int ho = h * 16;
#pragma unroll 1
        for (int pr = 0; pr < 12; pr++) {
            int p = wg + 8*pr;
            u64 qu2[8];
#pragma unroll
            for (int r = 0; r < 8; r++) qu2[r] = *(const u64*)&Qu[p*PSTR + ho + 2*r];
            float lg[3];
#pragma unroll
            for (int qi = 0; qi < 3; qi++) {
                int q = lane + 32*qi;
                u64 s2 = 0ull;
#pragma unroll
                for (int r = 0; r < 8; r++) {
                    u64 qv2 = *(const u64*)&Qv[q*PSTR + ho + 2*r];
                    s2 = fma2(qu2[r], qv2, s2);
                }
                float2 sp = up2(s2);
                lg[qi] = (sp.x + sp.y) * 0.25f;
            }
            float mx = fmaxf(lg[0], fmaxf(lg[1], lg[2]));
#pragma unroll
            for (int o = 16; o; o >>= 1) mx = fmaxf(mx, __shfl_xor_sync(0xffffffffu, mx, o));
            float e0 = expf(lg[0]-mx), e1 = expf(lg[1]-mx), e2 = expf(lg[2]-mx);
            float ssum = e0 + e1 + e2;
#pragma unroll
            for (int o = 16; o; o >>= 1) ssum += __shfl_xor_sync(0xffffffffu, ssum, o);
            float inv = 0.125f / ssum;            // fold 1/H
            As[p*ASTR + lane]      = e0 * inv;
            As[p*ASTR + lane + 32] = e1 * inv;
            As[p*ASTR + lane + 64] = e2 * inv;
        }
        __syncthreads();
#pragma unroll 2
        for (int q = 0; q < PP; q++) {
            ulonglong2 xA = *(const ulonglong2*)&Xs[q*PSTR + 4*lane];
#pragma unroll
            for (int k = 0; k < 12; k++) {
                u64 ap = pk2(As[(wg + 8*k)*ASTR + q]);
                acc[k][0] = fma2(ap, xA.x, acc[k][0]);
                acc[k][1] = fma2(ap, xA.y, acc[k][1]);
            }
        }
        __syncthreads();
    }
#pragma unroll
    for (int k = 0; k < 12; k++) {
        int p = wg + 8*k;
        float2 p0 = up2(acc[k][0]), p1 = up2(acc[k][1]);
        *(float4*)&g_msg[base + (size_t)p*DD + 4*lane] = make_float4(p0.x, p0.y, p1.x, p1.y);
    }
}

// ---------------- K6: channel attention -> g_msg += ----------------
#define SM_CATTN (3*128*PSTR*4)
__global__ __launch_bounds__(256) void k_cattn() {
    extern __shared__ float sm[];
    float* Qu = sm;                  // 128 x PSTR
    float* Qv = Qu + 128*PSTR;
    float* Ac = Qv + 128*PSTR;
    int b = blockIdx.x / PP, p = blockIdx.x % PP;
    int tid = threadIdx.x, lane = tid & 31, wg = tid >> 5;
    for (int i = tid; i < CC*DD; i += 256) {
        int c = i >> 7, d = i & 127;
        size_t gi = (((size_t)b*CC + c)*PP + p)*DD + d;
        Qu[c*PSTR+d] = g_quc[gi];
        Qv[c*PSTR+d] = g_qvc[gi];
        Ac[c*PSTR+d] = 0.f;
    }
    __syncthreads();
    for (int h = 0; h < HH; h++) {
        int ho = h*16;
#pragma unroll 1
        for (int cr = 0; cr < 16; cr++) {
            int c = wg + 8*cr;
            u64 qu2[8];
#pragma unroll
            for (int r = 0; r < 8; r++) qu2[r] = *(const u64*)&Qu[c*PSTR + ho + 2*r];
            float lg[4];
#pragma unroll
            for (int j = 0; j < 4; j++) {
                int d = lane + 32*j;
                u64 s2 = 0ull;
#pragma unroll
                for (int r = 0; r < 8; r++) {
                    u64 qv2 = *(const u64*)&Qv[d*PSTR + ho + 2*r];
                    s2 = fma2(qu2[r], qv2, s2);
                }
                float2 sp = up2(s2);
                lg[j] = (sp.x + sp.y) * 0.25f;
            }
            float mx = fmaxf(fmaxf(lg[0], lg[1]), fmaxf(lg[2], lg[3]));
#pragma unroll
            for (int o = 16; o; o >>= 1) mx = fmaxf(mx, __shfl_xor_sync(0xffffffffu, mx, o));
            float e[4], ssum = 0.f;
#pragma unroll
            for (int j = 0; j < 4; j++) { e[j] = expf(lg[j] - mx); ssum += e[j]; }
#pragma unroll
            for (int o = 16; o; o >>= 1) ssum += __shfl_xor_sync(0xffffffffu, ssum, o);
            float inv = 0.125f / ssum;            // fold 1/H
#pragma unroll
            for (int j = 0; j < 4; j++) Ac[c*PSTR + lane + 32*j] += e[j] * inv;
        }
    }
    // each (c,d) owned by its writer thread -> no sync needed
#pragma unroll
    for (int cr = 0; cr < 16; cr++) {
        int c = wg + 8*cr;
#pragma unroll
        for (int j = 0; j < 4; j++) {
            int d = lane + 32*j;
            size_t gi = (((size_t)b*CC + c)*PP + p)*DD + d;
            g_msg[gi] += Ac[c*PSTR+d] * g_qzn[gi];
        }
    }
}

// ---------------- K7: combine -> d_out = 0.5*(unary + msg + old) ----------------
__global__ __launch_bounds__(256) void k_combine(const float4* __restrict__ un,
                                                 const float4* __restrict__ old,
                                                 float4* __restrict__ out) {
    int i = blockIdx.x * 256 + threadIdx.x;
    if (i >= NELEM/4) return;
    const float4* m4 = reinterpret_cast<const float4*>(g_msg);
    float4 u = un[i], o = old[i], m = m4[i];
    float4 r;
    r.x = 0.5f*(u.x + m.x + o.x);
    r.y = 0.5f*(u.y + m.y + o.y);
    r.z = 0.5f*(u.z + m.z + o.z);
    r.w = 0.5f*(u.w + m.w + o.w);
    out[i] = r;
}

// ---------------- K8: LN + MLP (gelu exact) + residual, in-place on d_out ------
#define SM_MLP ((2*128*PSTR + 2*64*PSTR)*4)
__global__ __launch_bounds__(256) void k_mlp(float* __restrict__ io,
                                             const float* __restrict__ gw,
                                             const float* __restrict__ gb,
                                             const float* __restrict__ w1,
                                             const float* __restrict__ b1,
                                             const float* __restrict__ w2,
                                             const float* __restrict__ b2) {
    extern __shared__ float sm[];
    float* W1t = sm;                 // 128 x PSTR ([d][o])
    float* W2t = W1t + 128*PSTR;
    float* Hs  = W2t + 128*PSTR;     // 64 x PSTR
    float* As  = Hs + 64*PSTR;
    int tid = threadIdx.x, lane = tid & 31, wg = tid >> 5;
    size_t base = (size_t)blockIdx.x * 64 * DD;
    for (int i = tid; i < 128*128; i += 256) {
        W1t[(i&127)*PSTR + (i>>7)] = w1[i];
        W2t[(i&127)*PSTR + (i>>7)] = w2[i];
    }
    // LN: warp per token
#pragma unroll 1
    for (int it = 0; it < 8; it++) {
        int t = wg + 8*it;
        const float* xr = io + base + (size_t)t*DD;
        float v[4];
#pragma unroll
        for (int j = 0; j < 4; j++) v[j] = xr[lane + 32*j];
        float s = v[0]+v[1]+v[2]+v[3];
#pragma unroll
        for (int o = 16; o; o >>= 1) s += __shfl_xor_sync(0xffffffffu, s, o);
        float mu = s * (1.0f/128.0f);
        float q = 0.f;
#pragma unroll
        for (int j = 0; j < 4; j++) { float c = v[j]-mu; q += c*c; }
#pragma unroll
        for (int o = 16; o; o >>= 1) q += __shfl_xor_sync(0xffffffffu, q, o);
        float inv = rsqrtf(q * (1.0f/128.0f) + 1e-5f);
#pragma unroll
        for (int j = 0; j < 4; j++) {
            int d = lane + 32*j;
            Hs[t*PSTR+d] = (v[j]-mu)*inv*gw[d] + gb[d];
        }
    }
    __syncthreads();
    // GEMM1 + bias + gelu(exact)
    {
        u64 acc[8][2];
#pragma unroll
        for (int k = 0; k < 8; k++) { acc[k][0] = 0ull; acc[k][1] = 0ull; }
#pragma unroll 2
        for (int d2 = 0; d2 < 64; d2++) {
            int d = 2*d2;
            ulonglong2 wA = *(const ulonglong2*)&W1t[d*PSTR + 4*lane];
            ulonglong2 wB = *(const ulonglong2*)&W1t[(d+1)*PSTR + 4*lane];
#pragma unroll
            for (int k = 0; k < 8; k++) {
                float2 xv = *(const float2*)&Hs[(wg + 8*k)*PSTR + d];
                u64 x0 = pk2(xv.x), x1 = pk2(xv.y);
                acc[k][0] = fma2(x0, wA.x, acc[k][0]);
                acc[k][1] = fma2(x0, wA.y, acc[k][1]);
                acc[k][0] = fma2(x1, wB.x, acc[k][0]);
                acc[k][1] = fma2(x1, wB.y, acc[k][1]);
            }
        }
        float4 b1v = *(const float4*)&b1[4*lane];
#pragma unroll
        for (int k = 0; k < 8; k++) {
            float2 p0 = up2(acc[k][0]), p1 = up2(acc[k][1]);
            float xv[4] = {p0.x + b1v.x, p0.y + b1v.y, p1.x + b1v.z, p1.y + b1v.w};
            float g[4];
#pragma unroll
            for (int j = 0; j < 4; j++)
                g[j] = 0.5f * xv[j] * (1.0f + erff(xv[j] * 0.70710678118654752f));
            *(float4*)&As[(wg+8*k)*PSTR + 4*lane] = make_float4(g[0], g[1], g[2], g[3]);
        }
    }
    __syncthreads();
    // GEMM2 + bias + residual
    {
        u64 acc[8][2];
#pragma unroll
        for (int k = 0; k < 8; k++) { acc[k][0] = 0ull; acc[k][1] = 0ull; }
#pragma unroll 2
        for (int d2 = 0; d2 < 64; d2++) {
            int d = 2*d2;
            ulonglong2 wA = *(const ulonglong2*)&W2t[d*PSTR + 4*lane];
            ulonglong2 wB = *(const ulonglong2*)&W2t[(d+1)*PSTR + 4*lane];
#pragma unroll
            for (int k = 0; k < 8; k++) {
                float2 xv = *(const float2*)&As[(wg + 8*k)*PSTR + d];
                u64 x0 = pk2(xv.x), x1 = pk2(xv.y);
                acc[k][0] = fma2(x0, wA.x, acc[k][0]);
                acc[k][1] = fma2(x0, wA.y, acc[k][1]);
                acc[k][0] = fma2(x1, wB.x, acc[k][0]);
                acc[k][1] = fma2(x1, wB.y, acc[k][1]);
            }
        }
        float4 b2v = *(const float4*)&b2[4*lane];
#pragma unroll
        for (int k = 0; k < 8; k++) {
            float2 p0 = up2(acc[k][0]), p1 = up2(acc[k][1]);
            size_t idx = base + (size_t)(wg+8*k)*DD + 4*lane;
            float4 io4 = *(float4*)&io[idx];
            io4.x += p0.x + b2v.x;
            io4.y += p0.y + b2v.y;
            io4.z += p1.x + b2v.z;
            io4.w += p1.y + b2v.w;
            *(float4*)&io[idx] = io4;
        }
    }
}

// ---------------- host launcher ----------------
extern "C" void kernel_launch(void* const* d_in, const int* in_sizes, int n_in,
                              void* d_out, int out_size) {
    (void)in_sizes; (void)n_in; (void)out_size;
    const float* qz  = (const float*)d_in[0];
    const float* un  = (const float*)d_in[1];
    const float* tu  = (const float*)d_in[2];
    const float* tv  = (const float*)d_in[3];
    const float* cu  = (const float*)d_in[4];
    const float* cv  = (const float*)d_in[5];
    const float* bin = (const float*)d_in[6];
    const float* lng = (const float*)d_in[7];
    const float* lnb = (const float*)d_in[8];
    const float* w1  = (const float*)d_in[9];
    const float* b1  = (const float*)d_in[10];
    const float* w2  = (const float*)d_in[11];
    const float* b2  = (const float*)d_in[12];
    float* out = (float*)d_out;

    float *qut, *qvt, *quc, *qvc;
    cudaGetSymbolAddress((void**)&qut, g_qut);
    cudaGetSymbolAddress((void**)&qvt, g_qvt);
    cudaGetSymbolAddress((void**)&quc, g_quc);
    cudaGetSymbolAddress((void**)&qvc, g_qvc);

    cudaFuncSetAttribute(k_proj,   cudaFuncAttributeMaxDynamicSharedMemorySize, SM_PROJ);
    cudaFuncSetAttribute(k_topicS, cudaFuncAttributeMaxDynamicSharedMemorySize, SM_PROJ);
    cudaFuncSetAttribute(k_topicO, cudaFuncAttributeMaxDynamicSharedMemorySize, SM_PROJ);
    cudaFuncSetAttribute(k_tattn,  cudaFuncAttributeMaxDynamicSharedMemorySize, SM_TATTN);
    cudaFuncSetAttribute(k_cattn,  cudaFuncAttributeMaxDynamicSharedMemorySize, SM_CATTN);
    cudaFuncSetAttribute(k_mlp,    cudaFuncAttributeMaxDynamicSharedMemorySize, SM_MLP);

    k_ln<<<(NTOK*32)/256, 256>>>(qz, lng, lnb);

    dim3 pg(TPB/64, BB);
    k_proj<<<pg, 256, SM_PROJ>>>(tu, qut);
    k_proj<<<pg, 256, SM_PROJ>>>(tv, qvt);
    k_proj<<<pg, 256, SM_PROJ>>>(cu, quc);
    k_proj<<<pg, 256, SM_PROJ>>>(cv, qvc);

    dim3 sg(TPB/64, 4, BB);
    k_topicS<<<sg, 256, SM_PROJ>>>(bin);

    k_tattn<<<BB*CC, 256, SM_TATTN>>>();
    k_cattn<<<BB*PP, 256, SM_CATTN>>>();

    dim3 og(TPB/64, BB);
    k_topicO<<<og, 256, SM_PROJ>>>(bin);

    k_combine<<<(NELEM/4 + 255)/256, 256>>>((const float4*)un, (const float4*)qz,
                                            (float4*)out);
    k_mlp<<<NTOK/64, 256, SM_MLP>>>(out, lng, lnb, w1, b1, w2, b2);
}

// round 6
// speedup vs baseline: 1.2195x; 1.0042x over previous
#include <cuda_runtime.h>
#include <cuda_bf16.h>
#include <math.h>
#include <stdint.h>

#define BB 8
#define CC 128
#define PP 96
#define DD 128
#define HH 8
#define GG 512
#define TPB (CC*PP)          // 12288 tokens per batch
#define NTOK (BB*TPB)        // 98304
#define NELEM (NTOK*DD)      // 12582912

#define PSTR 132
#define ASTR 98
#define RSB 272              // smem bf16 tile row stride in BYTES (136 halves)

typedef unsigned long long u64;

__device__ __forceinline__ u64 pk2(float x) {
    u64 r; asm("mov.b64 %0,{%1,%1};" : "=l"(r) : "f"(x)); return r;
}
__device__ __forceinline__ u64 fma2(u64 a, u64 b, u64 c) {
    asm("fma.rn.f32x2 %0,%1,%2,%0;" : "+l"(c) : "l"(a), "l"(b)); return c;
}
__device__ __forceinline__ float2 up2(u64 v) {
    float2 f; asm("mov.b64 {%0,%1},%2;" : "=f"(f.x), "=f"(f.y) : "l"(v)); return f;
}

// ---------------- scratch (device globals: allocation-free) ----------------
__device__ __align__(16) float g_qzn[NELEM];
__device__ __align__(16) __nv_bfloat16 g_qzn_h[NELEM];
__device__ __align__(16) __nv_bfloat16 g_qzn_l[NELEM];
__device__ __align__(16) float g_qut[NELEM];
__device__ __align__(16) float g_qvt[NELEM];
__device__ __align__(16) float g_quc[NELEM];
__device__ __align__(16) float g_qvc[NELEM];
__device__ __align__(16) float g_msg[NELEM];
__device__ __align__(16) __nv_bfloat16 g_Shi[(size_t)NTOK * GG];
__device__ __align__(16) __nv_bfloat16 g_Slo[(size_t)NTOK * GG];
__device__ __align__(16) __nv_bfloat16 g_binT_h[(size_t)BB * DD * GG];
__device__ __align__(16) __nv_bfloat16 g_binT_l[(size_t)BB * DD * GG];

// ================= mma.sync helpers =================
__device__ __forceinline__ uint32_t smem_u32(const void* p) {
    uint32_t a;
    asm("{ .reg .u64 t; cvta.to.shared.u64 t, %1; cvt.u32.u64 %0, t; }" : "=r"(a) : "l"(p));
    return a;
}

#define LDSM4(R, addr) \
    asm volatile("ldmatrix.sync.aligned.m8n8.x4.shared.b16 {%0,%1,%2,%3}, [%4];" \
        : "=r"((R)[0]), "=r"((R)[1]), "=r"((R)[2]), "=r"((R)[3]) : "r"(addr))

#define MMA16816(C, A, b0, b1) \
    asm volatile("mma.sync.aligned.m16n8k16.row.col.f32.bf16.bf16.f32 " \
        "{%0,%1,%2,%3},{%4,%5,%6,%7},{%8,%9},{%0,%1,%2,%3};" \
        : "+f"((C)[0]), "+f"((C)[1]), "+f"((C)[2]), "+f"((C)[3]) \
        : "r"((A)[0]), "r"((A)[1]), "r"((A)[2]), "r"((A)[3]), "r"(b0), "r"(b1))

__device__ __forceinline__ void split2(float x0, float x1, uint32_t& hp, uint32_t& lp) {
    __nv_bfloat16 h0 = __float2bfloat16(x0), h1 = __float2bfloat16(x1);
    __nv_bfloat16 l0 = __float2bfloat16(x0 - __bfloat162float(h0));
    __nv_bfloat16 l1 = __float2bfloat16(x1 - __bfloat162float(h1));
    hp = ((uint32_t)__bfloat16_as_ushort(h1) << 16) | __bfloat16_as_ushort(h0);
    lp = ((uint32_t)__bfloat16_as_ushort(l1) << 16) | __bfloat16_as_ushort(l0);
}

// fp32 128x128 row-major -> hi/lo bf16 smem tiles (row stride RSB bytes)
__device__ __forceinline__ void fill_hilo(const float* __restrict__ src,
                                          char* smHi, char* smLo, int tid) {
    for (int i = tid; i < 128*64; i += 256) {
        int row = i >> 6, cp = (i & 63);
        float2 v = *(const float2*)(src + row*128 + 2*cp);
        uint32_t hp, lp;
        split2(v.x, v.y, hp, lp);
        *(uint32_t*)(smHi + row*RSB + 4*cp) = hp;
        *(uint32_t*)(smLo + row*RSB + 4*cp) = lp;
    }
}

// split-precision 128x128x128 mainloop. acc[2][8][4] per warp.
// warp: wm = wid&3 (32 M-rows), wn = wid>>2 (64 N-cols).
__device__ __forceinline__ void mm128(uint32_t ah, uint32_t al,
                                      uint32_t bh, uint32_t bl,
                                      int lane, int wm, int wn,
                                      float acc[2][8][4]) {
    int r16 = lane & 15;
    uint32_t aoff = (uint32_t)(wm*32 + r16)*RSB + ((lane >> 4) << 4);
    uint32_t boff = (uint32_t)(wn*64 + r16)*RSB + ((lane >> 4) << 4);
#pragma unroll
    for (int ks = 0; ks < 8; ks++) {
        uint32_t ko = ks * 32;
        uint32_t Ah[2][4], Al[2][4], Bh[4][4], Bl[4][4];
        LDSM4(Ah[0], ah + aoff + ko);
        LDSM4(Ah[1], ah + aoff + 16*RSB + ko);
        LDSM4(Al[0], al + aoff + ko);
        LDSM4(Al[1], al + aoff + 16*RSB + ko);
#pragma unroll
        for (int bt = 0; bt < 4; bt++) {
            LDSM4(Bh[bt], bh + boff + bt*16*RSB + ko);
            LDSM4(Bl[bt], bl + boff + bt*16*RSB + ko);
        }
#pragma unroll
        for (int mt = 0; mt < 2; mt++)
#pragma unroll
            for (int bt = 0; bt < 4; bt++) {
                MMA16816(acc[mt][2*bt],   Ah[mt], Bh[bt][0], Bh[bt][2]);
                MMA16816(acc[mt][2*bt+1], Ah[mt], Bh[bt][1], Bh[bt][3]);
                MMA16816(acc[mt][2*bt],   Ah[mt], Bl[bt][0], Bl[bt][2]);
                MMA16816(acc[mt][2*bt+1], Ah[mt], Bl[bt][1], Bl[bt][3]);
                MMA16816(acc[mt][2*bt],   Al[mt], Bh[bt][0], Bh[bt][2]);
                MMA16816(acc[mt][2*bt+1], Al[mt], Bh[bt][1], Bh[bt][3]);
            }
    }
}

#define TILE_B (128*RSB)     // 34816 bytes per bf16 tile
#define OFF_AH 0
#define OFF_AL (TILE_B)
#define OFF_BH (2*TILE_B)
#define OFF_BL (3*TILE_B)
#define SM_G4 (4*TILE_B)                 // 139264
#define SM_TOPICO (SM_G4 + 512)
#define SM_MLP6 (6*TILE_B)               // 208896
#define OFF_W1H (2*TILE_B)
#define OFF_W1L (3*TILE_B)
#define OFF_W2H (4*TILE_B)
#define OFF_W2L (5*TILE_B)

// ---------------- K1: layernorm -> g_qzn fp32 + hi/lo bf16 ----------------
__global__ __launch_bounds__(256) void k_ln(const float* __restrict__ x,
                                            const float* __restrict__ gw,
                                            const float* __restrict__ gb) {
    int w = (blockIdx.x * 256 + threadIdx.x) >> 5;
    int lane = threadIdx.x & 31;
    if (w >= NTOK) return;
    const float2* xr = (const float2*)(x + (size_t)w * DD);
    float2 v0 = xr[lane], v1 = xr[lane + 32];
    float s = v0.x + v0.y + v1.x + v1.y;
#pragma unroll
    for (int o = 16; o; o >>= 1) s += __shfl_xor_sync(0xffffffffu, s, o);
    float mu = s * (1.0f/128.0f);
    float q = (v0.x-mu)*(v0.x-mu) + (v0.y-mu)*(v0.y-mu)
            + (v1.x-mu)*(v1.x-mu) + (v1.y-mu)*(v1.y-mu);
#pragma unroll
    for (int o = 16; o; o >>= 1) q += __shfl_xor_sync(0xffffffffu, q, o);
    float inv = rsqrtf(q * (1.0f/128.0f) + 1e-5f);
    float2* yr = (float2*)(g_qzn + (size_t)w * DD);
    uint32_t* yh = (uint32_t*)(g_qzn_h + (size_t)w * DD);
    uint32_t* yl = (uint32_t*)(g_qzn_l + (size_t)w * DD);
#pragma unroll
    for (int j = 0; j < 2; j++) {
        float2 v = j ? v1 : v0;
        int dp = lane + 32*j;
        float y0 = (v.x-mu)*inv*gw[2*dp]   + gb[2*dp];
        float y1 = (v.y-mu)*inv*gw[2*dp+1] + gb[2*dp+1];
        yr[dp] = make_float2(y0, y1);
        uint32_t hp, lp;
        split2(y0, y1, hp, lp);
        yh[dp] = hp; yl[dp] = lp;
    }
}

// ---------------- K1b: transpose+split topic_binary -> g_binT [b][d][g] ------
#define TSTR 129
__global__ __launch_bounds__(256) void k_binT(const float* __restrict__ bin) {
    extern __shared__ float smf[];
    int gt = blockIdx.x, b = blockIdx.y;
    int tid = threadIdx.x;
    const float* src = bin + ((size_t)b * GG + (size_t)gt * 128) * DD;
    for (int i = tid; i < 128*128; i += 256) {
        int g = i >> 7, d = i & 127;
        smf[g*TSTR + d] = src[i];
    }
    __syncthreads();
    uint32_t* oh = (uint32_t*)(g_binT_h + (size_t)b * DD * GG + (size_t)gt * 128);
    uint32_t* ol = (uint32_t*)(g_binT_l + (size_t)b * DD * GG + (size_t)gt * 128);
    for (int i = tid; i < 128*64; i += 256) {
        int d = i >> 6, gp = i & 63;
        float v0 = smf[(2*gp)*TSTR + d], v1 = smf[(2*gp+1)*TSTR + d];
        uint32_t hp, lp;
        split2(v0, v1, hp, lp);
        size_t o = ((size_t)d * GG) / 2 + gp;   // u32 units within [d][512]
        oh[o] = hp; ol[o] = lp;
    }
}

// ---------------- K2: tensor projections: y = qzn @ W^T per batch ----------
// grid (96 token tiles, 4 proj, 8 b)
__global__ __launch_bounds__(256) void k_proj_tc(const float* __restrict__ tu,
                                                 const float* __restrict__ tv,
                                                 const float* __restrict__ cu,
                                                 const float* __restrict__ cv) {
    extern __shared__ char sm[];
    uint32_t smb = smem_u32(sm);
    int tid = threadIdx.x, wid = tid >> 5, lane = tid & 31;
    int wm = wid & 3, wn = wid >> 2;
    int tile = blockIdx.x, pj = blockIdx.y, b = blockIdx.z;
    const float* w = (pj == 0) ? tu : (pj == 1) ? tv : (pj == 2) ? cu : cv;
    float* y = (pj == 0) ? g_qut : (pj == 1) ? g_qvt : (pj == 2) ? g_quc : g_qvc;
    size_t tokbase = (size_t)b * TPB + (size_t)tile * 128;
    // A: copy prepacked qzn hi/lo
    {
        const uint32_t* sh = (const uint32_t*)(g_qzn_h + tokbase * DD);
        const uint32_t* sl = (const uint32_t*)(g_qzn_l + tokbase * DD);
        for (int i = tid; i < 128*64; i += 256) {
            int row = i >> 6, cp = i & 63;
            *(uint32_t*)(sm + OFF_AH + row*RSB + 4*cp) = sh[row*64 + cp];
            *(uint32_t*)(sm + OFF_AL + row*RSB + 4*cp) = sl[row*64 + cp];
        }
    }
    fill_hilo(w + (size_t)b * DD * DD, sm + OFF_BH, sm + OFF_BL, tid);
    __syncthreads();
    float acc[2][8][4];
#pragma unroll
    for (int mt = 0; mt < 2; mt++)
#pragma unroll
        for (int nt = 0; nt < 8; nt++)
#pragma unroll
            for (int j = 0; j < 4; j++) acc[mt][nt][j] = 0.f;
    mm128(smb + OFF_AH, smb + OFF_AL, smb + OFF_BH, smb + OFF_BL, lane, wm, wn, acc);
#pragma unroll
    for (int mt = 0; mt < 2; mt++)
#pragma unroll
        for (int h = 0; h < 2; h++) {
            int row = wm*32 + mt*16 + (lane >> 2) + 8*h;
            float* yr = y + (tokbase + row) * DD;
#pragma unroll
            for (int nt = 0; nt < 8; nt++) {
                int col = wn*64 + nt*8 + (lane & 3)*2;
                *(float2*)&yr[col] = make_float2(acc[mt][nt][2*h], acc[mt][nt][2*h+1]);
            }
        }
}

// ---------------- K3: topic scores S = relu(qzn @ bin^T) -> hi/lo ----------
// grid (96 token tiles, 4 g tiles, 8 b)
__global__ __launch_bounds__(256) void k_topicS_tc(const float* __restrict__ bin) {
    extern __shared__ char sm[];
    uint32_t smb = smem_u32(sm);
    int tid = threadIdx.x, wid = tid >> 5, lane = tid & 31;
    int wm = wid & 3, wn = wid >> 2;
    int tile = blockIdx.x, gt = blockIdx.y, b = blockIdx.z;
    size_t tokbase = (size_t)b * TPB + (size_t)tile * 128;
    {
        const uint32_t* sh = (const uint32_t*)(g_qzn_h + tokbase * DD);
        const uint32_t* sl = (const uint32_t*)(g_qzn_l + tokbase * DD);
        for (int i = tid; i < 128*64; i += 256) {
            int row = i >> 6, cp = i & 63;
            *(uint32_t*)(sm + OFF_AH + row*RSB + 4*cp) = sh[row*64 + cp];
            *(uint32_t*)(sm + OFF_AL + row*RSB + 4*cp) = sl[row*64 + cp];
        }
    }
    fill_hilo(bin + ((size_t)b * GG + (size_t)gt * 128) * DD, sm + OFF_BH, sm + OFF_BL, tid);
    __syncthreads();
    float acc[2][8][4];
#pragma unroll
    for (int mt = 0; mt < 2; mt++)
#pragma unroll
        for (int nt = 0; nt < 8; nt++)
#pragma unroll
            for (int j = 0; j < 4; j++) acc[mt][nt][j] = 0.f;
    mm128(smb + OFF_AH, smb + OFF_AL, smb + OFF_BH, smb + OFF_BL, lane, wm, wn, acc);
#pragma unroll
    for (int mt = 0; mt < 2; mt++)
#pragma unroll
        for (int h = 0; h < 2; h++) {
            int row = wm*32 + mt*16 + (lane >> 2) + 8*h;
            uint32_t* shp = (uint32_t*)&g_Shi[(tokbase + row) * GG + gt*128];
            uint32_t* slp = (uint32_t*)&g_Slo[(tokbase + row) * GG + gt*128];
#pragma unroll
            for (int nt = 0; nt < 8; nt++) {
                int col = wn*64 + nt*8 + (lane & 3)*2;
                float f0 = fmaxf(acc[mt][nt][2*h], 0.f);
                float f1 = fmaxf(acc[mt][nt][2*h+1], 0.f);
                uint32_t hp, lp;
                split2(f0, f1, hp, lp);
                shp[col >> 1] = hp;
                slp[col >> 1] = lp;
            }
        }
}

// ---------------- K4: topic out: msg += (S/rowsum) @ bin  (K=512) ----------
// grid (96 token tiles, 8 b)
__global__ __launch_bounds__(256) void k_topicO_tc() {
    extern __shared__ char sm[];
    uint32_t smb = smem_u32(sm);
    float* rs = (float*)(sm + SM_G4);
    int tid = threadIdx.x, wid = tid >> 5, lane = tid & 31;
    int wm = wid & 3, wn = wid >> 2;
    int tile = blockIdx.x, b = blockIdx.y;
    size_t btok = (size_t)b * TPB + (size_t)tile * 128;
    if (tid < 128) rs[tid] = 0.f;
    __syncthreads();
    float acc[2][8][4];
#pragma unroll
    for (int mt = 0; mt < 2; mt++)
#pragma unroll
        for (int nt = 0; nt < 8; nt++)
#pragma unroll
            for (int j = 0; j < 4; j++) acc[mt][nt][j] = 0.f;

    for (int gc = 0; gc < 4; gc++) {
        if (gc) __syncthreads();
        // A: S hi/lo direct copies + rowsum
        for (int i = tid; i < 128*64; i += 256) {
            int row = i >> 6, cp = i & 63;
            uint32_t hp = *(const uint32_t*)&g_Shi[(btok + row) * GG + gc*128 + 2*cp];
            uint32_t lp = *(const uint32_t*)&g_Slo[(btok + row) * GG + gc*128 + 2*cp];
            *(uint32_t*)(sm + OFF_AH + row*RSB + 4*cp) = hp;
            *(uint32_t*)(sm + OFF_AL + row*RSB + 4*cp) = lp;
            __nv_bfloat162 h2 = *reinterpret_cast<__nv_bfloat162*>(&hp);
            __nv_bfloat162 l2 = *reinterpret_cast<__nv_bfloat162*>(&lp);
            float2 fh = __bfloat1622float2(h2), fl = __bfloat1622float2(l2);
            float v = fh.x + fh.y + fl.x + fl.y;
#pragma unroll
            for (int o = 16; o; o >>= 1) v += __shfl_xor_sync(0xffffffffu, v, o);
            if (lane == 0) atomicAdd(&rs[row], v);
        }
        // B: binT hi/lo direct copies
        {
            const uint32_t* bh = (const uint32_t*)(g_binT_h + (size_t)b * DD * GG + gc*128);
            const uint32_t* bl = (const uint32_t*)(g_binT_l + (size_t)b * DD * GG + gc*128);
            for (int i = tid; i < 128*64; i += 256) {
                int d = i >> 6, gp = i & 63;
                size_t o = (size_t)d * (GG/2) + gp;
                *(uint32_t*)(sm + OFF_BH + d*RSB + 4*gp) = bh[o];
                *(uint32_t*)(sm + OFF_BL + d*RSB + 4*gp) = bl[o];
            }
        }
        __syncthreads();
        mm128(smb + OFF_AH, smb + OFF_AL, smb + OFF_BH, smb + OFF_BL, lane, wm, wn, acc);
    }
#pragma unroll
    for (int mt = 0; mt < 2; mt++)
#pragma unroll
        for (int h = 0; h < 2; h++) {
            int row = wm*32 + mt*16 + (lane >> 2) + 8*h;
            float inv = 1.0f / fmaxf(rs[row], 1e-6f);
            float* mg = g_msg + (btok + row) * DD;
#pragma unroll
            for (int nt = 0; nt < 8; nt++) {
                int col = wn*64 + nt*8 + (lane & 3)*2;
                float2 m = *(float2*)&mg[col];
                m.x += acc[mt][nt][2*h]   * inv;
                m.y += acc[mt][nt][2*h+1] * inv;
                *(float2*)&mg[col] = m;
            }
        }
}

// ---------------- K5: time attention -> g_msg (first writer) ----------------
#define SM_TATTN ((3*96*PSTR + 96*ASTR)*4)
__global__ __launch_bounds__(256) void k_tattn() {
    extern __shared__ float smf[];
    float* Xs = smf;                 // 96 x PSTR
    float* Qu = Xs + 96*PSTR;
    float* Qv = Qu + 96*PSTR;
    float* As = Qv + 96*PSTR;        // 96 x ASTR
    int tid = threadIdx.x, lane = tid & 31, wg = tid >> 5;
    size_t base = (size_t)blockIdx.x * PP * DD;
    for (int i = tid; i < PP*DD; i += 256) {
        int r = i >> 7, d = i & 127;
        Xs[r*PSTR+d] = g_qzn[base + i];
        Qu[r*PSTR+d] = g_qut[base + i];
        Qv[r*PSTR+d] = g_qvt[base + i];
    }
    __syncthreads();
    u64 acc[12][2];
#pragma unroll
    for (int k = 0; k < 12; k++) { acc[k][0] = 0ull; acc[k][1] = 0ull; }

    for (int h = 0; h < HH; h++) {
        int ho = h * 16;
#pragma unroll 1
        for (int pr = 0; pr < 12; pr++) {
            int p = wg + 8*pr;
            u64 qu2[8];
#pragma unroll
            for (int r = 0; r < 8; r++) qu2[r] = *(const u64*)&Qu[p*PSTR + ho + 2*r];
            float lg[3];
#pragma unroll
            for (int qi = 0; qi < 3; qi++) {
                int q = lane + 32*qi;
                u64 s2 = 0ull;
#pragma unroll
                for (int r = 0; r < 8; r++) {
                    u64 qv2 = *(const u64*)&Qv[q*PSTR + ho + 2*r];
                    s2 = fma2(qu2[r], qv2, s2);
                }
                float2 sp = up2(s2);
                lg[qi] = (sp.x + sp.y) * 0.25f;
            }
            float mx = fmaxf(lg[0], fmaxf(lg[1], lg[2]));
#pragma unroll
            for (int o = 16; o; o >>= 1) mx = fmaxf(mx, __shfl_xor_sync(0xffffffffu, mx, o));
            float e0 = expf(lg[0]-mx), e1 = expf(lg[1]-mx), e2 = expf(lg[2]-mx);
            float ssum = e0 + e1 + e2;
#pragma unroll
            for (int o = 16; o; o >>= 1) ssum += __shfl_xor_sync(0xffffffffu, ssum, o);
            float inv = 0.125f / ssum;            // fold 1/H
            As[p*ASTR + lane]      = e0 * inv;
            As[p*ASTR + lane + 32] = e1 * inv;
            As[p*ASTR + lane + 64] = e2 * inv;
        }
        __syncthreads();
#pragma unroll 2
        for (int q = 0; q < PP; q++) {
            ulonglong2 xA = *(const ulonglong2*)&Xs[q*PSTR + 4*lane];
#pragma unroll
            for (int k = 0; k < 12; k++) {
                u64 ap = pk2(As[(wg + 8*k)*ASTR + q]);
                acc[k][0] = fma2(ap, xA.x, acc[k][0]);
                acc[k][1] = fma2(ap, xA.y, acc[k][1]);
            }
        }
        __syncthreads();
    }
#pragma unroll
    for (int k = 0; k < 12; k++) {
        int p = wg + 8*k;
        float2 p0 = up2(acc[k][0]), p1 = up2(acc[k][1]);
        *(float4*)&g_msg[base + (size_t)p*DD + 4*lane] = make_float4(p0.x, p0.y, p1.x, p1.y);
    }
}

// ---------------- K6: channel attention -> g_msg += ----------------
#define SM_CATTN (3*128*PSTR*4)
__global__ __launch_bounds__(256) void k_cattn() {
    extern __shared__ float smf[];
    float* Qu = smf;                 // 128 x PSTR
    float* Qv = Qu + 128*PSTR;
    float* Ac = Qv + 128*PSTR;
    int b = blockIdx.x / PP, p = blockIdx.x % PP;
    int tid = threadIdx.x, lane = tid & 31, wg = tid >> 5;
    for (int i = tid; i < CC*DD; i += 256) {
        int c = i >> 7, d = i & 127;
        size_t gi = (((size_t)b*CC + c)*PP + p)*DD + d;
        Qu[c*PSTR+d] = g_quc[gi];
        Qv[c*PSTR+d] = g_qvc[gi];
        Ac[c*PSTR+d] = 0.f;
    }
    __syncthreads();
    for (int h = 0; h < HH; h++) {
        int ho = h*16;
#pragma unroll 1
        for (int cr = 0; cr < 16; cr++) {
            int c = wg + 8*cr;
            u64 qu2[8];
#pragma unroll
            for (int r = 0; r < 8; r++) qu2[r] = *(const u64*)&Qu[c*PSTR + ho + 2*r];
            float lg[4];
#pragma unroll
            for (int j = 0; j < 4; j++) {
                int d = lane + 32*j;
                u64 s2 = 0ull;
#pragma unroll
                for (int r = 0; r < 8; r++) {
                    u64 qv2 = *(const u64*)&Qv[d*PSTR + ho + 2*r];
                    s2 = fma2(qu2[r], qv2, s2);
                }
                float2 sp = up2(s2);
                lg[j] = (sp.x + sp.y) * 0.25f;
            }
            float mx = fmaxf(fmaxf(lg[0], lg[1]), fmaxf(lg[2], lg[3]));
#pragma unroll
            for (int o = 16; o; o >>= 1) mx = fmaxf(mx, __shfl_xor_sync(0xffffffffu, mx, o));
            float e[4], ssum = 0.f;
#pragma unroll
            for (int j = 0; j < 4; j++) { e[j] = expf(lg[j] - mx); ssum += e[j]; }
#pragma unroll
            for (int o = 16; o; o >>= 1) ssum += __shfl_xor_sync(0xffffffffu, ssum, o);
            float inv = 0.125f / ssum;            // fold 1/H
#pragma unroll
            for (int j = 0; j < 4; j++) Ac[c*PSTR + lane + 32*j] += e[j] * inv;
        }
    }
#pragma unroll
    for (int cr = 0; cr < 16; cr++) {
        int c = wg + 8*cr;
#pragma unroll
        for (int j = 0; j < 4; j++) {
            int d = lane + 32*j;
            size_t gi = (((size_t)b*CC + c)*PP + p)*DD + d;
            g_msg[gi] += Ac[c*PSTR+d] * g_qzn[gi];
        }
    }
}

// ---------------- K7: combine -> d_out = 0.5*(unary + msg + old) ------------
__global__ __launch_bounds__(256) void k_combine(const float4* __restrict__ un,
                                                 const float4* __restrict__ old,
                                                 float4* __restrict__ out) {
    int i = blockIdx.x * 256 + threadIdx.x;
    if (i >= NELEM/4) return;
    const float4* m4 = reinterpret_cast<const float4*>(g_msg);
    float4 u = un[i], o = old[i], m = m4[i];
    float4 r;
    r.x = 0.5f*(u.x + m.x + o.x);
    r.y = 0.5f*(u.y + m.y + o.y);
    r.z = 0.5f*(u.z + m.z + o.z);
    r.w = 0.5f*(u.w + m.w + o.w);
    out[i] = r;
}

// ---------------- K8: LN + MLP (tensor) + residual, in-place on d_out -------
// grid (NTOK/128). smem: A hi/lo + W1 hi/lo + W2 hi/lo.
__global__ __launch_bounds__(256) void k_mlp_tc(float* __restrict__ io,
                                                const float* __restrict__ gw,
                                                const float* __restrict__ gb,
                                                const float* __restrict__ w1,
                                                const float* __restrict__ b1,
                                                const float* __restrict__ w2,
                                                const float* __restrict__ b2) {
    extern __shared__ char sm[];
    uint32_t smb = smem_u32(sm);
    int tid = threadIdx.x, wid = tid >> 5, lane = tid & 31;
    int wm = wid & 3, wn = wid >> 2;
    size_t base = (size_t)blockIdx.x * 128 * DD;
    fill_hilo(w1, sm + OFF_W1H, sm + OFF_W1L, tid);
    fill_hilo(w2, sm + OFF_W2H, sm + OFF_W2L, tid);
    // LN: warp per token, 16 tokens per warp; write hi/lo into A tiles
#pragma unroll 1
    for (int it = 0; it < 16; it++) {
        int t = wid + 8*it;
        const float2* xr = (const float2*)(io + base + (size_t)t*DD);
        float2 v0 = xr[lane], v1 = xr[lane + 32];
        float s = v0.x + v0.y + v1.x + v1.y;
#pragma unroll
        for (int o = 16; o; o >>= 1) s += __shfl_xor_sync(0xffffffffu, s, o);
        float mu = s * (1.0f/128.0f);
        float q = (v0.x-mu)*(v0.x-mu) + (v0.y-mu)*(v0.y-mu)
                + (v1.x-mu)*(v1.x-mu) + (v1.y-mu)*(v1.y-mu);
#pragma unroll
        for (int o = 16; o; o >>= 1) q += __shfl_xor_sync(0xffffffffu, q, o);
        float inv = rsqrtf(q * (1.0f/128.0f) + 1e-5f);
#pragma unroll
        for (int j = 0; j < 2; j++) {
            float2 v = j ? v1 : v0;
            int dp = lane + 32*j;
            float y0 = (v.x-mu)*inv*gw[2*dp]   + gb[2*dp];
            float y1 = (v.y-mu)*inv*gw[2*dp+1] + gb[2*dp+1];
            uint32_t hp, lp;
            split2(y0, y1, hp, lp);
            *(uint32_t*)(sm + OFF_AH + t*RSB + 4*dp) = hp;
            *(uint32_t*)(sm + OFF_AL + t*RSB + 4*dp) = lp;
        }
    }
    __syncthreads();
    // GEMM1
    float acc[2][8][4];
#pragma unroll
    for (int mt = 0; mt < 2; mt++)
#pragma unroll
        for (int nt = 0; nt < 8; nt++)
#pragma unroll
            for (int j = 0; j < 4; j++) acc[mt][nt][j] = 0.f;
    mm128(smb + OFF_AH, smb + OFF_AL, smb + OFF_W1H, smb + OFF_W1L, lane, wm, wn, acc);
    __syncthreads();   // everyone done reading A before overwrite
    // bias + gelu -> back into A tiles
#pragma unroll
    for (int mt = 0; mt < 2; mt++)
#pragma unroll
        for (int h = 0; h < 2; h++) {
            int row = wm*32 + mt*16 + (lane >> 2) + 8*h;
#pragma unroll
            for (int nt = 0; nt < 8; nt++) {
                int col = wn*64 + nt*8 + (lane & 3)*2;
                float2 bv = *(const float2*)&b1[col];
                float x0 = acc[mt][nt][2*h]   + bv.x;
                float x1 = acc[mt][nt][2*h+1] + bv.y;
                float g0 = 0.5f * x0 * (1.0f + erff(x0 * 0.70710678118654752f));
                float g1 = 0.5f * x1 * (1.0f + erff(x1 * 0.70710678118654752f));
                uint32_t hp, lp;
                split2(g0, g1, hp, lp);
                *(uint32_t*)(sm + OFF_AH + row*RSB + 2*col) = hp;
                *(uint32_t*)(sm + OFF_AL + row*RSB + 2*col) = lp;
            }
        }
    __syncthreads();
    // GEMM2
    float acc2[2][8][4];
#pragma unroll
    for (int mt = 0; mt < 2; mt++)
#pragma unroll
        for (int nt = 0; nt < 8; nt++)
#pragma unroll
            for (int j = 0; j < 4; j++) acc2[mt][nt][j] = 0.f;
    mm128(smb + OFF_AH, smb + OFF_AL, smb + OFF_W2H, smb + OFF_W2L, lane, wm, wn, acc2);
#pragma unroll
    for (int mt = 0; mt < 2; mt++)
#pragma unroll
        for (int h = 0; h < 2; h++) {
            int row = wm*32 + mt*16 + (lane >> 2) + 8*h;
            float* ir = io + base + (size_t)row*DD;
#pragma unroll
            for (int nt = 0; nt < 8; nt++) {
                int col = wn*64 + nt*8 + (lane & 3)*2;
                float2 bv = *(const float2*)&b2[col];
                float2 v = *(float2*)&ir[col];
                v.x += acc2[mt][nt][2*h]   + bv.x;
                v.y += acc2[mt][nt][2*h+1] + bv.y;
                *(float2*)&ir[col] = v;
            }
        }
}

// ---------------- host launcher ----------------
extern "C" void kernel_launch(void* const* d_in, const int* in_sizes, int n_in,
                              void* d_out, int out_size) {
    (void)in_sizes; (void)n_in; (void)out_size;
    const float* qz  = (const float*)d_in[0];
    const float* un  = (const float*)d_in[1];
    const float* tu  = (const float*)d_in[2];
    const float* tv  = (const float*)d_in[3];
    const float* cu  = (const float*)d_in[4];
    const float* cv  = (const float*)d_in[5];
    const float* bin = (const float*)d_in[6];
    const float* lng = (const float*)d_in[7];
    const float* lnb = (const float*)d_in[8];
    const float* w1  = (const float*)d_in[9];
    const float* b1  = (const float*)d_in[10];
    const float* w2  = (const float*)d_in[11];
    const float* b2  = (const float*)d_in[12];
    float* out = (float*)d_out;

    cudaFuncSetAttribute(k_binT,      cudaFuncAttributeMaxDynamicSharedMemorySize, 128*TSTR*4);
    cudaFuncSetAttribute(k_proj_tc,   cudaFuncAttributeMaxDynamicSharedMemorySize, SM_G4);
    cudaFuncSetAttribute(k_topicS_tc, cudaFuncAttributeMaxDynamicSharedMemorySize, SM_G4);
    cudaFuncSetAttribute(k_topicO_tc, cudaFuncAttributeMaxDynamicSharedMemorySize, SM_TOPICO);
    cudaFuncSetAttribute(k_tattn,     cudaFuncAttributeMaxDynamicSharedMemorySize, SM_TATTN);
    cudaFuncSetAttribute(k_cattn,     cudaFuncAttributeMaxDynamicSharedMemorySize, SM_CATTN);
    cudaFuncSetAttribute(k_mlp_tc,    cudaFuncAttributeMaxDynamicSharedMemorySize, SM_MLP6);

    k_ln<<<(NTOK*32)/256, 256>>>(qz, lng, lnb);
    k_binT<<<dim3(4, BB), 256, 128*TSTR*4>>>(bin);

    dim3 pg(TPB/128, 4, BB);
    k_proj_tc<<<pg, 256, SM_G4>>>(tu, tv, cu, cv);

    dim3 sg(TPB/128, 4, BB);
    k_topicS_tc<<<sg, 256, SM_G4>>>(bin);

    k_tattn<<<BB*CC, 256, SM_TATTN>>>();
    k_cattn<<<BB*PP, 256, SM_CATTN>>>();

    dim3 og(TPB/128, BB);
    k_topicO_tc<<<og, 256, SM_TOPICO>>>();

    k_combine<<<(NELEM/4 + 255)/256, 256>>>((const float4*)un, (const float4*)qz,
                                            (float4*)out);
    k_mlp_tc<<<NTOK/128, 256, SM_MLP6>>>(out, lng, lnb, w1, b1, w2, b2);
}

// round 8
// speedup vs baseline: 1.4233x; 1.1671x over previous
#include <cuda_runtime.h>
#include <cuda_bf16.h>
#include <math.h>
#include <stdint.h>

#define BB 8
#define CC 128
#define PP 96
#define DD 128
#define HH 8
#define GG 512
#define TPB (CC*PP)          // 12288 tokens per batch
#define NTOK (BB*TPB)        // 98304
#define NELEM (NTOK*DD)      // 12582912

#define PSTR 132
#define ASTR 98
#define RSB 272              // smem bf16 tile row stride in BYTES (136 halves)

typedef unsigned long long u64;

__device__ __forceinline__ u64 pk2(float x) {
    u64 r; asm("mov.b64 %0,{%1,%1};" : "=l"(r) : "f"(x)); return r;
}
__device__ __forceinline__ u64 fma2(u64 a, u64 b, u64 c) {
    asm("fma.rn.f32x2 %0,%1,%2,%0;" : "+l"(c) : "l"(a), "l"(b)); return c;
}
__device__ __forceinline__ float2 up2(u64 v) {
    float2 f; asm("mov.b64 {%0,%1},%2;" : "=f"(f.x), "=f"(f.y) : "l"(v)); return f;
}

// ---------------- scratch (device globals: allocation-free) ----------------
__device__ __align__(16) float g_qzn[NELEM];
__device__ __align__(16) __nv_bfloat16 g_qzn_h[NELEM];
__device__ __align__(16) __nv_bfloat16 g_qzn_l[NELEM];
__device__ __align__(16) float g_qut[NELEM];
__device__ __align__(16) float g_qvt[NELEM];
__device__ __align__(16) float g_quc[NELEM];
__device__ __align__(16) float g_qvc[NELEM];
__device__ __align__(16) float g_msg[NELEM];
__device__ __align__(16) __nv_bfloat16 g_Shi[(size_t)NTOK * GG];
__device__ __align__(16) __nv_bfloat16 g_Slo[(size_t)NTOK * GG];
__device__ __align__(16) __nv_bfloat16 g_binT_h[(size_t)BB * DD * GG];
__device__ __align__(16) __nv_bfloat16 g_binT_l[(size_t)BB * DD * GG];

// ================= mma.sync helpers =================
__device__ __forceinline__ uint32_t smem_u32(const void* p) {
    uint32_t a;
    asm("{ .reg .u64 t; cvta.to.shared.u64 t, %1; cvt.u32.u64 %0, t; }" : "=r"(a) : "l"(p));
    return a;
}

#define LDSM4(R, addr) \
    asm volatile("ldmatrix.sync.aligned.m8n8.x4.shared.b16 {%0,%1,%2,%3}, [%4];" \
        : "=r"((R)[0]), "=r"((R)[1]), "=r"((R)[2]), "=r"((R)[3]) : "r"(addr))

#define MMA16816(C, A, b0, b1) \
    asm volatile("mma.sync.aligned.m16n8k16.row.col.f32.bf16.bf16.f32 " \
        "{%0,%1,%2,%3},{%4,%5,%6,%7},{%8,%9},{%0,%1,%2,%3};" \
        : "+f"((C)[0]), "+f"((C)[1]), "+f"((C)[2]), "+f"((C)[3]) \
        : "r"((A)[0]), "r"((A)[1]), "r"((A)[2]), "r"((A)[3]), "r"(b0), "r"(b1))

__device__ __forceinline__ void split2(float x0, float x1, uint32_t& hp, uint32_t& lp) {
    __nv_bfloat16 h0 = __float2bfloat16(x0), h1 = __float2bfloat16(x1);
    __nv_bfloat16 l0 = __float2bfloat16(x0 - __bfloat162float(h0));
    __nv_bfloat16 l1 = __float2bfloat16(x1 - __bfloat162float(h1));
    hp = ((uint32_t)__bfloat16_as_ushort(h1) << 16) | __bfloat16_as_ushort(h0);
    lp = ((uint32_t)__bfloat16_as_ushort(l1) << 16) | __bfloat16_as_ushort(l0);
}

// fp32 128x128 row-major -> hi/lo bf16 smem tiles (row stride RSB bytes)
__device__ __forceinline__ void fill_hilo(const float* __restrict__ src,
                                          char* smHi, char* smLo, int tid) {
    for (int i = tid; i < 128*64; i += 256) {
        int row = i >> 6, cp = (i & 63);
        float2 v = *(const float2*)(src + row*128 + 2*cp);
        uint32_t hp, lp;
        split2(v.x, v.y, hp, lp);
        *(uint32_t*)(smHi + row*RSB + 4*cp) = hp;
        *(uint32_t*)(smLo + row*RSB + 4*cp) = lp;
    }
}

// split-precision 128x128x128 mainloop. acc[2][8][4] per warp.
__device__ __forceinline__ void mm128(uint32_t ah, uint32_t al,
                                      uint32_t bh, uint32_t bl,
                                      int lane, int wm, int wn,
                                      float acc[2][8][4]) {
    int r16 = lane & 15;
    uint32_t aoff = (uint32_t)(wm*32 + r16)*RSB + ((lane >> 4) << 4);
    uint32_t boff = (uint32_t)(wn*64 + r16)*RSB + ((lane >> 4) << 4);
#pragma unroll
    for (int ks = 0; ks < 8; ks++) {
        uint32_t ko = ks * 32;
        uint32_t Ah[2][4], Al[2][4], Bh[4][4], Bl[4][4];
        LDSM4(Ah[0], ah + aoff + ko);
        LDSM4(Ah[1], ah + aoff + 16*RSB + ko);
        LDSM4(Al[0], al + aoff + ko);
        LDSM4(Al[1], al + aoff + 16*RSB + ko);
#pragma unroll
        for (int bt = 0; bt < 4; bt++) {
            LDSM4(Bh[bt], bh + boff + bt*16*RSB + ko);
            LDSM4(Bl[bt], bl + boff + bt*16*RSB + ko);
        }
#pragma unroll
        for (int mt = 0; mt < 2; mt++)
#pragma unroll
            for (int bt = 0; bt < 4; bt++) {
                MMA16816(acc[mt][2*bt],   Ah[mt], Bh[bt][0], Bh[bt][2]);
                MMA16816(acc[mt][2*bt+1], Ah[mt], Bh[bt][1], Bh[bt][3]);
                MMA16816(acc[mt][2*bt],   Ah[mt], Bl[bt][0], Bl[bt][2]);
                MMA16816(acc[mt][2*bt+1], Ah[mt], Bl[bt][1], Bl[bt][3]);
                MMA16816(acc[mt][2*bt],   Al[mt], Bh[bt][0], Bh[bt][2]);
                MMA16816(acc[mt][2*bt+1], Al[mt], Bh[bt][1], Bh[bt][3]);
            }
    }
}

#define TILE_B (128*RSB)     // 34816 bytes per bf16 tile
#define OFF_AH 0
#define OFF_AL (TILE_B)
#define OFF_BH (2*TILE_B)
#define OFF_BL (3*TILE_B)
#define SM_G4 (4*TILE_B)                 // 139264
#define SM_TOPICO (SM_G4 + 512)
#define SM_MLP6 (6*TILE_B)               // 208896
#define OFF_W1H (2*TILE_B)
#define OFF_W1L (3*TILE_B)
#define OFF_W2H (4*TILE_B)
#define OFF_W2L (5*TILE_B)

// ---------------- K1: layernorm -> g_qzn fp32 + hi/lo bf16 ----------------
__global__ __launch_bounds__(256) void k_ln(const float* __restrict__ x,
                                            const float* __restrict__ gw,
                                            const float* __restrict__ gb) {
    int w = (blockIdx.x * 256 + threadIdx.x) >> 5;
    int lane = threadIdx.x & 31;
    if (w >= NTOK) return;
    const float2* xr = (const float2*)(x + (size_t)w * DD);
    float2 v0 = xr[lane], v1 = xr[lane + 32];
    float s = v0.x + v0.y + v1.x + v1.y;
#pragma unroll
    for (int o = 16; o; o >>= 1) s += __shfl_xor_sync(0xffffffffu, s, o);
    float mu = s * (1.0f/128.0f);
    float q = (v0.x-mu)*(v0.x-mu) + (v0.y-mu)*(v0.y-mu)
            + (v1.x-mu)*(v1.x-mu) + (v1.y-mu)*(v1.y-mu);
#pragma unroll
    for (int o = 16; o; o >>= 1) q += __shfl_xor_sync(0xffffffffu, q, o);
    float inv = rsqrtf(q * (1.0f/128.0f) + 1e-5f);
    float2* yr = (float2*)(g_qzn + (size_t)w * DD);
    uint32_t* yh = (uint32_t*)(g_qzn_h + (size_t)w * DD);
    uint32_t* yl = (uint32_t*)(g_qzn_l + (size_t)w * DD);
#pragma unroll
    for (int j = 0; j < 2; j++) {
        float2 v = j ? v1 : v0;
        int dp = lane + 32*j;
        float y0 = (v.x-mu)*inv*gw[2*dp]   + gb[2*dp];
        float y1 = (v.y-mu)*inv*gw[2*dp+1] + gb[2*dp+1];
        yr[dp] = make_float2(y0, y1);
        uint32_t hp, lp;
        split2(y0, y1, hp, lp);
        yh[dp] = hp; yl[dp] = lp;
    }
}

// ---------------- K1b: transpose+split topic_binary -> g_binT [b][d][g] ------
#define TSTR 129
__global__ __launch_bounds__(256) void k_binT(const float* __restrict__ bin) {
    extern __shared__ float smf[];
    int gt = blockIdx.x, b = blockIdx.y;
    int tid = threadIdx.x;
    const float* src = bin + ((size_t)b * GG + (size_t)gt * 128) * DD;
    for (int i = tid; i < 128*128; i += 256) {
        int g = i >> 7, d = i & 127;
        smf[g*TSTR + d] = src[i];
    }
    __syncthreads();
    uint32_t* oh = (uint32_t*)(g_binT_h + (size_t)b * DD * GG + (size_t)gt * 128);
    uint32_t* ol = (uint32_t*)(g_binT_l + (size_t)b * DD * GG + (size_t)gt * 128);
    for (int i = tid; i < 128*64; i += 256) {
        int d = i >> 6, gp = i & 63;
        float v0 = smf[(2*gp)*TSTR + d], v1 = smf[(2*gp+1)*TSTR + d];
        uint32_t hp, lp;
        split2(v0, v1, hp, lp);
        size_t o = ((size_t)d * GG) / 2 + gp;   // u32 units within [d][512]
        oh[o] = hp; ol[o] = lp;
    }
}

// ---------------- K2: tensor projections: y = qzn @ W^T per batch ----------
__global__ __launch_bounds__(256) void k_proj_tc(const float* __restrict__ tu,
                                                 const float* __restrict__ tv,
                                                 const float* __restrict__ cu,
                                                 const float* __restrict__ cv) {
    extern __shared__ char sm[];
    uint32_t smb = smem_u32(sm);
    int tid = threadIdx.x, wid = tid >> 5, lane = tid & 31;
    int wm = wid & 3, wn = wid >> 2;
    int tile = blockIdx.x, pj = blockIdx.y, b = blockIdx.z;
    const float* w = (pj == 0) ? tu : (pj == 1) ? tv : (pj == 2) ? cu : cv;
    float* y = (pj == 0) ? g_qut : (pj == 1) ? g_qvt : (pj == 2) ? g_quc : g_qvc;
    size_t tokbase = (size_t)b * TPB + (size_t)tile * 128;
    {
        const uint32_t* sh = (const uint32_t*)(g_qzn_h + tokbase * DD);
        const uint32_t* sl = (const uint32_t*)(g_qzn_l + tokbase * DD);
        for (int i = tid; i < 128*64; i += 256) {
            int row = i >> 6, cp = i & 63;
            *(uint32_t*)(sm + OFF_AH + row*RSB + 4*cp) = sh[row*64 + cp];
            *(uint32_t*)(sm + OFF_AL + row*RSB + 4*cp) = sl[row*64 + cp];
        }
    }
    fill_hilo(w + (size_t)b * DD * DD, sm + OFF_BH, sm + OFF_BL, tid);
    __syncthreads();
    float acc[2][8][4];
#pragma unroll
    for (int mt = 0; mt < 2; mt++)
#pragma unroll
        for (int nt = 0; nt < 8; nt++)
#pragma unroll
            for (int j = 0; j < 4; j++) acc[mt][nt][j] = 0.f;
    mm128(smb + OFF_AH, smb + OFF_AL, smb + OFF_BH, smb + OFF_BL, lane, wm, wn, acc);
#pragma unroll
    for (int mt = 0; mt < 2; mt++)
#pragma unroll
        for (int h = 0; h < 2; h++) {
            int row = wm*32 + mt*16 + (lane >> 2) + 8*h;
            float* yr = y + (tokbase + row) * DD;
#pragma unroll
            for (int nt = 0; nt < 8; nt++) {
                int col = wn*64 + nt*8 + (lane & 3)*2;
                *(float2*)&yr[col] = make_float2(acc[mt][nt][2*h], acc[mt][nt][2*h+1]);
            }
        }
}

// ---------------- K3: topic scores S = relu(qzn @ bin^T) -> hi/lo ----------
__global__ __launch_bounds__(256) void k_topicS_tc(const float* __restrict__ bin) {
    extern __shared__ char sm[];
    uint32_t smb = smem_u32(sm);
    int tid = threadIdx.x, wid = tid >> 5, lane = tid & 31;
    int wm = wid & 3, wn = wid >> 2;
    int tile = blockIdx.x, gt = blockIdx.y, b = blockIdx.z;
    size_t tokbase = (size_t)b * TPB + (size_t)tile * 128;
    {
        const uint32_t* sh = (const uint32_t*)(g_qzn_h + tokbase * DD);
        const uint32_t* sl = (const uint32_t*)(g_qzn_l + tokbase * DD);
        for (int i = tid; i < 128*64; i += 256) {
            int row = i >> 6, cp = i & 63;
            *(uint32_t*)(sm + OFF_AH + row*RSB + 4*cp) = sh[row*64 + cp];
            *(uint32_t*)(sm + OFF_AL + row*RSB + 4*cp) = sl[row*64 + cp];
        }
    }
    fill_hilo(bin + ((size_t)b * GG + (size_t)gt * 128) * DD, sm + OFF_BH, sm + OFF_BL, tid);
    __syncthreads();
    float acc[2][8][4];
#pragma unroll
    for (int mt = 0; mt < 2; mt++)
#pragma unroll
        for (int nt = 0; nt < 8; nt++)
#pragma unroll
            for (int j = 0; j < 4; j++) acc[mt][nt][j] = 0.f;
    mm128(smb + OFF_AH, smb + OFF_AL, smb + OFF_BH, smb + OFF_BL, lane, wm, wn, acc);
#pragma unroll
    for (int mt = 0; mt < 2; mt++)
#pragma unroll
        for (int h = 0; h < 2; h++) {
            int row = wm*32 + mt*16 + (lane >> 2) + 8*h;
            uint32_t* shp = (uint32_t*)&g_Shi[(tokbase + row) * GG + gt*128];
            uint32_t* slp = (uint32_t*)&g_Slo[(tokbase + row) * GG + gt*128];
#pragma unroll
            for (int nt = 0; nt < 8; nt++) {
                int col = wn*64 + nt*8 + (lane & 3)*2;
                float f0 = fmaxf(acc[mt][nt][2*h], 0.f);
                float f1 = fmaxf(acc[mt][nt][2*h+1], 0.f);
                uint32_t hp, lp;
                split2(f0, f1, hp, lp);
                shp[col >> 1] = hp;
                slp[col >> 1] = lp;
            }
        }
}

// ---------------- K4: topic out + final combine -> d_out ----------
// d_out = 0.5*(unary + old + g_msg + (S/rowsum)@bin)
__global__ __launch_bounds__(256) void k_topicO_tc(const float* __restrict__ un,
                                                   const float* __restrict__ old,
                                                   float* __restrict__ out) {
    extern __shared__ char sm[];
    uint32_t smb = smem_u32(sm);
    float* rs = (float*)(sm + SM_G4);
    int tid = threadIdx.x, wid = tid >> 5, lane = tid & 31;
    int wm = wid & 3, wn = wid >> 2;
    int tile = blockIdx.x, b = blockIdx.y;
    size_t btok = (size_t)b * TPB + (size_t)tile * 128;
    if (tid < 128) rs[tid] = 0.f;
    __syncthreads();
    float acc[2][8][4];
#pragma unroll
    for (int mt = 0; mt < 2; mt++)
#pragma unroll
        for (int nt = 0; nt < 8; nt++)
#pragma unroll
            for (int j = 0; j < 4; j++) acc[mt][nt][j] = 0.f;

    for (int gc = 0; gc < 4; gc++) {
        if (gc) __syncthreads();
        for (int i = tid; i < 128*64; i += 256) {
            int row = i >> 6, cp = i & 63;
            uint32_t hp = *(const uint32_t*)&g_Shi[(btok + row) * GG + gc*128 + 2*cp];
            uint32_t lp = *(const uint32_t*)&g_Slo[(btok + row) * GG + gc*128 + 2*cp];
            *(uint32_t*)(sm + OFF_AH + row*RSB + 4*cp) = hp;
            *(uint32_t*)(sm + OFF_AL + row*RSB + 4*cp) = lp;
            __nv_bfloat162 h2 = *reinterpret_cast<__nv_bfloat162*>(&hp);
            __nv_bfloat162 l2 = *reinterpret_cast<__nv_bfloat162*>(&lp);
            float2 fh = __bfloat1622float2(h2), fl = __bfloat1622float2(l2);
            float v = fh.x + fh.y + fl.x + fl.y;
#pragma unroll
            for (int o = 16; o; o >>= 1) v += __shfl_xor_sync(0xffffffffu, v, o);
            if (lane == 0) atomicAdd(&rs[row], v);
        }
        {
            const uint32_t* bh = (const uint32_t*)(g_binT_h + (size_t)b * DD * GG + gc*128);
            const uint32_t* bl = (const uint32_t*)(g_binT_l + (size_t)b * DD * GG + gc*128);
            for (int i = tid; i < 128*64; i += 256) {
                int d = i >> 6, gp = i & 63;
                size_t o = (size_t)d * (GG/2) + gp;
                *(uint32_t*)(sm + OFF_BH + d*RSB + 4*gp) = bh[o];
                *(uint32_t*)(sm + OFF_BL + d*RSB + 4*gp) = bl[o];
            }
        }
        __syncthreads();
        mm128(smb + OFF_AH, smb + OFF_AL, smb + OFF_BH, smb + OFF_BL, lane, wm, wn, acc);
    }
#pragma unroll
    for (int mt = 0; mt < 2; mt++)
#pragma unroll
        for (int h = 0; h < 2; h++) {
            int row = wm*32 + mt*16 + (lane >> 2) + 8*h;
            float inv = 1.0f / fmaxf(rs[row], 1e-6f);
            size_t rbase = (btok + row) * DD;
#pragma unroll
            for (int nt = 0; nt < 8; nt++) {
                int col = wn*64 + nt*8 + (lane & 3)*2;
                float2 m = *(const float2*)&g_msg[rbase + col];
                float2 u = *(const float2*)&un[rbase + col];
                float2 o = *(const float2*)&old[rbase + col];
                float2 r;
                r.x = 0.5f*(u.x + o.x + m.x + acc[mt][nt][2*h]   * inv);
                r.y = 0.5f*(u.y + o.y + m.y + acc[mt][nt][2*h+1] * inv);
                *(float2*)&out[rbase + col] = r;
            }
        }
}

// ---------------- K5: time attention (head-sum folded) -> g_msg ------------
#define SM_TATTN ((3*96*PSTR + 96*ASTR)*4)
__global__ __launch_bounds__(256) void k_tattn() {
    extern __shared__ float smf[];
    float* Xs = smf;                 // 96 x PSTR
    float* Qu = Xs + 96*PSTR;
    float* Qv = Qu + 96*PSTR;
    float* As = Qv + 96*PSTR;        // 96 x ASTR : accumulated sum_h probs
    int tid = threadIdx.x, lane = tid & 31, wg = tid >> 5;
    size_t base = (size_t)blockIdx.x * PP * DD;
    for (int i = tid; i < PP*DD; i += 256) {
        int r = i >> 7, d = i & 127;
        Xs[r*PSTR+d] = g_qzn[base + i];
        Qu[r*PSTR+d] = g_qut[base + i];
        Qv[r*PSTR+d] = g_qvt[base + i];
    }
    // zero As (ownership: thread (wg,lane) owns As[wg+8k][lane+32j])
#pragma unroll
    for (int k = 0; k < 12; k++)
#pragma unroll
        for (int j = 0; j < 3; j++)
            As[(wg + 8*k)*ASTR + lane + 32*j] = 0.f;
    __syncthreads();

    // logits + softmax, accumulate probs over heads (no syncs needed inside)
    for (int h = 0; h < HH; h++) {
        int ho = h * 16;
#pragma unroll 1
        for (int pr = 0; pr < 12; pr++) {
            int p = wg + 8*pr;
            u64 qu2[8];
#pragma unroll
            for (int r = 0; r < 8; r++) qu2[r] = *(const u64*)&Qu[p*PSTR + ho + 2*r];
            float lg[3];
#pragma unroll
            for (int qi = 0; qi < 3; qi++) {
                int q = lane + 32*qi;
                u64 s2 = 0ull;
#pragma unroll
                for (int r = 0; r < 8; r++) {
                    u64 qv2 = *(const u64*)&Qv[q*PSTR + ho + 2*r];
                    s2 = fma2(qu2[r], qv2, s2);
                }
                float2 sp = up2(s2);
                lg[qi] = (sp.x + sp.y) * 0.25f;
            }
            float mx = fmaxf(lg[0], fmaxf(lg[1], lg[2]));
#pragma unroll
            for (int o = 16; o; o >>= 1) mx = fmaxf(mx, __shfl_xor_sync(0xffffffffu, mx, o));
            float e0 = expf(lg[0]-mx), e1 = expf(lg[1]-mx), e2 = expf(lg[2]-mx);
            float ssum = e0 + e1 + e2;
#pragma unroll
            for (int o = 16; o; o >>= 1) ssum += __shfl_xor_sync(0xffffffffu, ssum, o);
            float inv = 0.125f / ssum;            // fold 1/H
            As[p*ASTR + lane]      += e0 * inv;
            As[p*ASTR + lane + 32] += e1 * inv;
            As[p*ASTR + lane + 64] += e2 * inv;
        }
    }
    __syncthreads();

    // single AV pass: msg = (sum_h A_h) @ X
    u64 acc[12][2];
#pragma unroll
    for (int k = 0; k < 12; k++) { acc[k][0] = 0ull; acc[k][1] = 0ull; }
#pragma unroll 2
    for (int q = 0; q < PP; q++) {
        ulonglong2 xA = *(const ulonglong2*)&Xs[q*PSTR + 4*lane];
#pragma unroll
        for (int k = 0; k < 12; k++) {
            u64 ap = pk2(As[(wg + 8*k)*ASTR + q]);
            acc[k][0] = fma2(ap, xA.x, acc[k][0]);
            acc[k][1] = fma2(ap, xA.y, acc[k][1]);
        }
    }
#pragma unroll
    for (int k = 0; k < 12; k++) {
        int p = wg + 8*k;
        float2 p0 = up2(acc[k][0]), p1 = up2(acc[k][1]);
        *(float4*)&g_msg[base + (size_t)p*DD + 4*lane] = make_float4(p0.x, p0.y, p1.x, p1.y);
    }
}

// ---------------- K6: channel attention -> g_msg += ----------------
#define SM_CATTN (3*128*PSTR*4)
__global__ __launch_bounds__(256) void k_cattn() {
    extern __shared__ float smf[];
    float* Qu = smf;                 // 128 x PSTR
    float* Qv = Qu + 128*PSTR;
    float* Ac = Qv + 128*PSTR;
    int b = blockIdx.x / PP, p = blockIdx.x % PP;
    int tid = threadIdx.x, lane = tid & 31, wg = tid >> 5;
    for (int i = tid; i < CC*DD; i += 256) {
        int c = i >> 7, d = i & 127;
        size_t gi = (((size_t)b*CC + c)*PP + p)*DD + d;
        Qu[c*PSTR+d] = g_quc[gi];
        Qv[c*PSTR+d] = g_qvc[gi];
        Ac[c*PSTR+d] = 0.f;
    }
    __syncthreads();
    for (int h = 0; h < HH; h++) {
        int ho = h*16;
#pragma unroll 1
        for (int cr = 0; cr < 16; cr++) {
            int c = wg + 8*cr;
            u64 qu2[8];
#pragma unroll
            for (int r = 0; r < 8; r++) qu2[r] = *(const u64*)&Qu[c*PSTR + ho + 2*r];
            float lg[4];
#pragma unroll
            for (int j = 0; j < 4; j++) {
                int d = lane + 32*j;
                u64 s2 = 0ull;
#pragma unroll
                for (int r = 0; r < 8; r++) {
                    u64 qv2 = *(const u64*)&Qv[d*PSTR + ho + 2*r];
                    s2 = fma2(qu2[r], qv2, s2);
                }
                float2 sp = up2(s2);
                lg[j] = (sp.x + sp.y) * 0.25f;
            }
            float mx = fmaxf(fmaxf(lg[0], lg[1]), fmaxf(lg[2], lg[3]));
#pragma unroll
            for (int o = 16; o; o >>= 1) mx = fmaxf(mx, __shfl_xor_sync(0xffffffffu, mx, o));
            float e[4], ssum = 0.f;
#pragma unroll
            for (int j = 0; j < 4; j++) { e[j] = expf(lg[j] - mx); ssum += e[j]; }
#pragma unroll
            for (int o = 16; o; o >>= 1) ssum += __shfl_xor_sync(0xffffffffu, ssum, o);
            float inv = 0.125f / ssum;            // fold 1/H
#pragma unroll
            for (int j = 0; j < 4; j++) Ac[c*PSTR + lane + 32*j] += e[j] * inv;
        }
    }
#pragma unroll
    for (int cr = 0; cr < 16; cr++) {
        int c = wg + 8*cr;
#pragma unroll
        for (int j = 0; j < 4; j++) {
            int d = lane + 32*j;
            size_t gi = (((size_t)b*CC + c)*PP + p)*DD + d;
            g_msg[gi] += Ac[c*PSTR+d] * g_qzn[gi];
        }
    }
}

// ---------------- K8: LN + MLP (tensor) + residual, in-place on d_out -------
__global__ __launch_bounds__(256) void k_mlp_tc(float* __restrict__ io,
                                                const float* __restrict__ gw,
                                                const float* __restrict__ gb,
                                                const float* __restrict__ w1,
                                                const float* __restrict__ b1,
                                                const float* __restrict__ w2,
                                                const float* __restrict__ b2) {
    extern __shared__ char sm[];
    uint32_t smb = smem_u32(sm);
    int tid = threadIdx.x, wid = tid >> 5, lane = tid & 31;
    int wm = wid & 3, wn = wid >> 2;
    size_t base = (size_t)blockIdx.x * 128 * DD;
    fill_hilo(w1, sm + OFF_W1H, sm + OFF_W1L, tid);
    fill_hilo(w2, sm + OFF_W2H, sm + OFF_W2L, tid);
#pragma unroll 1
    for (int it = 0; it < 16; it++) {
        int t = wid + 8*it;
        const float2* xr = (const float2*)(io + base + (size_t)t*DD);
        float2 v0 = xr[lane], v1 = xr[lane + 32];
        float s = v0.x + v0.y + v1.x + v1.y;
#pragma unroll
        for (int o = 16; o; o >>= 1) s += __shfl_xor_sync(0xffffffffu, s, o);
        float mu = s * (1.0f/128.0f);
        float q = (v0.x-mu)*(v0.x-mu) + (v0.y-mu)*(v0.y-mu)
                + (v1.x-mu)*(v1.x-mu) + (v1.y-mu)*(v1.y-mu);
#pragma unroll
        for (int o = 16; o; o >>= 1) q += __shfl_xor_sync(0xffffffffu, q, o);
        float inv = rsqrtf(q * (1.0f/128.0f) + 1e-5f);
#pragma unroll
        for (int j = 0; j < 2; j++) {
            float2 v = j ? v1 : v0;
            int dp = lane + 32*j;
            float y0 = (v.x-mu)*inv*gw[2*dp]   + gb[2*dp];
            float y1 = (v.y-mu)*inv*gw[2*dp+1] + gb[2*dp+1];
            uint32_t hp, lp;
            split2(y0, y1, hp, lp);
            *(uint32_t*)(sm + OFF_AH + t*RSB + 4*dp) = hp;
            *(uint32_t*)(sm + OFF_AL + t*RSB + 4*dp) = lp;
        }
    }
    __syncthreads();
    float acc[2][8][4];
#pragma unroll
    for (int mt = 0; mt < 2; mt++)
#pragma unroll
        for (int nt = 0; nt < 8; nt++)
#pragma unroll
            for (int j = 0; j < 4; j++) acc[mt][nt][j] = 0.f;
    mm128(smb + OFF_AH, smb + OFF_AL, smb + OFF_W1H, smb + OFF_W1L, lane, wm, wn, acc);
    __syncthreads();
#pragma unroll
    for (int mt = 0; mt < 2; mt++)
#pragma unroll
        for (int h = 0; h < 2; h++) {
            int row = wm*32 + mt*16 + (lane >> 2) + 8*h;
#pragma unroll
            for (int nt = 0; nt < 8; nt++) {
                int col = wn*64 + nt*8 + (lane & 3)*2;
                float2 bv = *(const float2*)&b1[col];
                float x0 = acc[mt][nt][2*h]   + bv.x;
                float x1 = acc[mt][nt][2*h+1] + bv.y;
                float g0 = 0.5f * x0 * (1.0f + erff(x0 * 0.70710678118654752f));
                float g1 = 0.5f * x1 * (1.0f + erff(x1 * 0.70710678118654752f));
                uint32_t hp, lp;
                split2(g0, g1, hp, lp);
                *(uint32_t*)(sm + OFF_AH + row*RSB + 2*col) = hp;
                *(uint32_t*)(sm + OFF_AL + row*RSB + 2*col) = lp;
            }
        }
    __syncthreads();
    float acc2[2][8][4];
#pragma unroll
    for (int mt = 0; mt < 2; mt++)
#pragma unroll
        for (int nt = 0; nt < 8; nt++)
#pragma unroll
            for (int j = 0; j < 4; j++) acc2[mt][nt][j] = 0.f;
    mm128(smb + OFF_AH, smb + OFF_AL, smb + OFF_W2H, smb + OFF_W2L, lane, wm, wn, acc2);
#pragma unroll
    for (int mt = 0; mt < 2; mt++)
#pragma unroll
        for (int h = 0; h < 2; h++) {
            int row = wm*32 + mt*16 + (lane >> 2) + 8*h;
            float* ir = io + base + (size_t)row*DD;
#pragma unroll
            for (int nt = 0; nt < 8; nt++) {
                int col = wn*64 + nt*8 + (lane & 3)*2;
                float2 bv = *(const float2*)&b2[col];
                float2 v = *(float2*)&ir[col];
                v.x += acc2[mt][nt][2*h]   + bv.x;
                v.y += acc2[mt][nt][2*h+1] + bv.y;
                *(float2*)&ir[col] = v;
            }
        }
}

// ---------------- host launcher ----------------
extern "C" void kernel_launch(void* const* d_in, const int* in_sizes, int n_in,
                              void* d_out, int out_size) {
    (void)in_sizes; (void)n_in; (void)out_size;
    const float* qz  = (const float*)d_in[0];
    const float* un  = (const float*)d_in[1];
    const float* tu  = (const float*)d_in[2];
    const float* tv  = (const float*)d_in[3];
    const float* cu  = (const float*)d_in[4];
    const float* cv  = (const float*)d_in[5];
    const float* bin = (const float*)d_in[6];
    const float* lng = (const float*)d_in[7];
    const float* lnb = (const float*)d_in[8];
    const float* w1  = (const float*)d_in[9];
    const float* b1  = (const float*)d_in[10];
    const float* w2  = (const float*)d_in[11];
    const float* b2  = (const float*)d_in[12];
    float* out = (float*)d_out;

    cudaFuncSetAttribute(k_binT,      cudaFuncAttributeMaxDynamicSharedMemorySize, 128*TSTR*4);
    cudaFuncSetAttribute(k_proj_tc,   cudaFuncAttributeMaxDynamicSharedMemorySize, SM_G4);
    cudaFuncSetAttribute(k_topicS_tc, cudaFuncAttributeMaxDynamicSharedMemorySize, SM_G4);
    cudaFuncSetAttribute(k_topicO_tc, cudaFuncAttributeMaxDynamicSharedMemorySize, SM_TOPICO);
    cudaFuncSetAttribute(k_tattn,     cudaFuncAttributeMaxDynamicSharedMemorySize, SM_TATTN);
    cudaFuncSetAttribute(k_cattn,     cudaFuncAttributeMaxDynamicSharedMemorySize, SM_CATTN);
    cudaFuncSetAttribute(k_mlp_tc,    cudaFuncAttributeMaxDynamicSharedMemorySize, SM_MLP6);

    k_ln<<<(NTOK*32)/256, 256>>>(qz, lng, lnb);
    k_binT<<<dim3(4, BB), 256, 128*TSTR*4>>>(bin);

    dim3 pg(TPB/128, 4, BB);
    k_proj_tc<<<pg, 256, SM_G4>>>(tu, tv, cu, cv);

    dim3 sg(TPB/128, 4, BB);
    k_topicS_tc<<<sg, 256, SM_G4>>>(bin);

    k_tattn<<<BB*CC, 256, SM_TATTN>>>();
    k_cattn<<<BB*PP, 256, SM_CATTN>>>();

    dim3 og(TPB/128, BB);
    k_topicO_tc<<<og, 256, SM_TOPICO>>>(un, qz, out);

    k_mlp_tc<<<NTOK/128, 256, SM_MLP6>>>(out, lng, lnb, w1, b1, w2, b2);
}

// round 9
// speedup vs baseline: 1.6498x; 1.1591x over previous
#include <cuda_runtime.h>
#include <cuda_bf16.h>
#include <math.h>
#include <stdint.h>

#define BB 8
#define CC 128
#define PP 96
#define DD 128
#define HH 8
#define GG 512
#define TPB (CC*PP)          // 12288 tokens per batch
#define NTOK (BB*TPB)        // 98304
#define NELEM (NTOK*DD)      // 12582912

#define PSTR 132
#define ASTR 98
#define RSB 272              // smem bf16 tile row stride in BYTES (136 halves)

typedef unsigned long long u64;

__device__ __forceinline__ u64 pk2(float x) {
    u64 r; asm("mov.b64 %0,{%1,%1};" : "=l"(r) : "f"(x)); return r;
}
__device__ __forceinline__ u64 fma2(u64 a, u64 b, u64 c) {
    asm("fma.rn.f32x2 %0,%1,%2,%0;" : "+l"(c) : "l"(a), "l"(b)); return c;
}
__device__ __forceinline__ float2 up2(u64 v) {
    float2 f; asm("mov.b64 {%0,%1},%2;" : "=f"(f.x), "=f"(f.y) : "l"(v)); return f;
}

// fast exp on fma/alu pipes only (no MUFU). valid for |x| < ~80.
__device__ __forceinline__ float fexp(float x) {
    float t = x * 1.4426950408889634f;
    float fi = floorf(t);
    float f = t - fi;
    float p = 0.0018775767f;
    p = p * f + 0.0089893397f;
    p = p * f + 0.0558186204f;
    p = p * f + 0.2402301537f;
    p = p * f + 0.6931469188f;
    p = p * f + 1.0f;
    int ei = (int)fi;
    return p * __int_as_float((ei + 127) << 23);
}

// ---------------- scratch (device globals: allocation-free) ----------------
__device__ __align__(16) float g_qzn[NELEM];
__device__ __align__(16) __nv_bfloat16 g_qzn_h[NELEM];
__device__ __align__(16) __nv_bfloat16 g_qzn_l[NELEM];
__device__ __align__(16) float g_qut[NELEM];
__device__ __align__(16) float g_qvt[NELEM];
__device__ __align__(16) float g_quc[NELEM];
__device__ __align__(16) float g_qvc[NELEM];
__device__ __align__(16) float g_msg[NELEM];
__device__ __align__(16) __nv_bfloat16 g_Shi[(size_t)NTOK * GG];
__device__ __align__(16) __nv_bfloat16 g_Slo[(size_t)NTOK * GG];
__device__ __align__(16) __nv_bfloat16 g_binT_h[(size_t)BB * DD * GG];
__device__ __align__(16) __nv_bfloat16 g_binT_l[(size_t)BB * DD * GG];

// ================= mma.sync helpers =================
__device__ __forceinline__ uint32_t smem_u32(const void* p) {
    uint32_t a;
    asm("{ .reg .u64 t; cvta.to.shared.u64 t, %1; cvt.u32.u64 %0, t; }" : "=r"(a) : "l"(p));
    return a;
}

#define LDSM4(R, addr) \
    asm volatile("ldmatrix.sync.aligned.m8n8.x4.shared.b16 {%0,%1,%2,%3}, [%4];" \
        : "=r"((R)[0]), "=r"((R)[1]), "=r"((R)[2]), "=r"((R)[3]) : "r"(addr))

#define MMA16816(C, A, b0, b1) \
    asm volatile("mma.sync.aligned.m16n8k16.row.col.f32.bf16.bf16.f32 " \
        "{%0,%1,%2,%3},{%4,%5,%6,%7},{%8,%9},{%0,%1,%2,%3};" \
        : "+f"((C)[0]), "+f"((C)[1]), "+f"((C)[2]), "+f"((C)[3]) \
        : "r"((A)[0]), "r"((A)[1]), "r"((A)[2]), "r"((A)[3]), "r"(b0), "r"(b1))

__device__ __forceinline__ void split2(float x0, float x1, uint32_t& hp, uint32_t& lp) {
    __nv_bfloat16 h0 = __float2bfloat16(x0), h1 = __float2bfloat16(x1);
    __nv_bfloat16 l0 = __float2bfloat16(x0 - __bfloat162float(h0));
    __nv_bfloat16 l1 = __float2bfloat16(x1 - __bfloat162float(h1));
    hp = ((uint32_t)__bfloat16_as_ushort(h1) << 16) | __bfloat16_as_ushort(h0);
    lp = ((uint32_t)__bfloat16_as_ushort(l1) << 16) | __bfloat16_as_ushort(l0);
}

// fp32 128x128 row-major -> hi/lo bf16 smem tiles (row stride RSB bytes)
__device__ __forceinline__ void fill_hilo(const float* __restrict__ src,
                                          char* smHi, char* smLo, int tid) {
    for (int i = tid; i < 128*64; i += 256) {
        int row = i >> 6, cp = (i & 63);
        float2 v = *(const float2*)(src + row*128 + 2*cp);
        uint32_t hp, lp;
        split2(v.x, v.y, hp, lp);
        *(uint32_t*)(smHi + row*RSB + 4*cp) = hp;
        *(uint32_t*)(smLo + row*RSB + 4*cp) = lp;
    }
}

// ---- M=64 split-precision mainloop: C[64x128] = A[64x128] * B^T ----
// warps: wm = wid&1 (32 M-rows), wn = wid>>1 (32 N-cols). acc[2][4][4].
__device__ __forceinline__ void mm64(uint32_t ah, uint32_t al,
                                     uint32_t bh, uint32_t bl,
                                     int lane, int wm, int wn,
                                     float acc[2][4][4]) {
    int r16 = lane & 15;
    uint32_t aoff = (uint32_t)(wm*32 + r16)*RSB + ((lane >> 4) << 4);
    uint32_t boff = (uint32_t)(wn*32 + r16)*RSB + ((lane >> 4) << 4);
#pragma unroll
    for (int ks = 0; ks < 8; ks++) {
        uint32_t ko = ks * 32;
        uint32_t Ah[2][4], Al[2][4], Bh[2][4], Bl[2][4];
        LDSM4(Ah[0], ah + aoff + ko);
        LDSM4(Ah[1], ah + aoff + 16*RSB + ko);
        LDSM4(Al[0], al + aoff + ko);
        LDSM4(Al[1], al + aoff + 16*RSB + ko);
#pragma unroll
        for (int bt = 0; bt < 2; bt++) {
            LDSM4(Bh[bt], bh + boff + bt*16*RSB + ko);
            LDSM4(Bl[bt], bl + boff + bt*16*RSB + ko);
        }
#pragma unroll
        for (int mt = 0; mt < 2; mt++)
#pragma unroll
            for (int bt = 0; bt < 2; bt++) {
                MMA16816(acc[mt][2*bt],   Ah[mt], Bh[bt][0], Bh[bt][2]);
                MMA16816(acc[mt][2*bt+1], Ah[mt], Bh[bt][1], Bh[bt][3]);
                MMA16816(acc[mt][2*bt],   Ah[mt], Bl[bt][0], Bl[bt][2]);
                MMA16816(acc[mt][2*bt+1], Ah[mt], Bl[bt][1], Bl[bt][3]);
                MMA16816(acc[mt][2*bt],   Al[mt], Bh[bt][0], Bh[bt][2]);
                MMA16816(acc[mt][2*bt+1], Al[mt], Bh[bt][1], Bh[bt][3]);
            }
    }
}

// ---- M=128 mainloop (used by MLP) ----
__device__ __forceinline__ void mm128(uint32_t ah, uint32_t al,
                                      uint32_t bh, uint32_t bl,
                                      int lane, int wm, int wn,
                                      float acc[2][8][4]) {
    int r16 = lane & 15;
    uint32_t aoff = (uint32_t)(wm*32 + r16)*RSB + ((lane >> 4) << 4);
    uint32_t boff = (uint32_t)(wn*64 + r16)*RSB + ((lane >> 4) << 4);
#pragma unroll
    for (int ks = 0; ks < 8; ks++) {
        uint32_t ko = ks * 32;
        uint32_t Ah[2][4], Al[2][4], Bh[4][4], Bl[4][4];
        LDSM4(Ah[0], ah + aoff + ko);
        LDSM4(Ah[1], ah + aoff + 16*RSB + ko);
        LDSM4(Al[0], al + aoff + ko);
        LDSM4(Al[1], al + aoff + 16*RSB + ko);
#pragma unroll
        for (int bt = 0; bt < 4; bt++) {
            LDSM4(Bh[bt], bh + boff + bt*16*RSB + ko);
            LDSM4(Bl[bt], bl + boff + bt*16*RSB + ko);
        }
#pragma unroll
        for (int mt = 0; mt < 2; mt++)
#pragma unroll
            for (int bt = 0; bt < 4; bt++) {
                MMA16816(acc[mt][2*bt],   Ah[mt], Bh[bt][0], Bh[bt][2]);
                MMA16816(acc[mt][2*bt+1], Ah[mt], Bh[bt][1], Bh[bt][3]);
                MMA16816(acc[mt][2*bt],   Ah[mt], Bl[bt][0], Bl[bt][2]);
                MMA16816(acc[mt][2*bt+1], Ah[mt], Bl[bt][1], Bl[bt][3]);
                MMA16816(acc[mt][2*bt],   Al[mt], Bh[bt][0], Bh[bt][2]);
                MMA16816(acc[mt][2*bt+1], Al[mt], Bh[bt][1], Bh[bt][3]);
            }
    }
}

#define TILE_B (128*RSB)     // 34816 bytes per 128-row bf16 tile
#define A64 (64*RSB)         // 17408 bytes per 64-row tile
// M=64 GEMM smem layout
#define O64_AH 0
#define O64_AL A64
#define O64_BH (2*A64)
#define O64_BL (2*A64 + TILE_B)
#define SM_G64 (2*A64 + 2*TILE_B)        // 104448 -> 2 CTAs/SM
#define SM_TOPICO64 (SM_G64 + 256)
// MLP smem layout (M=128)
#define OFF_AH 0
#define OFF_AL (TILE_B)
#define OFF_W1H (2*TILE_B)
#define OFF_W1L (3*TILE_B)
#define OFF_W2H (4*TILE_B)
#define OFF_W2L (5*TILE_B)
#define SM_MLP6 (6*TILE_B)               // 208896

// ---------------- K1: layernorm -> g_qzn fp32 + hi/lo bf16 ----------------
__global__ __launch_bounds__(256) void k_ln(const float* __restrict__ x,
                                            const float* __restrict__ gw,
                                            const float* __restrict__ gb) {
    int w = (blockIdx.x * 256 + threadIdx.x) >> 5;
    int lane = threadIdx.x & 31;
    if (w >= NTOK) return;
    const float2* xr = (const float2*)(x + (size_t)w * DD);
    float2 v0 = xr[lane], v1 = xr[lane + 32];
    float s = v0.x + v0.y + v1.x + v1.y;
#pragma unroll
    for (int o = 16; o; o >>= 1) s += __shfl_xor_sync(0xffffffffu, s, o);
    float mu = s * (1.0f/128.0f);
    float q = (v0.x-mu)*(v0.x-mu) + (v0.y-mu)*(v0.y-mu)
            + (v1.x-mu)*(v1.x-mu) + (v1.y-mu)*(v1.y-mu);
#pragma unroll
    for (int o = 16; o; o >>= 1) q += __shfl_xor_sync(0xffffffffu, q, o);
    float inv = rsqrtf(q * (1.0f/128.0f) + 1e-5f);
    float2* yr = (float2*)(g_qzn + (size_t)w * DD);
    uint32_t* yh = (uint32_t*)(g_qzn_h + (size_t)w * DD);
    uint32_t* yl = (uint32_t*)(g_qzn_l + (size_t)w * DD);
#pragma unroll
    for (int j = 0; j < 2; j++) {
        float2 v = j ? v1 : v0;
        int dp = lane + 32*j;
        float y0 = (v.x-mu)*inv*gw[2*dp]   + gb[2*dp];
        float y1 = (v.y-mu)*inv*gw[2*dp+1] + gb[2*dp+1];
        yr[dp] = make_float2(y0, y1);
        uint32_t hp, lp;
        split2(y0, y1, hp, lp);
        yh[dp] = hp; yl[dp] = lp;
    }
}

// ---------------- K1b: transpose+split topic_binary -> g_binT [b][d][g] ------
#define TSTR 129
__global__ __launch_bounds__(256) void k_binT(const float* __restrict__ bin) {
    extern __shared__ float smf[];
    int gt = blockIdx.x, b = blockIdx.y;
    int tid = threadIdx.x;
    const float* src = bin + ((size_t)b * GG + (size_t)gt * 128) * DD;
    for (int i = tid; i < 128*128; i += 256) {
        int g = i >> 7, d = i & 127;
        smf[g*TSTR + d] = src[i];
    }
    __syncthreads();
    uint32_t* oh = (uint32_t*)(g_binT_h + (size_t)b * DD * GG + (size_t)gt * 128);
    uint32_t* ol = (uint32_t*)(g_binT_l + (size_t)b * DD * GG + (size_t)gt * 128);
    for (int i = tid; i < 128*64; i += 256) {
        int d = i >> 6, gp = i & 63;
        float v0 = smf[(2*gp)*TSTR + d], v1 = smf[(2*gp+1)*TSTR + d];
        uint32_t hp, lp;
        split2(v0, v1, hp, lp);
        size_t o = ((size_t)d * GG) / 2 + gp;
        oh[o] = hp; ol[o] = lp;
    }
}

// ---------------- K2: projections, M=64 tiles (2 CTAs/SM) ----------
// grid (192 token tiles, 4 proj, 8 b)
__global__ __launch_bounds__(256, 2) void k_proj_tc(const float* __restrict__ tu,
                                                    const float* __restrict__ tv,
                                                    const float* __restrict__ cu,
                                                    const float* __restrict__ cv) {
    extern __shared__ char sm[];
    uint32_t smb = smem_u32(sm);
    int tid = threadIdx.x, wid = tid >> 5, lane = tid & 31;
    int wm = wid & 1, wn = wid >> 1;
    int tile = blockIdx.x, pj = blockIdx.y, b = blockIdx.z;
    const float* w = (pj == 0) ? tu : (pj == 1) ? tv : (pj == 2) ? cu : cv;
    float* y = (pj == 0) ? g_qut : (pj == 1) ? g_qvt : (pj == 2) ? g_quc : g_qvc;
    size_t tokbase = (size_t)b * TPB + (size_t)tile * 64;
    {
        const uint32_t* sh = (const uint32_t*)(g_qzn_h + tokbase * DD);
        const uint32_t* sl = (const uint32_t*)(g_qzn_l + tokbase * DD);
        for (int i = tid; i < 64*64; i += 256) {
            int row = i >> 6, cp = i & 63;
            *(uint32_t*)(sm + O64_AH + row*RSB + 4*cp) = sh[row*64 + cp];
            *(uint32_t*)(sm + O64_AL + row*RSB + 4*cp) = sl[row*64 + cp];
        }
    }
    fill_hilo(w + (size_t)b * DD * DD, sm + O64_BH, sm + O64_BL, tid);
    __syncthreads();
    float acc[2][4][4];
#pragma unroll
    for (int mt = 0; mt < 2; mt++)
#pragma unroll
        for (int nt = 0; nt < 4; nt++)
#pragma unroll
            for (int j = 0; j < 4; j++) acc[mt][nt][j] = 0.f;
    mm64(smb + O64_AH, smb + O64_AL, smb + O64_BH, smb + O64_BL, lane, wm, wn, acc);
#pragma unroll
    for (int mt = 0; mt < 2; mt++)
#pragma unroll
        for (int h = 0; h < 2; h++) {
            int row = wm*32 + mt*16 + (lane >> 2) + 8*h;
            float* yr = y + (tokbase + row) * DD;
#pragma unroll
            for (int nt = 0; nt < 4; nt++) {
                int col = wn*32 + nt*8 + (lane & 3)*2;
                *(float2*)&yr[col] = make_float2(acc[mt][nt][2*h], acc[mt][nt][2*h+1]);
            }
        }
}

// ---------------- K3: topic scores, M=64 tiles ----------
// grid (192 token tiles, 4 g tiles, 8 b)
__global__ __launch_bounds__(256, 2) void k_topicS_tc(const float* __restrict__ bin) {
    extern __shared__ char sm[];
    uint32_t smb = smem_u32(sm);
    int tid = threadIdx.x, wid = tid >> 5, lane = tid & 31;
    int wm = wid & 1, wn = wid >> 1;
    int tile = blockIdx.x, gt = blockIdx.y, b = blockIdx.z;
    size_t tokbase = (size_t)b * TPB + (size_t)tile * 64;
    {
        const uint32_t* sh = (const uint32_t*)(g_qzn_h + tokbase * DD);
        const uint32_t* sl = (const uint32_t*)(g_qzn_l + tokbase * DD);
        for (int i = tid; i < 64*64; i += 256) {
            int row = i >> 6, cp = i & 63;
            *(uint32_t*)(sm + O64_AH + row*RSB + 4*cp) = sh[row*64 + cp];
            *(uint32_t*)(sm + O64_AL + row*RSB + 4*cp) = sl[row*64 + cp];
        }
    }
    fill_hilo(bin + ((size_t)b * GG + (size_t)gt * 128) * DD, sm + O64_BH, sm + O64_BL, tid);
    __syncthreads();
    float acc[2][4][4];
#pragma unroll
    for (int mt = 0; mt < 2; mt++)
#pragma unroll
        for (int nt = 0; nt < 4; nt++)
#pragma unroll
            for (int j = 0; j < 4; j++) acc[mt][nt][j] = 0.f;
    mm64(smb + O64_AH, smb + O64_AL, smb + O64_BH, smb + O64_BL, lane, wm, wn, acc);
#pragma unroll
    for (int mt = 0; mt < 2; mt++)
#pragma unroll
        for (int h = 0; h < 2; h++) {
            int row = wm*32 + mt*16 + (lane >> 2) + 8*h;
            uint32_t* shp = (uint32_t*)&g_Shi[(tokbase + row) * GG + gt*128];
            uint32_t* slp = (uint32_t*)&g_Slo[(tokbase + row) * GG + gt*128];
#pragma unroll
            for (int nt = 0; nt < 4; nt++) {
                int col = wn*32 + nt*8 + (lane & 3)*2;
                float f0 = fmaxf(acc[mt][nt][2*h], 0.f);
                float f1 = fmaxf(acc[mt][nt][2*h+1], 0.f);
                uint32_t hp, lp;
                split2(f0, f1, hp, lp);
                shp[col >> 1] = hp;
                slp[col >> 1] = lp;
            }
        }
}

// ---------------- K4: topic out + combine, M=64 tiles ----------
// grid (192 token tiles, 8 b); K=512 in 4 chunks
__global__ __launch_bounds__(256, 2) void k_topicO_tc(const float* __restrict__ un,
                                                      const float* __restrict__ old,
                                                      float* __restrict__ out) {
    extern __shared__ char sm[];
    uint32_t smb = smem_u32(sm);
    float* rs = (float*)(sm + SM_G64);
    int tid = threadIdx.x, wid = tid >> 5, lane = tid & 31;
    int wm = wid & 1, wn = wid >> 1;
    int tile = blockIdx.x, b = blockIdx.y;
    size_t btok = (size_t)b * TPB + (size_t)tile * 64;
    if (tid < 64) rs[tid] = 0.f;
    __syncthreads();
    float acc[2][4][4];
#pragma unroll
    for (int mt = 0; mt < 2; mt++)
#pragma unroll
        for (int nt = 0; nt < 4; nt++)
#pragma unroll
            for (int j = 0; j < 4; j++) acc[mt][nt][j] = 0.f;

    for (int gc = 0; gc < 4; gc++) {
        if (gc) __syncthreads();
        for (int i = tid; i < 64*64; i += 256) {
            int row = i >> 6, cp = i & 63;
            uint32_t hp = *(const uint32_t*)&g_Shi[(btok + row) * GG + gc*128 + 2*cp];
            uint32_t lp = *(const uint32_t*)&g_Slo[(btok + row) * GG + gc*128 + 2*cp];
            *(uint32_t*)(sm + O64_AH + row*RSB + 4*cp) = hp;
            *(uint32_t*)(sm + O64_AL + row*RSB + 4*cp) = lp;
            __nv_bfloat162 h2 = *reinterpret_cast<__nv_bfloat162*>(&hp);
            __nv_bfloat162 l2 = *reinterpret_cast<__nv_bfloat162*>(&lp);
            float2 fh = __bfloat1622float2(h2), fl = __bfloat1622float2(l2);
            float v = fh.x + fh.y + fl.x + fl.y;
#pragma unroll
            for (int o = 16; o; o >>= 1) v += __shfl_xor_sync(0xffffffffu, v, o);
            if (lane == 0) atomicAdd(&rs[row], v);
        }
        {
            const uint32_t* bh = (const uint32_t*)(g_binT_h + (size_t)b * DD * GG + gc*128);
            const uint32_t* bl = (const uint32_t*)(g_binT_l + (size_t)b * DD * GG + gc*128);
            for (int i = tid; i < 128*64; i += 256) {
                int d = i >> 6, gp = i & 63;
                size_t o = (size_t)d * (GG/2) + gp;
                *(uint32_t*)(sm + O64_BH + d*RSB + 4*gp) = bh[o];
                *(uint32_t*)(sm + O64_BL + d*RSB + 4*gp) = bl[o];
            }
        }
        __syncthreads();
        mm64(smb + O64_AH, smb + O64_AL, smb + O64_BH, smb + O64_BL, lane, wm, wn, acc);
    }
#pragma unroll
    for (int mt = 0; mt < 2; mt++)
#pragma unroll
        for (int h = 0; h < 2; h++) {
            int row = wm*32 + mt*16 + (lane >> 2) + 8*h;
            float inv = 1.0f / fmaxf(rs[row], 1e-6f);
            size_t rbase = (btok + row) * DD;
#pragma unroll
            for (int nt = 0; nt < 4; nt++) {
                int col = wn*32 + nt*8 + (lane & 3)*2;
                float2 m = *(const float2*)&g_msg[rbase + col];
                float2 u = *(const float2*)&un[rbase + col];
                float2 o = *(const float2*)&old[rbase + col];
                float2 r;
                r.x = 0.5f*(u.x + o.x + m.x + acc[mt][nt][2*h]   * inv);
                r.y = 0.5f*(u.y + o.y + m.y + acc[mt][nt][2*h+1] * inv);
                *(float2*)&out[rbase + col] = r;
            }
        }
}

// ---------------- K5: time attention (head-sum folded, poly exp) ------------
#define SM_TATTN ((3*96*PSTR + 96*ASTR)*4)
__global__ __launch_bounds__(256) void k_tattn() {
    extern __shared__ float smf[];
    float* Xs = smf;                 // 96 x PSTR
    float* Qu = Xs + 96*PSTR;
    float* Qv = Qu + 96*PSTR;
    float* As = Qv + 96*PSTR;        // 96 x ASTR : accumulated sum_h probs
    int tid = threadIdx.x, lane = tid & 31, wg = tid >> 5;
    size_t base = (size_t)blockIdx.x * PP * DD;
    for (int i = tid; i < PP*DD; i += 256) {
        int r = i >> 7, d = i & 127;
        Xs[r*PSTR+d] = g_qzn[base + i];
        Qu[r*PSTR+d] = g_qut[base + i];
        Qv[r*PSTR+d] = g_qvt[base + i];
    }
#pragma unroll
    for (int k = 0; k < 12; k++)
#pragma unroll
        for (int j = 0; j < 3; j++)
            As[(wg + 8*k)*ASTR + lane + 32*j] = 0.f;
    __syncthreads();

    for (int h = 0; h < HH; h++) {
        int ho = h * 16;
#pragma unroll 1
        for (int pr = 0; pr < 12; pr++) {
            int p = wg + 8*pr;
            u64 qu2[8];
#pragma unroll
            for (int r = 0; r < 8; r++) qu2[r] = *(const u64*)&Qu[p*PSTR + ho + 2*r];
            float lg[3];
#pragma unroll
            for (int qi = 0; qi < 3; qi++) {
                int q = lane + 32*qi;
                u64 s2 = 0ull;
#pragma unroll
                for (int r = 0; r < 8; r++) {
                    u64 qv2 = *(const u64*)&Qv[q*PSTR + ho + 2*r];
                    s2 = fma2(qu2[r], qv2, s2);
                }
                float2 sp = up2(s2);
                lg[qi] = (sp.x + sp.y) * 0.25f;
            }
            // logits are bounded (factor weights ~0.02) -> softmax without max-shift
            float e0 = fexp(lg[0]), e1 = fexp(lg[1]), e2 = fexp(lg[2]);
            float ssum = e0 + e1 + e2;
#pragma unroll
            for (int o = 16; o; o >>= 1) ssum += __shfl_xor_sync(0xffffffffu, ssum, o);
            float inv = 0.125f / ssum;            // fold 1/H
            As[p*ASTR + lane]      += e0 * inv;
            As[p*ASTR + lane + 32] += e1 * inv;
            As[p*ASTR + lane + 64] += e2 * inv;
        }
    }
    __syncthreads();

    u64 acc[12][2];
#pragma unroll
    for (int k = 0; k < 12; k++) { acc[k][0] = 0ull; acc[k][1] = 0ull; }
#pragma unroll 2
    for (int q = 0; q < PP; q++) {
        ulonglong2 xA = *(const ulonglong2*)&Xs[q*PSTR + 4*lane];
#pragma unroll
        for (int k = 0; k < 12; k++) {
            u64 ap = pk2(As[(wg + 8*k)*ASTR + q]);
            acc[k][0] = fma2(ap, xA.x, acc[k][0]);
            acc[k][1] = fma2(ap, xA.y, acc[k][1]);
        }
    }
#pragma unroll
    for (int k = 0; k < 12; k++) {
        int p = wg + 8*k;
        float2 p0 = up2(acc[k][0]), p1 = up2(acc[k][1]);
        *(float4*)&g_msg[base + (size_t)p*DD + 4*lane] = make_float4(p0.x, p0.y, p1.x, p1.y);
    }
}

// ---------------- K6: channel attention (poly exp) -> g_msg += ----------------
#define SM_CATTN (3*128*PSTR*4)
__global__ __launch_bounds__(256) void k_cattn() {
    extern __shared__ float smf[];
    float* Qu = smf;                 // 128 x PSTR
    float* Qv = Qu + 128*PSTR;
    float* Ac = Qv + 128*PSTR;
    int b = blockIdx.x / PP, p = blockIdx.x % PP;
    int tid = threadIdx.x, lane = tid & 31, wg = tid >> 5;
    for (int i = tid; i < CC*DD; i += 256) {
        int c = i >> 7, d = i & 127;
        size_t gi = (((size_t)b*CC + c)*PP + p)*DD + d;
        Qu[c*PSTR+d] = g_quc[gi];
        Qv[c*PSTR+d] = g_qvc[gi];
        Ac[c*PSTR+d] = 0.f;
    }
    __syncthreads();
    for (int h = 0; h < HH; h++) {
        int ho = h*16;
#pragma unroll 1
        for (int cr = 0; cr < 16; cr++) {
            int c = wg + 8*cr;
            u64 qu2[8];
#pragma unroll
            for (int r = 0; r < 8; r++) qu2[r] = *(const u64*)&Qu[c*PSTR + ho + 2*r];
            float lg[4];
#pragma unroll
            for (int j = 0; j < 4; j++) {
                int d = lane + 32*j;
                u64 s2 = 0ull;
#pragma unroll
                for (int r = 0; r < 8; r++) {
                    u64 qv2 = *(const u64*)&Qv[d*PSTR + ho + 2*r];
                    s2 = fma2(qu2[r], qv2, s2);
                }
                float2 sp = up2(s2);
                lg[j] = (sp.x + sp.y) * 0.25f;
            }
            float e[4], ssum = 0.f;
#pragma unroll
            for (int j = 0; j < 4; j++) { e[j] = fexp(lg[j]); ssum += e[j]; }
#pragma unroll
            for (int o = 16; o; o >>= 1) ssum += __shfl_xor_sync(0xffffffffu, ssum, o);
            float inv = 0.125f / ssum;            // fold 1/H
#pragma unroll
            for (int j = 0; j < 4; j++) Ac[c*PSTR + lane + 32*j] += e[j] * inv;
        }
    }
#pragma unroll
    for (int cr = 0; cr < 16; cr++) {
        int c = wg + 8*cr;
#pragma unroll
        for (int j = 0; j < 4; j++) {
            int d = lane + 32*j;
            size_t gi = (((size_t)b*CC + c)*PP + p)*DD + d;
            g_msg[gi] += Ac[c*PSTR+d] * g_qzn[gi];
        }
    }
}

// ---------------- K8: LN + MLP (tensor) + residual, in-place on d_out -------
__global__ __launch_bounds__(256) void k_mlp_tc(float* __restrict__ io,
                                                const float* __restrict__ gw,
                                                const float* __restrict__ gb,
                                                const float* __restrict__ w1,
                                                const float* __restrict__ b1,
                                                const float* __restrict__ w2,
                                                const float* __restrict__ b2) {
    extern __shared__ char sm[];
    uint32_t smb = smem_u32(sm);
    int tid = threadIdx.x, wid = tid >> 5, lane = tid & 31;
    int wm = wid & 3, wn = wid >> 2;
    size_t base = (size_t)blockIdx.x * 128 * DD;
    fill_hilo(w1, sm + OFF_W1H, sm + OFF_W1L, tid);
    fill_hilo(w2, sm + OFF_W2H, sm + OFF_W2L, tid);
#pragma unroll 1
    for (int it = 0; it < 16; it++) {
        int t = wid + 8*it;
        const float2* xr = (const float2*)(io + base + (size_t)t*DD);
        float2 v0 = xr[lane], v1 = xr[lane + 32];
        float s = v0.x + v0.y + v1.x + v1.y;
#pragma unroll
        for (int o = 16; o; o >>= 1) s += __shfl_xor_sync(0xffffffffu, s, o);
        float mu = s * (1.0f/128.0f);
        float q = (v0.x-mu)*(v0.x-mu) + (v0.y-mu)*(v0.y-mu)
                + (v1.x-mu)*(v1.x-mu) + (v1.y-mu)*(v1.y-mu);
#pragma unroll
        for (int o = 16; o; o >>= 1) q += __shfl_xor_sync(0xffffffffu, q, o);
        float inv = rsqrtf(q * (1.0f/128.0f) + 1e-5f);
#pragma unroll
        for (int j = 0; j < 2; j++) {
            float2 v = j ? v1 : v0;
            int dp = lane + 32*j;
            float y0 = (v.x-mu)*inv*gw[2*dp]   + gb[2*dp];
            float y1 = (v.y-mu)*inv*gw[2*dp+1] + gb[2*dp+1];
            uint32_t hp, lp;
            split2(y0, y1, hp, lp);
            *(uint32_t*)(sm + OFF_AH + t*RSB + 4*dp) = hp;
            *(uint32_t*)(sm + OFF_AL + t*RSB + 4*dp) = lp;
        }
    }
    __syncthreads();
    float acc[2][8][4];
#pragma unroll
    for (int mt = 0; mt < 2; mt++)
#pragma unroll
        for (int nt = 0; nt < 8; nt++)
#pragma unroll
            for (int j = 0; j < 4; j++) acc[mt][nt][j] = 0.f;
    mm128(smb + OFF_AH, smb + OFF_AL, smb + OFF_W1H, smb + OFF_W1L, lane, wm, wn, acc);
    __syncthreads();
#pragma unroll
    for (int mt = 0; mt < 2; mt++)
#pragma unroll
        for (int h = 0; h < 2; h++) {
            int row = wm*32 + mt*16 + (lane >> 2) + 8*h;
#pragma unroll
            for (int nt = 0; nt < 8; nt++) {
                int col = wn*64 + nt*8 + (lane & 3)*2;
                float2 bv = *(const float2*)&b1[col];
                float x0 = acc[mt][nt][2*h]   + bv.x;
                float x1 = acc[mt][nt][2*h+1] + bv.y;
                float g0 = 0.5f * x0 * (1.0f + erff(x0 * 0.70710678118654752f));
                float g1 = 0.5f * x1 * (1.0f + erff(x1 * 0.70710678118654752f));
                uint32_t hp, lp;
                split2(g0, g1, hp, lp);
                *(uint32_t*)(sm + OFF_AH + row*RSB + 2*col) = hp;
                *(uint32_t*)(sm + OFF_AL + row*RSB + 2*col) = lp;
            }
        }
    __syncthreads();
    float acc2[2][8][4];
#pragma unroll
    for (int mt = 0; mt < 2; mt++)
#pragma unroll
        for (int nt = 0; nt < 8; nt++)
#pragma unroll
            for (int j = 0; j < 4; j++) acc2[mt][nt][j] = 0.f;
    mm128(smb + OFF_AH, smb + OFF_AL, smb + OFF_W2H, smb + OFF_W2L, lane, wm, wn, acc2);
#pragma unroll
    for (int mt = 0; mt < 2; mt++)
#pragma unroll
        for (int h = 0; h < 2; h++) {
            int row = wm*32 + mt*16 + (lane >> 2) + 8*h;
            float* ir = io + base + (size_t)row*DD;
#pragma unroll
            for (int nt = 0; nt < 8; nt++) {
                int col = wn*64 + nt*8 + (lane & 3)*2;
                float2 bv = *(const float2*)&b2[col];
                float2 v = *(float2*)&ir[col];
                v.x += acc2[mt][nt][2*h]   + bv.x;
                v.y += acc2[mt][nt][2*h+1] + bv.y;
                *(float2*)&ir[col] = v;
            }
        }
}

// ---------------- host launcher ----------------
extern "C" void kernel_launch(void* const* d_in, const int* in_sizes, int n_in,
                              void* d_out, int out_size) {
    (void)in_sizes; (void)n_in; (void)out_size;
    const float* qz  = (const float*)d_in[0];
    const float* un  = (const float*)d_in[1];
    const float* tu  = (const float*)d_in[2];
    const float* tv  = (const float*)d_in[3];
    const float* cu  = (const float*)d_in[4];
    const float* cv  = (const float*)d_in[5];
    const float* bin = (const float*)d_in[6];
    const float* lng = (const float*)d_in[7];
    const float* lnb = (const float*)d_in[8];
    const float* w1  = (const float*)d_in[9];
    const float* b1  = (const float*)d_in[10];
    const float* w2  = (const float*)d_in[11];
    const float* b2  = (const float*)d_in[12];
    float* out = (float*)d_out;

    cudaFuncSetAttribute(k_binT,      cudaFuncAttributeMaxDynamicSharedMemorySize, 128*TSTR*4);
    cudaFuncSetAttribute(k_proj_tc,   cudaFuncAttributeMaxDynamicSharedMemorySize, SM_G64);
    cudaFuncSetAttribute(k_topicS_tc, cudaFuncAttributeMaxDynamicSharedMemorySize, SM_G64);
    cudaFuncSetAttribute(k_topicO_tc, cudaFuncAttributeMaxDynamicSharedMemorySize, SM_TOPICO64);
    cudaFuncSetAttribute(k_tattn,     cudaFuncAttributeMaxDynamicSharedMemorySize, SM_TATTN);
    cudaFuncSetAttribute(k_cattn,     cudaFuncAttributeMaxDynamicSharedMemorySize, SM_CATTN);
    cudaFuncSetAttribute(k_mlp_tc,    cudaFuncAttributeMaxDynamicSharedMemorySize, SM_MLP6);

    k_ln<<<(NTOK*32)/256, 256>>>(qz, lng, lnb);
    k_binT<<<dim3(4, BB), 256, 128*TSTR*4>>>(bin);

    dim3 pg(TPB/64, 4, BB);
    k_proj_tc<<<pg, 256, SM_G64>>>(tu, tv, cu, cv);

    dim3 sg(TPB/64, 4, BB);
    k_topicS_tc<<<sg, 256, SM_G64>>>(bin);

    k_tattn<<<BB*CC, 256, SM_TATTN>>>();
    k_cattn<<<BB*PP, 256, SM_CATTN>>>();

    dim3 og(TPB/64, BB);
    k_topicO_tc<<<og, 256, SM_TOPICO64>>>(un, qz, out);

    k_mlp_tc<<<NTOK/128, 256, SM_MLP6>>>(out, lng, lnb, w1, b1, w2, b2);
}

// round 10
// speedup vs baseline: 2.0831x; 1.2626x over previous
#include <cuda_runtime.h>
#include <cuda_bf16.h>
#include <math.h>
#include <stdint.h>

#define BB 8
#define CC 128
#define PP 96
#define DD 128
#define HH 8
#define GG 512
#define TPB (CC*PP)          // 12288 tokens per batch
#define NTOK (BB*TPB)        // 98304
#define NELEM (NTOK*DD)      // 12582912

#define PSTR 132
#define ASTR 98
#define RSB 272              // smem bf16 tile row stride in BYTES

typedef unsigned long long u64;

__device__ __forceinline__ u64 pk2(float x) {
    u64 r; asm("mov.b64 %0,{%1,%1};" : "=l"(r) : "f"(x)); return r;
}
__device__ __forceinline__ u64 fma2(u64 a, u64 b, u64 c) {
    asm("fma.rn.f32x2 %0,%1,%2,%0;" : "+l"(c) : "l"(a), "l"(b)); return c;
}
__device__ __forceinline__ float2 up2(u64 v) {
    float2 f; asm("mov.b64 {%0,%1},%2;" : "=f"(f.x), "=f"(f.y) : "l"(v)); return f;
}

// fast exp on fma/alu pipes only (no MUFU). valid for |x| < ~80.
__device__ __forceinline__ float fexp(float x) {
    float t = x * 1.4426950408889634f;
    float fi = floorf(t);
    float f = t - fi;
    float p = 0.0018775767f;
    p = p * f + 0.0089893397f;
    p = p * f + 0.0558186204f;
    p = p * f + 0.2402301537f;
    p = p * f + 0.6931469188f;
    p = p * f + 1.0f;
    int ei = (int)fi;
    return p * __int_as_float((ei + 127) << 23);
}

// ---------------- scratch (device globals: allocation-free) ----------------
__device__ __align__(16) float g_qzn[NELEM];
__device__ __align__(16) __nv_bfloat16 g_qzn_h[NELEM];
__device__ __align__(16) __nv_bfloat16 g_qzn_l[NELEM];
__device__ __align__(16) float g_qut[NELEM];
__device__ __align__(16) float g_qvt[NELEM];
__device__ __align__(16) float g_quc[NELEM];
__device__ __align__(16) float g_qvc[NELEM];
__device__ __align__(16) float g_msg[NELEM];
__device__ __align__(16) __nv_bfloat16 g_Shi[(size_t)NTOK * GG];
__device__ __align__(16) __nv_bfloat16 g_Slo[(size_t)NTOK * GG];
__device__ __align__(16) __nv_bfloat16 g_binN_h[(size_t)BB * GG * DD];
__device__ __align__(16) __nv_bfloat16 g_binN_l[(size_t)BB * GG * DD];
__device__ __align__(16) __nv_bfloat16 g_binT_h[(size_t)BB * DD * GG];
__device__ __align__(16) __nv_bfloat16 g_binT_l[(size_t)BB * DD * GG];
__device__ __align__(16) __nv_bfloat16 g_wp_h[(size_t)4 * BB * DD * DD];
__device__ __align__(16) __nv_bfloat16 g_wp_l[(size_t)4 * BB * DD * DD];
__device__ __align__(16) __nv_bfloat16 g_w1_h[DD*DD], g_w1_l[DD*DD];
__device__ __align__(16) __nv_bfloat16 g_w2_h[DD*DD], g_w2_l[DD*DD];
__device__ __align__(16) __nv_bfloat16 g_H_h[NELEM], g_H_l[NELEM];

// ================= mma.sync helpers =================
__device__ __forceinline__ uint32_t smem_u32(const void* p) {
    uint32_t a;
    asm("{ .reg .u64 t; cvta.to.shared.u64 t, %1; cvt.u32.u64 %0, t; }" : "=r"(a) : "l"(p));
    return a;
}

#define LDSM4(R, addr) \
    asm volatile("ldmatrix.sync.aligned.m8n8.x4.shared.b16 {%0,%1,%2,%3}, [%4];" \
        : "=r"((R)[0]), "=r"((R)[1]), "=r"((R)[2]), "=r"((R)[3]) : "r"(addr))

#define MMA16816(C, A, b0, b1) \
    asm volatile("mma.sync.aligned.m16n8k16.row.col.f32.bf16.bf16.f32 " \
        "{%0,%1,%2,%3},{%4,%5,%6,%7},{%8,%9},{%0,%1,%2,%3};" \
        : "+f"((C)[0]), "+f"((C)[1]), "+f"((C)[2]), "+f"((C)[3]) \
        : "r"((A)[0]), "r"((A)[1]), "r"((A)[2]), "r"((A)[3]), "r"(b0), "r"(b1))

__device__ __forceinline__ void split2(float x0, float x1, uint32_t& hp, uint32_t& lp) {
    __nv_bfloat16 h0 = __float2bfloat16(x0), h1 = __float2bfloat16(x1);
    __nv_bfloat16 l0 = __float2bfloat16(x0 - __bfloat162float(h0));
    __nv_bfloat16 l1 = __float2bfloat16(x1 - __bfloat162float(h1));
    hp = ((uint32_t)__bfloat16_as_ushort(h1) << 16) | __bfloat16_as_ushort(h0);
    lp = ((uint32_t)__bfloat16_as_ushort(l1) << 16) | __bfloat16_as_ushort(l0);
}

// copy pre-split hi/lo global rows (rowlen 128 bf16 = 16B x 16) into smem tiles
__device__ __forceinline__ void copy_rows(const uint32_t* gh, const uint32_t* gl,
                                          int rows, int stride_u32,
                                          char* smH, char* smL, int tid) {
    for (int i = tid; i < rows*16; i += 256) {
        int row = i >> 4, c = i & 15;
        *(uint4*)(smH + row*RSB + 16*c) = *(const uint4*)(gh + row*stride_u32 + 4*c);
        *(uint4*)(smL + row*RSB + 16*c) = *(const uint4*)(gl + row*stride_u32 + 4*c);
    }
}

// ---- M=64 split-precision mainloop, double-buffered LDSM ----
// warps: wm = wid&1 (32 M-rows), wn = wid>>1 (32 N-cols). acc[2][4][4].
__device__ __forceinline__ void mm64(uint32_t ah, uint32_t al,
                                     uint32_t bh, uint32_t bl,
                                     int lane, int wm, int wn,
                                     float acc[2][4][4]) {
    int r16 = lane & 15;
    uint32_t aoff = (uint32_t)(wm*32 + r16)*RSB + ((lane >> 4) << 4);
    uint32_t boff = (uint32_t)(wn*32 + r16)*RSB + ((lane >> 4) << 4);
    uint32_t Ah[2][2][4], Al[2][2][4], Bh[2][2][4], Bl[2][2][4];
    LDSM4(Ah[0][0], ah + aoff); LDSM4(Ah[0][1], ah + aoff + 16*RSB);
    LDSM4(Al[0][0], al + aoff); LDSM4(Al[0][1], al + aoff + 16*RSB);
    LDSM4(Bh[0][0], bh + boff); LDSM4(Bh[0][1], bh + boff + 16*RSB);
    LDSM4(Bl[0][0], bl + boff); LDSM4(Bl[0][1], bl + boff + 16*RSB);
#pragma unroll
    for (int ks = 0; ks < 8; ks++) {
        int cur = ks & 1, nxt = cur ^ 1;
        if (ks < 7) {
            uint32_t ko = (uint32_t)(ks + 1) * 32;
            LDSM4(Ah[nxt][0], ah + aoff + ko); LDSM4(Ah[nxt][1], ah + aoff + 16*RSB + ko);
            LDSM4(Al[nxt][0], al + aoff + ko); LDSM4(Al[nxt][1], al + aoff + 16*RSB + ko);
            LDSM4(Bh[nxt][0], bh + boff + ko); LDSM4(Bh[nxt][1], bh + boff + 16*RSB + ko);
            LDSM4(Bl[nxt][0], bl + boff + ko); LDSM4(Bl[nxt][1], bl + boff + 16*RSB + ko);
        }
#pragma unroll
        for (int mt = 0; mt < 2; mt++)
#pragma unroll
            for (int bt = 0; bt < 2; bt++) {
                MMA16816(acc[mt][2*bt],   Ah[cur][mt], Bh[cur][bt][0], Bh[cur][bt][2]);
                MMA16816(acc[mt][2*bt+1], Ah[cur][mt], Bh[cur][bt][1], Bh[cur][bt][3]);
                MMA16816(acc[mt][2*bt],   Ah[cur][mt], Bl[cur][bt][0], Bl[cur][bt][2]);
                MMA16816(acc[mt][2*bt+1], Ah[cur][mt], Bl[cur][bt][1], Bl[cur][bt][3]);
                MMA16816(acc[mt][2*bt],   Al[cur][mt], Bh[cur][bt][0], Bh[cur][bt][2]);
                MMA16816(acc[mt][2*bt+1], Al[cur][mt], Bh[cur][bt][1], Bh[cur][bt][3]);
            }
    }
}

#define A64 (64*RSB)         // 17408
#define TILE_B (128*RSB)     // 34816
#define O64_AH 0
#define O64_AL A64
#define O64_BH (2*A64)
#define O64_BL (2*A64 + TILE_B)
#define SM_G64 (2*A64 + 2*TILE_B)        // 104448 -> 2 CTAs/SM
#define SM_TOPICO64 (SM_G64 + 256)

// ---------------- K1: layernorm -> g_qzn fp32 + hi/lo bf16 ----------------
__global__ __launch_bounds__(256) void k_ln(const float* __restrict__ x,
                                            const float* __restrict__ gw,
                                            const float* __restrict__ gb) {
    int w = (blockIdx.x * 256 + threadIdx.x) >> 5;
    int lane = threadIdx.x & 31;
    if (w >= NTOK) return;
    const float2* xr = (const float2*)(x + (size_t)w * DD);
    float2 v0 = xr[lane], v1 = xr[lane + 32];
    float s = v0.x + v0.y + v1.x + v1.y;
#pragma unroll
    for (int o = 16; o; o >>= 1) s += __shfl_xor_sync(0xffffffffu, s, o);
    float mu = s * (1.0f/128.0f);
    float q = (v0.x-mu)*(v0.x-mu) + (v0.y-mu)*(v0.y-mu)
            + (v1.x-mu)*(v1.x-mu) + (v1.y-mu)*(v1.y-mu);
#pragma unroll
    for (int o = 16; o; o >>= 1) q += __shfl_xor_sync(0xffffffffu, q, o);
    float inv = rsqrtf(q * (1.0f/128.0f) + 1e-5f);
    float2* yr = (float2*)(g_qzn + (size_t)w * DD);
    uint32_t* yh = (uint32_t*)(g_qzn_h + (size_t)w * DD);
    uint32_t* yl = (uint32_t*)(g_qzn_l + (size_t)w * DD);
#pragma unroll
    for (int j = 0; j < 2; j++) {
        float2 v = j ? v1 : v0;
        int dp = lane + 32*j;
        float y0 = (v.x-mu)*inv*gw[2*dp]   + gb[2*dp];
        float y1 = (v.y-mu)*inv*gw[2*dp+1] + gb[2*dp+1];
        yr[dp] = make_float2(y0, y1);
        uint32_t hp, lp;
        split2(y0, y1, hp, lp);
        yh[dp] = hp; yl[dp] = lp;
    }
}

// ---------------- K1b: split all static GEMM operands (native layouts) -------
// ranges (in float2 units): binN 262144 | wp 4x65536 | w1 8192 | w2 8192
#define N2_BIN (BB*GG*DD/2)
#define N2_W   (BB*DD*DD/2)
#define N2_MW  (DD*DD/2)
#define N2_TOT (N2_BIN + 4*N2_W + 2*N2_MW)
__global__ __launch_bounds__(256) void k_split_all(const float* __restrict__ bin,
                                                   const float* __restrict__ tu,
                                                   const float* __restrict__ tv,
                                                   const float* __restrict__ cu,
                                                   const float* __restrict__ cv) {
    int i = blockIdx.x * 256 + threadIdx.x;
    if (i >= N2_TOT) return;
    const float* src; uint32_t *dh, *dl; int off;
    if (i < N2_BIN) {
        src = bin; dh = (uint32_t*)g_binN_h; dl = (uint32_t*)g_binN_l; off = i;
    } else if (i < N2_BIN + 4*N2_W) {
        int j = i - N2_BIN, pj = j / N2_W; off = j % N2_W;
        src = (pj == 0) ? tu : (pj == 1) ? tv : (pj == 2) ? cu : cv;
        dh = (uint32_t*)g_wp_h + (size_t)pj * N2_W;
        dl = (uint32_t*)g_wp_l + (size_t)pj * N2_W;
    } else {
        int j = i - N2_BIN - 4*N2_W;
        // w1/w2 handled by k_split_mw (separate pointers) — dead branch guard
        return;
    }
    float2 v = ((const float2*)src)[off];
    uint32_t hp, lp; split2(v.x, v.y, hp, lp);
    dh[off] = hp; dl[off] = lp;
}
__global__ __launch_bounds__(256) void k_split_mw(const float* __restrict__ w1,
                                                  const float* __restrict__ w2) {
    int i = blockIdx.x * 256 + threadIdx.x;
    if (i >= 2*N2_MW) return;
    const float* src = (i < N2_MW) ? w1 : w2;
    uint32_t* dh = (i < N2_MW) ? (uint32_t*)g_w1_h : (uint32_t*)g_w2_h;
    uint32_t* dl = (i < N2_MW) ? (uint32_t*)g_w1_l : (uint32_t*)g_w2_l;
    int off = (i < N2_MW) ? i : i - N2_MW;
    float2 v = ((const float2*)src)[off];
    uint32_t hp, lp; split2(v.x, v.y, hp, lp);
    dh[off] = hp; dl[off] = lp;
}

// ---------------- K1c: transpose+split topic_binary -> g_binT [b][d][g] ------
#define TSTR 129
__global__ __launch_bounds__(256) void k_binT(const float* __restrict__ bin) {
    extern __shared__ float smf[];
    int gt = blockIdx.x, b = blockIdx.y;
    int tid = threadIdx.x;
    const float* src = bin + ((size_t)b * GG + (size_t)gt * 128) * DD;
    for (int i = tid; i < 128*128; i += 256) {
        int g = i >> 7, d = i & 127;
        smf[g*TSTR + d] = src[i];
    }
    __syncthreads();
    uint32_t* oh = (uint32_t*)(g_binT_h + (size_t)b * DD * GG + (size_t)gt * 128);
    uint32_t* ol = (uint32_t*)(g_binT_l + (size_t)b * DD * GG + (size_t)gt * 128);
    for (int i = tid; i < 128*64; i += 256) {
        int d = i >> 6, gp = i & 63;
        float v0 = smf[(2*gp)*TSTR + d], v1 = smf[(2*gp+1)*TSTR + d];
        uint32_t hp, lp;
        split2(v0, v1, hp, lp);
        size_t o = ((size_t)d * GG) / 2 + gp;
        oh[o] = hp; ol[o] = lp;
    }
}

// ---------------- K2: merged proj+topicS GEMM, M=64 tiles, 2 CTAs/SM --------
// grid (192 token tiles, 8 outs [0-3 proj, 4-7 topicS gt], 8 b)
__global__ __launch_bounds__(256, 2) void k_gemm1() {
    extern __shared__ char sm[];
    uint32_t smb = smem_u32(sm);
    int tid = threadIdx.x, wid = tid >> 5, lane = tid & 31;
    int wm = wid & 1, wn = wid >> 1;
    int tile = blockIdx.x, pj = blockIdx.y, b = blockIdx.z;
    size_t tokbase = (size_t)b * TPB + (size_t)tile * 64;
    copy_rows((const uint32_t*)(g_qzn_h + tokbase * DD),
              (const uint32_t*)(g_qzn_l + tokbase * DD),
              64, 64, sm + O64_AH, sm + O64_AL, tid);
    const uint32_t *bh, *bl;
    if (pj < 4) {
        size_t o = ((size_t)pj * BB + b) * (DD*DD/2);
        bh = (const uint32_t*)g_wp_h + o;
        bl = (const uint32_t*)g_wp_l + o;
    } else {
        size_t o = ((size_t)b * GG + (size_t)(pj - 4) * 128) * (DD/2);
        bh = (const uint32_t*)g_binN_h + o;
        bl = (const uint32_t*)g_binN_l + o;
    }
    copy_rows(bh, bl, 128, 64, sm + O64_BH, sm + O64_BL, tid);
    __syncthreads();
    float acc[2][4][4];
#pragma unroll
    for (int mt = 0; mt < 2; mt++)
#pragma unroll
        for (int nt = 0; nt < 4; nt++)
#pragma unroll
            for (int j = 0; j < 4; j++) acc[mt][nt][j] = 0.f;
    mm64(smb + O64_AH, smb + O64_AL, smb + O64_BH, smb + O64_BL, lane, wm, wn, acc);
    if (pj < 4) {
        float* y = (pj == 0) ? g_qut : (pj == 1) ? g_qvt : (pj == 2) ? g_quc : g_qvc;
#pragma unroll
        for (int mt = 0; mt < 2; mt++)
#pragma unroll
            for (int h = 0; h < 2; h++) {
                int row = wm*32 + mt*16 + (lane >> 2) + 8*h;
                float* yr = y + (tokbase + row) * DD;
#pragma unroll
                for (int nt = 0; nt < 4; nt++) {
                    int col = wn*32 + nt*8 + (lane & 3)*2;
                    *(float2*)&yr[col] = make_float2(acc[mt][nt][2*h], acc[mt][nt][2*h+1]);
                }
            }
    } else {
        int gt = pj - 4;
#pragma unroll
        for (int mt = 0; mt < 2; mt++)
#pragma unroll
            for (int h = 0; h < 2; h++) {
                int row = wm*32 + mt*16 + (lane >> 2) + 8*h;
                uint32_t* shp = (uint32_t*)&g_Shi[(tokbase + row) * GG + gt*128];
                uint32_t* slp = (uint32_t*)&g_Slo[(tokbase + row) * GG + gt*128];
#pragma unroll
                for (int nt = 0; nt < 4; nt++) {
                    int col = wn*32 + nt*8 + (lane & 3)*2;
                    float f0 = fmaxf(acc[mt][nt][2*h], 0.f);
                    float f1 = fmaxf(acc[mt][nt][2*h+1], 0.f);
                    uint32_t hp, lp;
                    split2(f0, f1, hp, lp);
                    shp[col >> 1] = hp;
                    slp[col >> 1] = lp;
                }
            }
    }
}

// ---------------- K4: topic out + combine, M=64 tiles ----------
__global__ __launch_bounds__(256, 2) void k_topicO_tc(const float* __restrict__ un,
                                                      const float* __restrict__ old,
                                                      float* __restrict__ out) {
    extern __shared__ char sm[];
    uint32_t smb = smem_u32(sm);
    float* rs = (float*)(sm + SM_G64);
    int tid = threadIdx.x, wid = tid >> 5, lane = tid & 31;
    int wm = wid & 1, wn = wid >> 1;
    int tile = blockIdx.x, b = blockIdx.y;
    size_t btok = (size_t)b * TPB + (size_t)tile * 64;
    if (tid < 64) rs[tid] = 0.f;
    __syncthreads();
    float acc[2][4][4];
#pragma unroll
    for (int mt = 0; mt < 2; mt++)
#pragma unroll
        for (int nt = 0; nt < 4; nt++)
#pragma unroll
            for (int j = 0; j < 4; j++) acc[mt][nt][j] = 0.f;

    for (int gc = 0; gc < 4; gc++) {
        if (gc) __syncthreads();
        // A: S chunk copy + rowsum (16 lanes per row -> reduce over 16)
        {
            const uint32_t* sh = (const uint32_t*)g_Shi + btok * (GG/2) + gc*64;
            const uint32_t* sl = (const uint32_t*)g_Slo + btok * (GG/2) + gc*64;
            for (int i = tid; i < 64*16; i += 256) {
                int row = i >> 4, c = i & 15;
                uint4 hp4 = *(const uint4*)(sh + row*(GG/2) + 4*c);
                uint4 lp4 = *(const uint4*)(sl + row*(GG/2) + 4*c);
                *(uint4*)(sm + O64_AH + row*RSB + 16*c) = hp4;
                *(uint4*)(sm + O64_AL + row*RSB + 16*c) = lp4;
                float v = 0.f;
                const uint32_t* hs = (const uint32_t*)&hp4;
                const uint32_t* ls = (const uint32_t*)&lp4;
#pragma unroll
                for (int q = 0; q < 4; q++) {
                    float2 fh = __bfloat1622float2(*(const __nv_bfloat162*)&hs[q]);
                    float2 fl = __bfloat1622float2(*(const __nv_bfloat162*)&ls[q]);
                    v += fh.x + fh.y + fl.x + fl.y;
                }
#pragma unroll
                for (int o = 8; o; o >>= 1) v += __shfl_xor_sync(0xffffffffu, v, o);
                if ((lane & 15) == 0) atomicAdd(&rs[row], v);
            }
        }
        copy_rows((const uint32_t*)g_binT_h + (size_t)b * (DD*GG/2) + gc*64,
                  (const uint32_t*)g_binT_l + (size_t)b * (DD*GG/2) + gc*64,
                  128, GG/2, sm + O64_BH, sm + O64_BL, tid);
        __syncthreads();
        mm64(smb + O64_AH, smb + O64_AL, smb + O64_BH, smb + O64_BL, lane, wm, wn, acc);
    }
#pragma unroll
    for (int mt = 0; mt < 2; mt++)
#pragma unroll
        for (int h = 0; h < 2; h++) {
            int row = wm*32 + mt*16 + (lane >> 2) + 8*h;
            float inv = 1.0f / fmaxf(rs[row], 1e-6f);
            size_t rbase = (btok + row) * DD;
#pragma unroll
            for (int nt = 0; nt < 4; nt++) {
                int col = wn*32 + nt*8 + (lane & 3)*2;
                float2 m = *(const float2*)&g_msg[rbase + col];
                float2 u = *(const float2*)&un[rbase + col];
                float2 o = *(const float2*)&old[rbase + col];
                float2 r;
                r.x = 0.5f*(u.x + o.x + m.x + acc[mt][nt][2*h]   * inv);
                r.y = 0.5f*(u.y + o.y + m.y + acc[mt][nt][2*h+1] * inv);
                *(float2*)&out[rbase + col] = r;
            }
        }
}

// ---------------- K5: time attention (head-sum folded, poly exp) ------------
#define SM_TATTN ((3*96*PSTR + 96*ASTR)*4)
__global__ __launch_bounds__(256) void k_tattn() {
    extern __shared__ float smf[];
    float* Xs = smf;
    float* Qu = Xs + 96*PSTR;
    float* Qv = Qu + 96*PSTR;
    float* As = Qv + 96*PSTR;
    int tid = threadIdx.x, lane = tid & 31, wg = tid >> 5;
    size_t base = (size_t)blockIdx.x * PP * DD;
    for (int i = tid; i < PP*DD; i += 256) {
        int r = i >> 7, d = i & 127;
        Xs[r*PSTR+d] = g_qzn[base + i];
        Qu[r*PSTR+d] = g_qut[base + i];
        Qv[r*PSTR+d] = g_qvt[base + i];
    }
#pragma unroll
    for (int k = 0; k < 12; k++)
#pragma unroll
        for (int j = 0; j < 3; j++)
            As[(wg + 8*k)*ASTR + lane + 32*j] = 0.f;
    __syncthreads();

    for (int h = 0; h < HH; h++) {
        int ho = h * 16;
#pragma unroll 1
        for (int pr = 0; pr < 12; pr++) {
            int p = wg + 8*pr;
            u64 qu2[8];
#pragma unroll
            for (int r = 0; r < 8; r++) qu2[r] = *(const u64*)&Qu[p*PSTR + ho + 2*r];
            float lg[3];
#pragma unroll
            for (int qi = 0; qi < 3; qi++) {
                int q = lane + 32*qi;
                u64 s2 = 0ull;
#pragma unroll
                for (int r = 0; r < 8; r++) {
                    u64 qv2 = *(const u64*)&Qv[q*PSTR + ho + 2*r];
                    s2 = fma2(qu2[r], qv2, s2);
                }
                float2 sp = up2(s2);
                lg[qi] = (sp.x + sp.y) * 0.25f;
            }
            float e0 = fexp(lg[0]), e1 = fexp(lg[1]), e2 = fexp(lg[2]);
            float ssum = e0 + e1 + e2;
#pragma unroll
            for (int o = 16; o; o >>= 1) ssum += __shfl_xor_sync(0xffffffffu, ssum, o);
            float inv = 0.125f / ssum;
            As[p*ASTR + lane]      += e0 * inv;
            As[p*ASTR + lane + 32] += e1 * inv;
            As[p*ASTR + lane + 64] += e2 * inv;
        }
    }
    __syncthreads();

    u64 acc[12][2];
#pragma unroll
    for (int k = 0; k < 12; k++) { acc[k][0] = 0ull; acc[k][1] = 0ull; }
#pragma unroll 2
    for (int q = 0; q < PP; q++) {
        ulonglong2 xA = *(const ulonglong2*)&Xs[q*PSTR + 4*lane];
#pragma unroll
        for (int k = 0; k < 12; k++) {
            u64 ap = pk2(As[(wg + 8*k)*ASTR + q]);
            acc[k][0] = fma2(ap, xA.x, acc[k][0]);
            acc[k][1] = fma2(ap, xA.y, acc[k][1]);
        }
    }
#pragma unroll
    for (int k = 0; k < 12; k++) {
        int p = wg + 8*k;
        float2 p0 = up2(acc[k][0]), p1 = up2(acc[k][1]);
        *(float4*)&g_msg[base + (size_t)p*DD + 4*lane] = make_float4(p0.x, p0.y, p1.x, p1.y);
    }
}

// ---------------- K6: channel attention (poly exp) -> g_msg += ----------------
#define SM_CATTN (3*128*PSTR*4)
__global__ __launch_bounds__(256) void k_cattn() {
    extern __shared__ float smf[];
    float* Qu = smf;
    float* Qv = Qu + 128*PSTR;
    float* Ac = Qv + 128*PSTR;
    int b = blockIdx.x / PP, p = blockIdx.x % PP;
    int tid = threadIdx.x, lane = tid & 31, wg = tid >> 5;
    for (int i = tid; i < CC*DD; i += 256) {
        int c = i >> 7, d = i & 127;
        size_t gi = (((size_t)b*CC + c)*PP + p)*DD + d;
        Qu[c*PSTR+d] = g_quc[gi];
        Qv[c*PSTR+d] = g_qvc[gi];
        Ac[c*PSTR+d] = 0.f;
    }
    __syncthreads();
    for (int h = 0; h < HH; h++) {
        int ho = h*16;
#pragma unroll 1
        for (int cr = 0; cr < 16; cr++) {
            int c = wg + 8*cr;
            u64 qu2[8];
#pragma unroll
            for (int r = 0; r < 8; r++) qu2[r] = *(const u64*)&Qu[c*PSTR + ho + 2*r];
            float lg[4];
#pragma unroll
            for (int j = 0; j < 4; j++) {
                int d = lane + 32*j;
                u64 s2 = 0ull;
#pragma unroll
                for (int r = 0; r < 8; r++) {
                    u64 qv2 = *(const u64*)&Qv[d*PSTR + ho + 2*r];
                    s2 = fma2(qu2[r], qv2, s2);
                }
                float2 sp = up2(s2);
                lg[j] = (sp.x + sp.y) * 0.25f;
            }
            float e[4], ssum = 0.f;
#pragma unroll
            for (int j = 0; j < 4; j++) { e[j] = fexp(lg[j]); ssum += e[j]; }
#pragma unroll
            for (int o = 16; o; o >>= 1) ssum += __shfl_xor_sync(0xffffffffu, ssum, o);
            float inv = 0.125f / ssum;
#pragma unroll
            for (int j = 0; j < 4; j++) Ac[c*PSTR + lane + 32*j] += e[j] * inv;
        }
    }
#pragma unroll
    for (int cr = 0; cr < 16; cr++) {
        int c = wg + 8*cr;
#pragma unroll
        for (int j = 0; j < 4; j++) {
            int d = lane + 32*j;
            size_t gi = (((size_t)b*CC + c)*PP + p)*DD + d;
            g_msg[gi] += Ac[c*PSTR+d] * g_qzn[gi];
        }
    }
}

// ---------------- K7: MLP part1: LN + GEMM1 + gelu -> g_H hi/lo -------------
__global__ __launch_bounds__(256, 2) void k_mlp1(const float* __restrict__ io,
                                                 const float* __restrict__ gw,
                                                 const float* __restrict__ gb,
                                                 const float* __restrict__ b1) {
    extern __shared__ char sm[];
    uint32_t smb = smem_u32(sm);
    int tid = threadIdx.x, wid = tid >> 5, lane = tid & 31;
    int wm = wid & 1, wn = wid >> 1;
    size_t tokbase = (size_t)blockIdx.x * 64;
    copy_rows((const uint32_t*)g_w1_h, (const uint32_t*)g_w1_l,
              128, 64, sm + O64_BH, sm + O64_BL, tid);
    // LN: 8 warps x 8 tokens
#pragma unroll 1
    for (int it = 0; it < 8; it++) {
        int t = wid + 8*it;
        const float2* xr = (const float2*)(io + (tokbase + t) * DD);
        float2 v0 = xr[lane], v1 = xr[lane + 32];
        float s = v0.x + v0.y + v1.x + v1.y;
#pragma unroll
        for (int o = 16; o; o >>= 1) s += __shfl_xor_sync(0xffffffffu, s, o);
        float mu = s * (1.0f/128.0f);
        float q = (v0.x-mu)*(v0.x-mu) + (v0.y-mu)*(v0.y-mu)
                + (v1.x-mu)*(v1.x-mu) + (v1.y-mu)*(v1.y-mu);
#pragma unroll
        for (int o = 16; o; o >>= 1) q += __shfl_xor_sync(0xffffffffu, q, o);
        float inv = rsqrtf(q * (1.0f/128.0f) + 1e-5f);
#pragma unroll
        for (int j = 0; j < 2; j++) {
            float2 v = j ? v1 : v0;
            int dp = lane + 32*j;
            float y0 = (v.x-mu)*inv*gw[2*dp]   + gb[2*dp];
            float y1 = (v.y-mu)*inv*gw[2*dp+1] + gb[2*dp+1];
            uint32_t hp, lp;
            split2(y0, y1, hp, lp);
            *(uint32_t*)(sm + O64_AH + t*RSB + 4*dp) = hp;
            *(uint32_t*)(sm + O64_AL + t*RSB + 4*dp) = lp;
        }
    }
    __syncthreads();
    float acc[2][4][4];
#pragma unroll
    for (int mt = 0; mt < 2; mt++)
#pragma unroll
        for (int nt = 0; nt < 4; nt++)
#pragma unroll
            for (int j = 0; j < 4; j++) acc[mt][nt][j] = 0.f;
    mm64(smb + O64_AH, smb + O64_AL, smb + O64_BH, smb + O64_BL, lane, wm, wn, acc);
#pragma unroll
    for (int mt = 0; mt < 2; mt++)
#pragma unroll
        for (int h = 0; h < 2; h++) {
            int row = wm*32 + mt*16 + (lane >> 2) + 8*h;
            uint32_t* hh = (uint32_t*)g_H_h + (tokbase + row) * (DD/2);
            uint32_t* hl = (uint32_t*)g_H_l + (tokbase + row) * (DD/2);
#pragma unroll
            for (int nt = 0; nt < 4; nt++) {
                int col = wn*32 + nt*8 + (lane & 3)*2;
                float2 bv = *(const float2*)&b1[col];
                float x0 = acc[mt][nt][2*h]   + bv.x;
                float x1 = acc[mt][nt][2*h+1] + bv.y;
                float g0 = 0.5f * x0 * (1.0f + erff(x0 * 0.70710678118654752f));
                float g1 = 0.5f * x1 * (1.0f + erff(x1 * 0.70710678118654752f));
                uint32_t hp, lp;
                split2(g0, g1, hp, lp);
                hh[col >> 1] = hp;
                hl[col >> 1] = lp;
            }
        }
}

// ---------------- K8: MLP part2: GEMM2 + bias + residual -> io --------------
__global__ __launch_bounds__(256, 2) void k_mlp2(float* __restrict__ io,
                                                 const float* __restrict__ b2) {
    extern __shared__ char sm[];
    uint32_t smb = smem_u32(sm);
    int tid = threadIdx.x, wid = tid >> 5, lane = tid & 31;
    int wm = wid & 1, wn = wid >> 1;
    size_t tokbase = (size_t)blockIdx.x * 64;
    copy_rows((const uint32_t*)g_H_h + tokbase * (DD/2),
              (const uint32_t*)g_H_l + tokbase * (DD/2),
              64, 64, sm + O64_AH, sm + O64_AL, tid);
    copy_rows((const uint32_t*)g_w2_h, (const uint32_t*)g_w2_l,
              128, 64, sm + O64_BH, sm + O64_BL, tid);
    __syncthreads();
    float acc[2][4][4];
#pragma unroll
    for (int mt = 0; mt < 2; mt++)
#pragma unroll
        for (int nt = 0; nt < 4; nt++)
#pragma unroll
            for (int j = 0; j < 4; j++) acc[mt][nt][j] = 0.f;
    mm64(smb + O64_AH, smb + O64_AL, smb + O64_BH, smb + O64_BL, lane, wm, wn, acc);
#pragma unroll
    for (int mt = 0; mt < 2; mt++)
#pragma unroll
        for (int h = 0; h < 2; h++) {
            int row = wm*32 + mt*16 + (lane >> 2) + 8*h;
            float* ir = io + (tokbase + row) * DD;
#pragma unroll
            for (int nt = 0; nt < 4; nt++) {
                int col = wn*32 + nt*8 + (lane & 3)*2;
                float2 bv = *(const float2*)&b2[col];
                float2 v = *(float2*)&ir[col];
                v.x += acc[mt][nt][2*h]   + bv.x;
                v.y += acc[mt][nt][2*h+1] + bv.y;
                *(float2*)&ir[col] = v;
            }
        }
}

// ---------------- host launcher ----------------
extern "C" void kernel_launch(void* const* d_in, const int* in_sizes, int n_in,
                              void* d_out, int out_size) {
    (void)in_sizes; (void)n_in; (void)out_size;
    const float* qz  = (const float*)d_in[0];
    const float* un  = (const float*)d_in[1];
    const float* tu  = (const float*)d_in[2];
    const float* tv  = (const float*)d_in[3];
    const float* cu  = (const float*)d_in[4];
    const float* cv  = (const float*)d_in[5];
    const float* bin = (const float*)d_in[6];
    const float* lng = (const float*)d_in[7];
    const float* lnb = (const float*)d_in[8];
    const float* w1  = (const float*)d_in[9];
    const float* b1  = (const float*)d_in[10];
    const float* w2  = (const float*)d_in[11];
    const float* b2  = (const float*)d_in[12];
    float* out = (float*)d_out;

    cudaFuncSetAttribute(k_binT,      cudaFuncAttributeMaxDynamicSharedMemorySize, 128*TSTR*4);
    cudaFuncSetAttribute(k_gemm1,     cudaFuncAttributeMaxDynamicSharedMemorySize, SM_G64);
    cudaFuncSetAttribute(k_topicO_tc, cudaFuncAttributeMaxDynamicSharedMemorySize, SM_TOPICO64);
    cudaFuncSetAttribute(k_tattn,     cudaFuncAttributeMaxDynamicSharedMemorySize, SM_TATTN);
    cudaFuncSetAttribute(k_cattn,     cudaFuncAttributeMaxDynamicSharedMemorySize, SM_CATTN);
    cudaFuncSetAttribute(k_mlp1,      cudaFuncAttributeMaxDynamicSharedMemorySize, SM_G64);
    cudaFuncSetAttribute(k_mlp2,      cudaFuncAttributeMaxDynamicSharedMemorySize, SM_G64);

    k_ln<<<(NTOK*32)/256, 256>>>(qz, lng, lnb);
    k_split_all<<<(N2_TOT + 255)/256, 256>>>(bin, tu, tv, cu, cv);
    k_split_mw<<<(2*N2_MW + 255)/256, 256>>>(w1, w2);
    k_binT<<<dim3(4, BB), 256, 128*TSTR*4>>>(bin);

    dim3 g1(TPB/64, 8, BB);
    k_gemm1<<<g1, 256, SM_G64>>>();

    k_tattn<<<BB*CC, 256, SM_TATTN>>>();
    k_cattn<<<BB*PP, 256, SM_CATTN>>>();

    dim3 og(TPB/64, BB);
    k_topicO_tc<<<og, 256, SM_TOPICO64>>>(un, qz, out);

    k_mlp1<<<NTOK/64, 256, SM_G64>>>(out, lng, lnb, b1);
    k_mlp2<<<NTOK/64, 256, SM_G64>>>(out, b2);
}

// round 13
// speedup vs baseline: 2.2912x; 1.0999x over previous
#include <cuda_runtime.h>
#include <cuda_bf16.h>
#include <math.h>
#include <stdint.h>

#define BB 8
#define CC 128
#define PP 96
#define DD 128
#define HH 8
#define GG 512
#define TPB (CC*PP)          // 12288 tokens per batch
#define NTOK (BB*TPB)        // 98304
#define NELEM (NTOK*DD)      // 12582912

#define PSTR 132
#define ASTR 98
#define RSB 272              // smem bf16 tile row stride in BYTES

typedef unsigned long long u64;

__device__ __forceinline__ u64 pk2(float x) {
    u64 r; asm("mov.b64 %0,{%1,%1};" : "=l"(r) : "f"(x)); return r;
}
__device__ __forceinline__ u64 fma2(u64 a, u64 b, u64 c) {
    asm("fma.rn.f32x2 %0,%1,%2,%0;" : "+l"(c) : "l"(a), "l"(b)); return c;
}
__device__ __forceinline__ float2 up2(u64 v) {
    float2 f; asm("mov.b64 {%0,%1},%2;" : "=f"(f.x), "=f"(f.y) : "l"(v)); return f;
}

// fast exp on fma/alu pipes only (no MUFU). valid for |x| < ~80.
__device__ __forceinline__ float fexp(float x) {
    float t = x * 1.4426950408889634f;
    float fi = floorf(t);
    float f = t - fi;
    float p = 0.0018775767f;
    p = p * f + 0.0089893397f;
    p = p * f + 0.0558186204f;
    p = p * f + 0.2402301537f;
    p = p * f + 0.6931469188f;
    p = p * f + 1.0f;
    int ei = (int)fi;
    return p * __int_as_float((ei + 127) << 23);
}

// ---------------- scratch (device globals: allocation-free) ----------------
__device__ __align__(16) float g_qzn[NELEM];
__device__ __align__(16) __nv_bfloat16 g_qzn_h[NELEM];
__device__ __align__(16) __nv_bfloat16 g_qzn_l[NELEM];
__device__ __align__(16) float g_qut[NELEM];
__device__ __align__(16) float g_qvt[NELEM];
__device__ __align__(16) float g_quc[NELEM];
__device__ __align__(16) float g_qvc[NELEM];
__device__ __align__(16) float g_msg[NELEM];
__device__ __align__(16) __nv_bfloat16 g_Shi[(size_t)NTOK * GG];
__device__ __align__(16) __nv_bfloat16 g_Slo[(size_t)NTOK * GG];
__device__ __align__(16) __nv_bfloat16 g_binN_h[(size_t)BB * GG * DD];
__device__ __align__(16) __nv_bfloat16 g_binT_h[(size_t)BB * DD * GG];
__device__ __align__(16) __nv_bfloat16 g_wp_h[(size_t)4 * BB * DD * DD];
__device__ __align__(16) __nv_bfloat16 g_w1_h[DD*DD], g_w1_l[DD*DD];
__device__ __align__(16) __nv_bfloat16 g_w2_h[DD*DD], g_w2_l[DD*DD];
__device__ __align__(16) __nv_bfloat16 g_H_h[NELEM], g_H_l[NELEM];

// ================= mma.sync helpers =================
__device__ __forceinline__ uint32_t smem_u32(const void* p) {
    uint32_t a;
    asm("{ .reg .u64 t; cvta.to.shared.u64 t, %1; cvt.u32.u64 %0, t; }" : "=r"(a) : "l"(p));
    return a;
}

#define LDSM4(R, addr) \
    asm volatile("ldmatrix.sync.aligned.m8n8.x4.shared.b16 {%0,%1,%2,%3}, [%4];" \
        : "=r"((R)[0]), "=r"((R)[1]), "=r"((R)[2]), "=r"((R)[3]) : "r"(addr))

#define MMA16816(C, A, b0, b1) \
    asm volatile("mma.sync.aligned.m16n8k16.row.col.f32.bf16.bf16.f32 " \
        "{%0,%1,%2,%3},{%4,%5,%6,%7},{%8,%9},{%0,%1,%2,%3};" \
        : "+f"((C)[0]), "+f"((C)[1]), "+f"((C)[2]), "+f"((C)[3]) \
        : "r"((A)[0]), "r"((A)[1]), "r"((A)[2]), "r"((A)[3]), "r"(b0), "r"(b1))

__device__ __forceinline__ void split2(float x0, float x1, uint32_t& hp, uint32_t& lp) {
    __nv_bfloat16 h0 = __float2bfloat16(x0), h1 = __float2bfloat16(x1);
    __nv_bfloat16 l0 = __float2bfloat16(x0 - __bfloat162float(h0));
    __nv_bfloat16 l1 = __float2bfloat16(x1 - __bfloat162float(h1));
    hp = ((uint32_t)__bfloat16_as_ushort(h1) << 16) | __bfloat16_as_ushort(h0);
    lp = ((uint32_t)__bfloat16_as_ushort(l1) << 16) | __bfloat16_as_ushort(l0);
}
__device__ __forceinline__ uint32_t hi2(float x0, float x1) {
    __nv_bfloat16 h0 = __float2bfloat16(x0), h1 = __float2bfloat16(x1);
    return ((uint32_t)__bfloat16_as_ushort(h1) << 16) | __bfloat16_as_ushort(h0);
}

// copy pre-split hi/lo global rows into smem tiles
__device__ __forceinline__ void copy_rows(const uint32_t* gh, const uint32_t* gl,
                                          int rows, int stride_u32,
                                          char* smH, char* smL, int tid) {
    for (int i = tid; i < rows*16; i += 256) {
        int row = i >> 4, c = i & 15;
        *(uint4*)(smH + row*RSB + 16*c) = *(const uint4*)(gh + row*stride_u32 + 4*c);
        *(uint4*)(smL + row*RSB + 16*c) = *(const uint4*)(gl + row*stride_u32 + 4*c);
    }
}
// hi-only copy
__device__ __forceinline__ void copy_rows1(const uint32_t* gh,
                                           int rows, int stride_u32,
                                           char* smH, int tid) {
    for (int i = tid; i < rows*16; i += 256) {
        int row = i >> 4, c = i & 15;
        *(uint4*)(smH + row*RSB + 16*c) = *(const uint4*)(gh + row*stride_u32 + 4*c);
    }
}

// ---- M=64 3-product mainloop (MLP), double-buffered LDSM ----
__device__ __forceinline__ void mm64(uint32_t ah, uint32_t al,
                                     uint32_t bh, uint32_t bl,
                                     int lane, int wm, int wn,
                                     float acc[2][4][4]) {
    int r16 = lane & 15;
    uint32_t aoff = (uint32_t)(wm*32 + r16)*RSB + ((lane >> 4) << 4);
    uint32_t boff = (uint32_t)(wn*32 + r16)*RSB + ((lane >> 4) << 4);
    uint32_t Ah[2][2][4], Al[2][2][4], Bh[2][2][4], Bl[2][2][4];
    LDSM4(Ah[0][0], ah + aoff); LDSM4(Ah[0][1], ah + aoff + 16*RSB);
    LDSM4(Al[0][0], al + aoff); LDSM4(Al[0][1], al + aoff + 16*RSB);
    LDSM4(Bh[0][0], bh + boff); LDSM4(Bh[0][1], bh + boff + 16*RSB);
    LDSM4(Bl[0][0], bl + boff); LDSM4(Bl[0][1], bl + boff + 16*RSB);
#pragma unroll
    for (int ks = 0; ks < 8; ks++) {
        int cur = ks & 1, nxt = cur ^ 1;
        if (ks < 7) {
            uint32_t ko = (uint32_t)(ks + 1) * 32;
            LDSM4(Ah[nxt][0], ah + aoff + ko); LDSM4(Ah[nxt][1], ah + aoff + 16*RSB + ko);
            LDSM4(Al[nxt][0], al + aoff + ko); LDSM4(Al[nxt][1], al + aoff + 16*RSB + ko);
            LDSM4(Bh[nxt][0], bh + boff + ko); LDSM4(Bh[nxt][1], bh + boff + 16*RSB + ko);
            LDSM4(Bl[nxt][0], bl + boff + ko); LDSM4(Bl[nxt][1], bl + boff + 16*RSB + ko);
        }
#pragma unroll
        for (int mt = 0; mt < 2; mt++)
#pragma unroll
            for (int bt = 0; bt < 2; bt++) {
                MMA16816(acc[mt][2*bt],   Ah[cur][mt], Bh[cur][bt][0], Bh[cur][bt][2]);
                MMA16816(acc[mt][2*bt+1], Ah[cur][mt], Bh[cur][bt][1], Bh[cur][bt][3]);
                MMA16816(acc[mt][2*bt],   Ah[cur][mt], Bl[cur][bt][0], Bl[cur][bt][2]);
                MMA16816(acc[mt][2*bt+1], Ah[cur][mt], Bl[cur][bt][1], Bl[cur][bt][3]);
                MMA16816(acc[mt][2*bt],   Al[cur][mt], Bh[cur][bt][0], Bh[cur][bt][2]);
                MMA16816(acc[mt][2*bt+1], Al[cur][mt], Bh[cur][bt][1], Bh[cur][bt][3]);
            }
    }
}

// ---- M=64 2-product mainloop (B hi only): C = (Ah+Al)·Bh ----
__device__ __forceinline__ void mm64_2p(uint32_t ah, uint32_t al, uint32_t bh,
                                        int lane, int wm, int wn,
                                        float acc[2][4][4]) {
    int r16 = lane & 15;
    uint32_t aoff = (uint32_t)(wm*32 + r16)*RSB + ((lane >> 4) << 4);
    uint32_t boff = (uint32_t)(wn*32 + r16)*RSB + ((lane >> 4) << 4);
    uint32_t Ah[2][2][4], Al[2][2][4], Bh[2][2][4];
    LDSM4(Ah[0][0], ah + aoff); LDSM4(Ah[0][1], ah + aoff + 16*RSB);
    LDSM4(Al[0][0], al + aoff); LDSM4(Al[0][1], al + aoff + 16*RSB);
    LDSM4(Bh[0][0], bh + boff); LDSM4(Bh[0][1], bh + boff + 16*RSB);
#pragma unroll
    for (int ks = 0; ks < 8; ks++) {
        int cur = ks & 1, nxt = cur ^ 1;
        if (ks < 7) {
            uint32_t ko = (uint32_t)(ks + 1) * 32;
            LDSM4(Ah[nxt][0], ah + aoff + ko); LDSM4(Ah[nxt][1], ah + aoff + 16*RSB + ko);
            LDSM4(Al[nxt][0], al + aoff + ko); LDSM4(Al[nxt][1], al + aoff + 16*RSB + ko);
            LDSM4(Bh[nxt][0], bh + boff + ko); LDSM4(Bh[nxt][1], bh + boff + 16*RSB + ko);
        }
#pragma unroll
        for (int mt = 0; mt < 2; mt++)
#pragma unroll
            for (int bt = 0; bt < 2; bt++) {
                MMA16816(acc[mt][2*bt],   Ah[cur][mt], Bh[cur][bt][0], Bh[cur][bt][2]);
                MMA16816(acc[mt][2*bt+1], Ah[cur][mt], Bh[cur][bt][1], Bh[cur][bt][3]);
                MMA16816(acc[mt][2*bt],   Al[cur][mt], Bh[cur][bt][0], Bh[cur][bt][2]);
                MMA16816(acc[mt][2*bt+1], Al[cur][mt], Bh[cur][bt][1], Bh[cur][bt][3]);
            }
    }
}

#define A64 (64*RSB)         // 17408
#define TILE_B (128*RSB)     // 34816
// 3-product layout (MLP)
#define O64_AH 0
#define O64_AL A64
#define O64_BH (2*A64)
#define O64_BL (2*A64 + TILE_B)
#define SM_G64 (2*A64 + 2*TILE_B)        // 104448 -> 2 CTAs/SM
// 2-product layout (gemm1/topicO): A hi/lo + B hi
#define SM_G2 (2*A64 + TILE_B)           // 69632 -> 3 CTAs/SM
#define SM_TOPICO2 (SM_G2 + 256)

// ---------------- K1: layernorm -> g_qzn fp32 + hi/lo bf16 ----------------
__global__ __launch_bounds__(256) void k_ln(const float* __restrict__ x,
                                            const float* __restrict__ gw,
                                            const float* __restrict__ gb) {
    int w = (blockIdx.x * 256 + threadIdx.x) >> 5;
    int lane = threadIdx.x & 31;
    if (w >= NTOK) return;
    const float2* xr = (const float2*)(x + (size_t)w * DD);
    float2 v0 = xr[lane], v1 = xr[lane + 32];
    float s = v0.x + v0.y + v1.x + v1.y;
#pragma unroll
    for (int o = 16; o; o >>= 1) s += __shfl_xor_sync(0xffffffffu, s, o);
    float mu = s * (1.0f/128.0f);
    float q = (v0.x-mu)*(v0.x-mu) + (v0.y-mu)*(v0.y-mu)
            + (v1.x-mu)*(v1.x-mu) + (v1.y-mu)*(v1.y-mu);
#pragma unroll
    for (int o = 16; o; o >>= 1) q += __shfl_xor_sync(0xffffffffu, q, o);
    float inv = rsqrtf(q * (1.0f/128.0f) + 1e-5f);
    float2* yr = (float2*)(g_qzn + (size_t)w * DD);
    uint32_t* yh = (uint32_t*)(g_qzn_h + (size_t)w * DD);
    uint32_t* yl = (uint32_t*)(g_qzn_l + (size_t)w * DD);
#pragma unroll
    for (int j = 0; j < 2; j++) {
        float2 v = j ? v1 : v0;
        int dp = lane + 32*j;
        float y0 = (v.x-mu)*inv*gw[2*dp]   + gb[2*dp];
        float y1 = (v.y-mu)*inv*gw[2*dp+1] + gb[2*dp+1];
        yr[dp] = make_float2(y0, y1);
        uint32_t hp, lp;
        split2(y0, y1, hp, lp);
        yh[dp] = hp; yl[dp] = lp;
    }
}

// ---------------- K1b: split/convert static GEMM operands -------------------
#define N2_BIN (BB*GG*DD/2)
#define N2_W   (BB*DD*DD/2)
#define N2_MW  (DD*DD/2)
#define N2_TOT (N2_BIN + 4*N2_W)
__global__ __launch_bounds__(256) void k_split_all(const float* __restrict__ bin,
                                                   const float* __restrict__ tu,
                                                   const float* __restrict__ tv,
                                                   const float* __restrict__ cu,
                                                   const float* __restrict__ cv) {
    int i = blockIdx.x * 256 + threadIdx.x;
    if (i >= N2_TOT) return;
    const float* src; uint32_t* dh; int off;
    if (i < N2_BIN) {
        src = bin; dh = (uint32_t*)g_binN_h; off = i;
    } else {
        int j = i - N2_BIN, pj = j / N2_W; off = j % N2_W;
        src = (pj == 0) ? tu : (pj == 1) ? tv : (pj == 2) ? cu : cv;
        dh = (uint32_t*)g_wp_h + (size_t)pj * N2_W;
    }
    float2 v = ((const float2*)src)[off];
    dh[off] = hi2(v.x, v.y);
}
__global__ __launch_bounds__(256) void k_split_mw(const float* __restrict__ w1,
                                                  const float* __restrict__ w2) {
    int i = blockIdx.x * 256 + threadIdx.x;
    if (i >= 2*N2_MW) return;
    const float* src = (i < N2_MW) ? w1 : w2;
    uint32_t* dh = (i < N2_MW) ? (uint32_t*)g_w1_h : (uint32_t*)g_w2_h;
    uint32_t* dl = (i < N2_MW) ? (uint32_t*)g_w1_l : (uint32_t*)g_w2_l;
    int off = (i < N2_MW) ? i : i - N2_MW;
    float2 v = ((const float2*)src)[off];
    uint32_t hp, lp; split2(v.x, v.y, hp, lp);
    dh[off] = hp; dl[off] = lp;
}

// ---------------- K1c: transpose topic_binary -> g_binT_h [b][d][g] ---------
#define TSTR 129
__global__ __launch_bounds__(256) void k_binT(const float* __restrict__ bin) {
    extern __shared__ float smf[];
    int gt = blockIdx.x, b = blockIdx.y;
    int tid = threadIdx.x;
    const float* src = bin + ((size_t)b * GG + (size_t)gt * 128) * DD;
    for (int i = tid; i < 128*128; i += 256) {
        int g = i >> 7, d = i & 127;
        smf[g*TSTR + d] = src[i];
    }
    __syncthreads();
    uint32_t* oh = (uint32_t*)(g_binT_h + (size_t)b * DD * GG + (size_t)gt * 128);
    for (int i = tid; i < 128*64; i += 256) {
        int d = i >> 6, gp = i & 63;
        float v0 = smf[(2*gp)*TSTR + d], v1 = smf[(2*gp+1)*TSTR + d];
        size_t o = ((size_t)d * GG) / 2 + gp;
        oh[o] = hi2(v0, v1);
    }
}

// ---------------- K2: merged proj+topicS GEMM (2-product), 3 CTAs/SM --------
// grid (192 token tiles, 8 outs [0-3 proj, 4-7 topicS gt], 8 b)
__global__ __launch_bounds__(256, 3) void k_gemm1() {
    extern __shared__ char sm[];
    uint32_t smb = smem_u32(sm);
    int tid = threadIdx.x, wid = tid >> 5, lane = tid & 31;
    int wm = wid & 1, wn = wid >> 1;
    int tile = blockIdx.x, pj = blockIdx.y, b = blockIdx.z;
    size_t tokbase = (size_t)b * TPB + (size_t)tile * 64;
    copy_rows((const uint32_t*)(g_qzn_h + tokbase * DD),
              (const uint32_t*)(g_qzn_l + tokbase * DD),
              64, 64, sm + O64_AH, sm + O64_AL, tid);
    const uint32_t* bh;
    if (pj < 4) {
        bh = (const uint32_t*)g_wp_h + ((size_t)pj * BB + b) * (DD*DD/2);
    } else {
        bh = (const uint32_t*)g_binN_h + ((size_t)b * GG + (size_t)(pj - 4) * 128) * (DD/2);
    }
    copy_rows1(bh, 128, 64, sm + O64_BH, tid);
    __syncthreads();
    float acc[2][4][4];
#pragma unroll
    for (int mt = 0; mt < 2; mt++)
#pragma unroll
        for (int nt = 0; nt < 4; nt++)
#pragma unroll
            for (int j = 0; j < 4; j++) acc[mt][nt][j] = 0.f;
    mm64_2p(smb + O64_AH, smb + O64_AL, smb + O64_BH, lane, wm, wn, acc);
    if (pj < 4) {
        float* y = (pj == 0) ? g_qut : (pj == 1) ? g_qvt : (pj == 2) ? g_quc : g_qvc;
#pragma unroll
        for (int mt = 0; mt < 2; mt++)
#pragma unroll
            for (int h = 0; h < 2; h++) {
                int row = wm*32 + mt*16 + (lane >> 2) + 8*h;
                float* yr = y + (tokbase + row) * DD;
#pragma unroll
                for (int nt = 0; nt < 4; nt++) {
                    int col = wn*32 + nt*8 + (lane & 3)*2;
                    *(float2*)&yr[col] = make_float2(acc[mt][nt][2*h], acc[mt][nt][2*h+1]);
                }
            }
    } else {
        int gt = pj - 4;
#pragma unroll
        for (int mt = 0; mt < 2; mt++)
#pragma unroll
            for (int h = 0; h < 2; h++) {
                int row = wm*32 + mt*16 + (lane >> 2) + 8*h;
                uint32_t* shp = (uint32_t*)&g_Shi[(tokbase + row) * GG + gt*128];
                uint32_t* slp = (uint32_t*)&g_Slo[(tokbase + row) * GG + gt*128];
#pragma unroll
                for (int nt = 0; nt < 4; nt++) {
                    int col = wn*32 + nt*8 + (lane & 3)*2;
                    float f0 = fmaxf(acc[mt][nt][2*h], 0.f);
                    float f1 = fmaxf(acc[mt][nt][2*h+1], 0.f);
                    uint32_t hp, lp;
                    split2(f0, f1, hp, lp);
                    shp[col >> 1] = hp;
                    slp[col >> 1] = lp;
                }
            }
    }
}

// ---------------- K4: topic out + combine (2-product), 3 CTAs/SM ------------
__global__ __launch_bounds__(256, 3) void k_topicO_tc(const float* __restrict__ un,
                                                      const float* __restrict__ old,
                                                      float* __restrict__ out) {
    extern __shared__ char sm[];
    uint32_t smb = smem_u32(sm);
    float* rs = (float*)(sm + SM_G2);
    int tid = threadIdx.x, wid = tid >> 5, lane = tid & 31;
    int wm = wid & 1, wn = wid >> 1;
    int tile = blockIdx.x, b = blockIdx.y;
    size_t btok = (size_t)b * TPB + (size_t)tile * 64;
    if (tid < 64) rs[tid] = 0.f;
    __syncthreads();
    float acc[2][4][4];
#pragma unroll
    for (int mt = 0; mt < 2; mt++)
#pragma unroll
        for (int nt = 0; nt < 4; nt++)
#pragma unroll
            for (int j = 0; j < 4; j++) acc[mt][nt][j] = 0.f;

    for (int gc = 0; gc < 4; gc++) {
        if (gc) __syncthreads();
        // A: S chunk copy + rowsum
        {
            const uint32_t* sh = (const uint32_t*)g_Shi + btok * (GG/2) + gc*64;
            const uint32_t* sl = (const uint32_t*)g_Slo + btok * (GG/2) + gc*64;
            for (int i = tid; i < 64*16; i += 256) {
                int row = i >> 4, c = i & 15;
                uint4 hp4 = *(const uint4*)(sh + row*(GG/2) + 4*c);
                uint4 lp4 = *(const uint4*)(sl + row*(GG/2) + 4*c);
                *(uint4*)(sm + O64_AH + row*RSB + 16*c) = hp4;
                *(uint4*)(sm + O64_AL + row*RSB + 16*c) = lp4;
                float v = 0.f;
                const uint32_t* hs = (const uint32_t*)&hp4;
                const uint32_t* ls = (const uint32_t*)&lp4;
#pragma unroll
                for (int q = 0; q < 4; q++) {
                    float2 fh = __bfloat1622float2(*(const __nv_bfloat162*)&hs[q]);
                    float2 fl = __bfloat1622float2(*(const __nv_bfloat162*)&ls[q]);
                    v += fh.x + fh.y + fl.x + fl.y;
                }
#pragma unroll
                for (int o = 8; o; o >>= 1) v += __shfl_xor_sync(0xffffffffu, v, o);
                if ((lane & 15) == 0) atomicAdd(&rs[row], v);
            }
        }
        copy_rows1((const uint32_t*)g_binT_h + (size_t)b * (DD*GG/2) + gc*64,
                   128, GG/2, sm + O64_BH, tid);
        __syncthreads();
        mm64_2p(smb + O64_AH, smb + O64_AL, smb + O64_BH, lane, wm, wn, acc);
    }
#pragma unroll
    for (int mt = 0; mt < 2; mt++)
#pragma unroll
        for (int h = 0; h < 2; h++) {
            int row = wm*32 + mt*16 + (lane >> 2) + 8*h;
            float inv = 1.0f / fmaxf(rs[row], 1e-6f);
            size_t rbase = (btok + row) * DD;
#pragma unroll
            for (int nt = 0; nt < 4; nt++) {
                int col = wn*32 + nt*8 + (lane & 3)*2;
                float2 m = *(const float2*)&g_msg[rbase + col];
                float2 u = *(const float2*)&un[rbase + col];
                float2 o = *(const float2*)&old[rbase + col];
                float2 r;
                r.x = 0.5f*(u.x + o.x + m.x + acc[mt][nt][2*h]   * inv);
                r.y = 0.5f*(u.y + o.y + m.y + acc[mt][nt][2*h+1] * inv);
                *(float2*)&out[rbase + col] = r;
            }
        }
}

// ---------------- K5: time attention (head-sum folded, poly exp) ------------
#define SM_TATTN ((3*96*PSTR + 96*ASTR)*4)
__global__ __launch_bounds__(256) void k_tattn() {
    extern __shared__ float smf[];
    float* Xs = smf;
    float* Qu = Xs + 96*PSTR;
    float* Qv = Qu + 96*PSTR;
    float* As = Qv + 96*PSTR;
    int tid = threadIdx.x, lane = tid & 31, wg = tid >> 5;
    size_t base = (size_t)blockIdx.x * PP * DD;
    for (int i = tid; i < PP*DD; i += 256) {
        int r = i >> 7, d = i & 127;
        Xs[r*PSTR+d] = g_qzn[base + i];
        Qu[r*PSTR+d] = g_qut[base + i];
        Qv[r*PSTR+d] = g_qvt[base + i];
    }
#pragma unroll
    for (int k = 0; k < 12; k++)
#pragma unroll
        for (int j = 0; j < 3; j++)
            As[(wg + 8*k)*ASTR + lane + 32*j] = 0.f;
    __syncthreads();

    for (int h = 0; h < HH; h++) {
        int ho = h * 16;
#pragma unroll 1
        for (int pr = 0; pr < 12; pr++) {
            int p = wg + 8*pr;
            u64 qu2[8];
#pragma unroll
            for (int r = 0; r < 8; r++) qu2[r] = *(const u64*)&Qu[p*PSTR + ho + 2*r];
            float lg[3];
#pragma unroll
            for (int qi = 0; qi < 3; qi++) {
                int q = lane + 32*qi;
                u64 s2 = 0ull;
#pragma unroll
                for (int r = 0; r < 8; r++) {
                    u64 qv2 = *(const u64*)&Qv[q*PSTR + ho + 2*r];
                    s2 = fma2(qu2[r], qv2, s2);
                }
                float2 sp = up2(s2);
                lg[qi] = (sp.x + sp.y) * 0.25f;
            }
            float e0 = fexp(lg[0]), e1 = fexp(lg[1]), e2 = fexp(lg[2]);
            float ssum = e0 + e1 + e2;
#pragma unroll
            for (int o = 16; o; o >>= 1) ssum += __shfl_xor_sync(0xffffffffu, ssum, o);
            float inv = 0.125f / ssum;
            As[p*ASTR + lane]      += e0 * inv;
            As[p*ASTR + lane + 32] += e1 * inv;
            As[p*ASTR + lane + 64] += e2 * inv;
        }
    }
    __syncthreads();

    u64 acc[12][2];
#pragma unroll
    for (int k = 0; k < 12; k++) { acc[k][0] = 0ull; acc[k][1] = 0ull; }
#pragma unroll 2
    for (int q = 0; q < PP; q++) {
        ulonglong2 xA = *(const ulonglong2*)&Xs[q*PSTR + 4*lane];
#pragma unroll
        for (int k = 0; k < 12; k++) {
            u64 ap = pk2(As[(wg + 8*k)*ASTR + q]);
            acc[k][0] = fma2(ap, xA.x, acc[k][0]);
            acc[k][1] = fma2(ap, xA.y, acc[k][1]);
        }
    }
#pragma unroll
    for (int k = 0; k < 12; k++) {
        int p = wg + 8*k;
        float2 p0 = up2(acc[k][0]), p1 = up2(acc[k][1]);
        *(float4*)&g_msg[base + (size_t)p*DD + 4*lane] = make_float4(p0.x, p0.y, p1.x, p1.y);
    }
}

// ---------------- K6: channel attention (poly exp) -> g_msg += ----------------
#define SM_CATTN (3*128*PSTR*4)
__global__ __launch_bounds__(256) void k_cattn() {
    extern __shared__ float smf[];
    float* Qu = smf;
    float* Qv = Qu + 128*PSTR;
    float* Ac = Qv + 128*PSTR;
    int b = blockIdx.x / PP, p = blockIdx.x % PP;
    int tid = threadIdx.x, lane = tid & 31, wg = tid >> 5;
    for (int i = tid; i < CC*DD; i += 256) {
        int c = i >> 7, d = i & 127;
        size_t gi = (((size_t)b*CC + c)*PP + p)*DD + d;
        Qu[c*PSTR+d] = g_quc[gi];
        Qv[c*PSTR+d] = g_qvc[gi];
        Ac[c*PSTR+d] = 0.f;
    }
    __syncthreads();
    for (int h = 0; h < HH; h++) {
        int ho = h*16;
#pragma unroll 1
        for (int cr = 0; cr < 16; cr++) {
            int c = wg + 8*cr;
            u64 qu2[8];
#pragma unroll
            for (int r = 0; r < 8; r++) qu2[r] = *(const u64*)&Qu[c*PSTR + ho + 2*r];
            float lg[4];
#pragma unroll
            for (int j = 0; j < 4; j++) {
                int d = lane + 32*j;
                u64 s2 = 0ull;
#pragma unroll
                for (int r = 0; r < 8; r++) {
                    u64 qv2 = *(const u64*)&Qv[d*PSTR + ho + 2*r];
                    s2 = fma2(qu2[r], qv2, s2);
                }
                float2 sp = up2(s2);
                lg[j] = (sp.x + sp.y) * 0.25f;
            }
            float e[4], ssum = 0.f;
#pragma unroll
            for (int j = 0; j < 4; j++) { e[j] = fexp(lg[j]); ssum += e[j]; }
#pragma unroll
            for (int o = 16; o; o >>= 1) ssum += __shfl_xor_sync(0xffffffffu, ssum, o);
            float inv = 0.125f / ssum;
#pragma unroll
            for (int j = 0; j < 4; j++) Ac[c*PSTR + lane + 32*j] += e[j] * inv;
        }
    }
#pragma unroll
    for (int cr = 0; cr < 16; cr++) {
        int c = wg + 8*cr;
#pragma unroll
        for (int j = 0; j < 4; j++) {
            int d = lane + 32*j;
            size_t gi = (((size_t)b*CC + c)*PP + p)*DD + d;
            g_msg[gi] += Ac[c*PSTR+d] * g_qzn[gi];
        }
    }
}

// ---------------- K7: MLP part1: LN + GEMM1 + gelu -> g_H hi/lo -------------
__global__ __launch_bounds__(256, 2) void k_mlp1(const float* __restrict__ io,
                                                 const float* __restrict__ gw,
                                                 const float* __restrict__ gb,
                                                 const float* __restrict__ b1) {
    extern __shared__ char sm[];
    uint32_t smb = smem_u32(sm);
    int tid = threadIdx.x, wid = tid >> 5, lane = tid & 31;
    int wm = wid & 1, wn = wid >> 1;
    size_t tokbase = (size_t)blockIdx.x * 64;
    copy_rows((const uint32_t*)g_w1_h, (const uint32_t*)g_w1_l,
              128, 64, sm + O64_BH, sm + O64_BL, tid);
#pragma unroll 1
    for (int it = 0; it < 8; it++) {
        int t = wid + 8*it;
        const float2* xr = (const float2*)(io + (tokbase + t) * DD);
        float2 v0 = xr[lane], v1 = xr[lane + 32];
        float s = v0.x + v0.y + v1.x + v1.y;
#pragma unroll
        for (int o = 16; o; o >>= 1) s += __shfl_xor_sync(0xffffffffu, s, o);
        float mu = s * (1.0f/128.0f);
        float q = (v0.x-mu)*(v0.x-mu) + (v0.y-mu)*(v0.y-mu)
                + (v1.x-mu)*(v1.x-mu) + (v1.y-mu)*(v1.y-mu);
#pragma unroll
        for (int o = 16; o; o >>= 1) q += __shfl_xor_sync(0xffffffffu, q, o);
        float inv = rsqrtf(q * (1.0f/128.0f) + 1e-5f);
#pragma unroll
        for (int j = 0; j < 2; j++) {
            float2 v = j ? v1 : v0;
            int dp = lane + 32*j;
            float y0 = (v.x-mu)*inv*gw[2*dp]   + gb[2*dp];
            float y1 = (v.y-mu)*inv*gw[2*dp+1] + gb[2*dp+1];
            uint32_t hp, lp;
            split2(y0, y1, hp, lp);
            *(uint32_t*)(sm + O64_AH + t*RSB + 4*dp) = hp;
            *(uint32_t*)(sm + O64_AL + t*RSB + 4*dp) = lp;
        }
    }
    __syncthreads();
    float acc[2][4][4];
#pragma unroll
    for (int mt = 0; mt < 2; mt++)
#pragma unroll
        for (int nt = 0; nt < 4; nt++)
#pragma unroll
            for (int j = 0; j < 4; j++) acc[mt][nt][j] = 0.f;
    mm64(smb + O64_AH, smb + O64_AL, smb + O64_BH, smb + O64_BL, lane, wm, wn, acc);
#pragma unroll
    for (int mt = 0; mt < 2; mt++)
#pragma unroll
        for (int h = 0; h < 2; h++) {
            int row = wm*32 + mt*16 + (lane >> 2) + 8*h;
            uint32_t* hh = (uint32_t*)g_H_h + (tokbase + row) * (DD/2);
            uint32_t* hl = (uint32_t*)g_H_l + (tokbase + row) * (DD/2);
#pragma unroll
            for (int nt = 0; nt < 4; nt++) {
                int col = wn*32 + nt*8 + (lane & 3)*2;
                float2 bv = *(const float2*)&b1[col];
                float x0 = acc[mt][nt][2*h]   + bv.x;
                float x1 = acc[mt][nt][2*h+1] + bv.y;
                float g0 = 0.5f * x0 * (1.0f + erff(x0 * 0.70710678118654752f));
                float g1 = 0.5f * x1 * (1.0f + erff(x1 * 0.70710678118654752f));
                uint32_t hp, lp;
                split2(g0, g1, hp, lp);
                hh[col >> 1] = hp;
                hl[col >> 1] = lp;
            }
        }
}

// ---------------- K8: MLP part2: GEMM2 + bias + residual -> io --------------
__global__ __launch_bounds__(256, 2) void k_mlp2(float* __restrict__ io,
                                                 const float* __restrict__ b2) {
    extern __shared__ char sm[];
    uint32_t smb = smem_u32(sm);
    int tid = threadIdx.x, wid = tid >> 5, lane = tid & 31;
    int wm = wid & 1, wn = wid >> 1;
    size_t tokbase = (size_t)blockIdx.x * 64;
    copy_rows((const uint32_t*)g_H_h + tokbase * (DD/2),
              (const uint32_t*)g_H_l + tokbase * (DD/2),
              64, 64, sm + O64_AH, sm + O64_AL, tid);
    copy_rows((const uint32_t*)g_w2_h, (const uint32_t*)g_w2_l,
              128, 64, sm + O64_BH, sm + O64_BL, tid);
    __syncthreads();
    float acc[2][4][4];
#pragma unroll
    for (int mt = 0; mt < 2; mt++)
#pragma unroll
        for (int nt = 0; nt < 4; nt++)
#pragma unroll
            for (int j = 0; j < 4; j++) acc[mt][nt][j] = 0.f;
    mm64(smb + O64_AH, smb + O64_AL, smb + O64_BH, smb + O64_BL, lane, wm, wn, acc);
#pragma unroll
    for (int mt = 0; mt < 2; mt++)
#pragma unroll
        for (int h = 0; h < 2; h++) {
            int row = wm*32 + mt*16 + (lane >> 2) + 8*h;
            float* ir = io + (tokbase + row) * DD;
#pragma unroll
            for (int nt = 0; nt < 4; nt++) {
                int col = wn*32 + nt*8 + (lane & 3)*2;
                float2 bv = *(const float2*)&b2[col];
                float2 v = *(float2*)&ir[col];
                v.x += acc[mt][nt][2*h]   + bv.x;
                v.y += acc[mt][nt][2*h+1] + bv.y;
                *(float2*)&ir[col] = v;
            }
        }
}

// ---------------- host launcher ----------------
extern "C" void kernel_launch(void* const* d_in, const int* in_sizes, int n_in,
                              void* d_out, int out_size) {
    (void)in_sizes; (void)n_in; (void)out_size;
    const float* qz  = (const float*)d_in[0];
    const float* un  = (const float*)d_in[1];
    const float* tu  = (const float*)d_in[2];
    const float* tv  = (const float*)d_in[3];
    const float* cu  = (const float*)d_in[4];
    const float* cv  = (const float*)d_in[5];
    const float* bin = (const float*)d_in[6];
    const float* lng = (const float*)d_in[7];
    const float* lnb = (const float*)d_in[8];
    const float* w1  = (const float*)d_in[9];
    const float* b1  = (const float*)d_in[10];
    const float* w2  = (const float*)d_in[11];
    const float* b2  = (const float*)d_in[12];
    float* out = (float*)d_out;

    cudaFuncSetAttribute(k_binT,      cudaFuncAttributeMaxDynamicSharedMemorySize, 128*TSTR*4);
    cudaFuncSetAttribute(k_gemm1,     cudaFuncAttributeMaxDynamicSharedMemorySize, SM_G2);
    cudaFuncSetAttribute(k_topicO_tc, cudaFuncAttributeMaxDynamicSharedMemorySize, SM_TOPICO2);
    cudaFuncSetAttribute(k_tattn,     cudaFuncAttributeMaxDynamicSharedMemorySize, SM_TATTN);
    cudaFuncSetAttribute(k_cattn,     cudaFuncAttributeMaxDynamicSharedMemorySize, SM_CATTN);
    cudaFuncSetAttribute(k_mlp1,      cudaFuncAttributeMaxDynamicSharedMemorySize, SM_G64);
    cudaFuncSetAttribute(k_mlp2,      cudaFuncAttributeMaxDynamicSharedMemorySize, SM_G64);

    k_ln<<<(NTOK*32)/256, 256>>>(qz, lng, lnb);
    k_split_all<<<(N2_TOT + 255)/256, 256>>>(bin, tu, tv, cu, cv);
    k_split_mw<<<(2*N2_MW + 255)/256, 256>>>(w1, w2);
    k_binT<<<dim3(4, BB), 256, 128*TSTR*4>>>(bin);

    dim3 g1(TPB/64, 8, BB);
    k_gemm1<<<g1, 256, SM_G2>>>();

    k_tattn<<<BB*CC, 256, SM_TATTN>>>();
    k_cattn<<<BB*PP, 256, SM_CATTN>>>();

    dim3 og(TPB/64, BB);
    k_topicO_tc<<<og, 256, SM_TOPICO2>>>(un, qz, out);

    k_mlp1<<<NTOK/64, 256, SM_G64>>>(out, lng, lnb, b1);
    k_mlp2<<<NTOK/64, 256, SM_G64>>>(out, b2);
}

// round 15
// speedup vs baseline: 2.4543x; 1.0712x over previous
#include <cuda_runtime.h>
#include <cuda_bf16.h>
#include <math.h>
#include <stdint.h>

#define BB 8
#define CC 128
#define PP 96
#define DD 128
#define HH 8
#define GG 512
#define TPB (CC*PP)          // 12288 tokens per batch
#define NTOK (BB*TPB)        // 98304
#define NELEM (NTOK*DD)      // 12582912

#define PSTR 132
#define ASTR 98
#define RSB 272              // smem bf16 tile row stride in BYTES

typedef unsigned long long u64;

__device__ __forceinline__ u64 pk2(float x) {
    u64 r; asm("mov.b64 %0,{%1,%1};" : "=l"(r) : "f"(x)); return r;
}
__device__ __forceinline__ u64 fma2(u64 a, u64 b, u64 c) {
    asm("fma.rn.f32x2 %0,%1,%2,%0;" : "+l"(c) : "l"(a), "l"(b)); return c;
}
__device__ __forceinline__ float2 up2(u64 v) {
    float2 f; asm("mov.b64 {%0,%1},%2;" : "=f"(f.x), "=f"(f.y) : "l"(v)); return f;
}

// fast exp on fma/alu pipes only (no MUFU). valid for |x| < ~80.
__device__ __forceinline__ float fexp(float x) {
    float t = x * 1.4426950408889634f;
    float fi = floorf(t);
    float f = t - fi;
    float p = 0.0018775767f;
    p = p * f + 0.0089893397f;
    p = p * f + 0.0558186204f;
    p = p * f + 0.2402301537f;
    p = p * f + 0.6931469188f;
    p = p * f + 1.0f;
    int ei = (int)fi;
    return p * __int_as_float((ei + 127) << 23);
}

// ---------------- scratch (device globals: allocation-free) ----------------
__device__ __align__(16) float g_qzn[NELEM];
__device__ __align__(16) __nv_bfloat16 g_qzn_h[NELEM];
__device__ __align__(16) __nv_bfloat16 g_qzn_l[NELEM];
__device__ __align__(16) float g_qut[NELEM];
__device__ __align__(16) float g_qvt[NELEM];
__device__ __align__(16) float g_quc[NELEM];
__device__ __align__(16) float g_qvc[NELEM];
__device__ __align__(16) float g_msg[NELEM];
__device__ __align__(16) __nv_bfloat16 g_binN_h[(size_t)BB * GG * DD];
__device__ __align__(16) __nv_bfloat16 g_binT_h[(size_t)BB * DD * GG];
__device__ __align__(16) __nv_bfloat16 g_wp_h[(size_t)4 * BB * DD * DD];
__device__ __align__(16) __nv_bfloat16 g_w1_h[DD*DD], g_w1_l[DD*DD];
__device__ __align__(16) __nv_bfloat16 g_w2_h[DD*DD], g_w2_l[DD*DD];

// ================= mma.sync helpers =================
__device__ __forceinline__ uint32_t smem_u32(const void* p) {
    uint32_t a;
    asm("{ .reg .u64 t; cvta.to.shared.u64 t, %1; cvt.u32.u64 %0, t; }" : "=r"(a) : "l"(p));
    return a;
}

#define LDSM4(R, addr) \
    asm volatile("ldmatrix.sync.aligned.m8n8.x4.shared.b16 {%0,%1,%2,%3}, [%4];" \
        : "=r"((R)[0]), "=r"((R)[1]), "=r"((R)[2]), "=r"((R)[3]) : "r"(addr))

#define MMA16816(C, A, b0, b1) \
    asm volatile("mma.sync.aligned.m16n8k16.row.col.f32.bf16.bf16.f32 " \
        "{%0,%1,%2,%3},{%4,%5,%6,%7},{%8,%9},{%0,%1,%2,%3};" \
        : "+f"((C)[0]), "+f"((C)[1]), "+f"((C)[2]), "+f"((C)[3]) \
        : "r"((A)[0]), "r"((A)[1]), "r"((A)[2]), "r"((A)[3]), "r"(b0), "r"(b1))

__device__ __forceinline__ void split2(float x0, float x1, uint32_t& hp, uint32_t& lp) {
    __nv_bfloat16 h0 = __float2bfloat16(x0), h1 = __float2bfloat16(x1);
    __nv_bfloat16 l0 = __float2bfloat16(x0 - __bfloat162float(h0));
    __nv_bfloat16 l1 = __float2bfloat16(x1 - __bfloat162float(h1));
    hp = ((uint32_t)__bfloat16_as_ushort(h1) << 16) | __bfloat16_as_ushort(h0);
    lp = ((uint32_t)__bfloat16_as_ushort(l1) << 16) | __bfloat16_as_ushort(l0);
}
__device__ __forceinline__ uint32_t hi2(float x0, float x1) {
    __nv_bfloat16 h0 = __float2bfloat16(x0), h1 = __float2bfloat16(x1);
    return ((uint32_t)__bfloat16_as_ushort(h1) << 16) | __bfloat16_as_ushort(h0);
}

// copy pre-split hi/lo global rows into smem tiles
__device__ __forceinline__ void copy_rows(const uint32_t* gh, const uint32_t* gl,
                                          int rows, int stride_u32,
                                          char* smH, char* smL, int tid) {
    for (int i = tid; i < rows*16; i += 256) {
        int row = i >> 4, c = i & 15;
        *(uint4*)(smH + row*RSB + 16*c) = *(const uint4*)(gh + row*stride_u32 + 4*c);
        *(uint4*)(smL + row*RSB + 16*c) = *(const uint4*)(gl + row*stride_u32 + 4*c);
    }
}
__device__ __forceinline__ void copy_rows1(const uint32_t* gh,
                                           int rows, int stride_u32,
                                           char* smH, int tid) {
    for (int i = tid; i < rows*16; i += 256) {
        int row = i >> 4, c = i & 15;
        *(uint4*)(smH + row*RSB + 16*c) = *(const uint4*)(gh + row*stride_u32 + 4*c);
    }
}

// ---- M=64 3-product mainloop, double-buffered LDSM ----
__device__ __forceinline__ void mm64(uint32_t ah, uint32_t al,
                                     uint32_t bh, uint32_t bl,
                                     int lane, int wm, int wn,
                                     float acc[2][4][4]) {
    int r16 = lane & 15;
    uint32_t aoff = (uint32_t)(wm*32 + r16)*RSB + ((lane >> 4) << 4);
    uint32_t boff = (uint32_t)(wn*32 + r16)*RSB + ((lane >> 4) << 4);
    uint32_t Ah[2][2][4], Al[2][2][4], Bh[2][2][4], Bl[2][2][4];
    LDSM4(Ah[0][0], ah + aoff); LDSM4(Ah[0][1], ah + aoff + 16*RSB);
    LDSM4(Al[0][0], al + aoff); LDSM4(Al[0][1], al + aoff + 16*RSB);
    LDSM4(Bh[0][0], bh + boff); LDSM4(Bh[0][1], bh + boff + 16*RSB);
    LDSM4(Bl[0][0], bl + boff); LDSM4(Bl[0][1], bl + boff + 16*RSB);
#pragma unroll
    for (int ks = 0; ks < 8; ks++) {
        int cur = ks & 1, nxt = cur ^ 1;
        if (ks < 7) {
            uint32_t ko = (uint32_t)(ks + 1) * 32;
            LDSM4(Ah[nxt][0], ah + aoff + ko); LDSM4(Ah[nxt][1], ah + aoff + 16*RSB + ko);
            LDSM4(Al[nxt][0], al + aoff + ko); LDSM4(Al[nxt][1], al + aoff + 16*RSB + ko);
            LDSM4(Bh[nxt][0], bh + boff + ko); LDSM4(Bh[nxt][1], bh + boff + 16*RSB + ko);
            LDSM4(Bl[nxt][0], bl + boff + ko); LDSM4(Bl[nxt][1], bl + boff + 16*RSB + ko);
        }
#pragma unroll
        for (int mt = 0; mt < 2; mt++)
#pragma unroll
            for (int bt = 0; bt < 2; bt++) {
                MMA16816(acc[mt][2*bt],   Ah[cur][mt], Bh[cur][bt][0], Bh[cur][bt][2]);
                MMA16816(acc[mt][2*bt+1], Ah[cur][mt], Bh[cur][bt][1], Bh[cur][bt][3]);
                MMA16816(acc[mt][2*bt],   Ah[cur][mt], Bl[cur][bt][0], Bl[cur][bt][2]);
                MMA16816(acc[mt][2*bt+1], Ah[cur][mt], Bl[cur][bt][1], Bl[cur][bt][3]);
                MMA16816(acc[mt][2*bt],   Al[cur][mt], Bh[cur][bt][0], Bh[cur][bt][2]);
                MMA16816(acc[mt][2*bt+1], Al[cur][mt], Bh[cur][bt][1], Bh[cur][bt][3]);
            }
    }
}

// ---- M=64 2-product mainloop (B hi only): C = (Ah+Al)·Bh ----
__device__ __forceinline__ void mm64_2p(uint32_t ah, uint32_t al, uint32_t bh,
                                        int lane, int wm, int wn,
                                        float acc[2][4][4]) {
    int r16 = lane & 15;
    uint32_t aoff = (uint32_t)(wm*32 + r16)*RSB + ((lane >> 4) << 4);
    uint32_t boff = (uint32_t)(wn*32 + r16)*RSB + ((lane >> 4) << 4);
    uint32_t Ah[2][2][4], Al[2][2][4], Bh[2][2][4];
    LDSM4(Ah[0][0], ah + aoff); LDSM4(Ah[0][1], ah + aoff + 16*RSB);
    LDSM4(Al[0][0], al + aoff); LDSM4(Al[0][1], al + aoff + 16*RSB);
    LDSM4(Bh[0][0], bh + boff); LDSM4(Bh[0][1], bh + boff + 16*RSB);
#pragma unroll
    for (int ks = 0; ks < 8; ks++) {
        int cur = ks & 1, nxt = cur ^ 1;
        if (ks < 7) {
            uint32_t ko = (uint32_t)(ks + 1) * 32;
            LDSM4(Ah[nxt][0], ah + aoff + ko); LDSM4(Ah[nxt][1], ah + aoff + 16*RSB + ko);
            LDSM4(Al[nxt][0], al + aoff + ko); LDSM4(Al[nxt][1], al + aoff + 16*RSB + ko);
            LDSM4(Bh[nxt][0], bh + boff + ko); LDSM4(Bh[nxt][1], bh + boff + 16*RSB + ko);
        }
#pragma unroll
        for (int mt = 0; mt < 2; mt++)
#pragma unroll
            for (int bt = 0; bt < 2; bt++) {
                MMA16816(acc[mt][2*bt],   Ah[cur][mt], Bh[cur][bt][0], Bh[cur][bt][2]);
                MMA16816(acc[mt][2*bt+1], Ah[cur][mt], Bh[cur][bt][1], Bh[cur][bt][3]);
                MMA16816(acc[mt][2*bt],   Al[cur][mt], Bh[cur][bt][0], Bh[cur][bt][2]);
                MMA16816(acc[mt][2*bt+1], Al[cur][mt], Bh[cur][bt][1], Bh[cur][bt][3]);
            }
    }
}

#define A64 (64*RSB)         // 17408
#define TILE_B (128*RSB)     // 34816
// generic 2-product layout: A hi/lo + B hi
#define O64_AH 0
#define O64_AL A64
#define O64_BH (2*A64)
#define SM_G2 (2*A64 + TILE_B)           // 69632 -> 3 CTAs/SM
// fused topic layout: + S hi/lo after BH
#define OT_SH (2*A64 + TILE_B)
#define OT_SL (OT_SH + A64)
#define SM_TOPIC (OT_SL + A64 + 256)     // 104704 -> 2 CTAs/SM
// fused MLP layout: A hi/lo + W hi/lo (W1 then W2 in-place)
#define OM_BH (2*A64)
#define OM_BL (2*A64 + TILE_B)
#define SM_MLP (2*A64 + 2*TILE_B)        // 104448 -> 2 CTAs/SM

// ---------------- K1: layernorm -> g_qzn fp32 + hi/lo bf16 ----------------
__global__ __launch_bounds__(256) void k_ln(const float* __restrict__ x,
                                            const float* __restrict__ gw,
                                            const float* __restrict__ gb) {
    int w = (blockIdx.x * 256 + threadIdx.x) >> 5;
    int lane = threadIdx.x & 31;
    if (w >= NTOK) return;
    const float2* xr = (const float2*)(x + (size_t)w * DD);
    float2 v0 = xr[lane], v1 = xr[lane + 32];
    float s = v0.x + v0.y + v1.x + v1.y;
#pragma unroll
    for (int o = 16; o; o >>= 1) s += __shfl_xor_sync(0xffffffffu, s, o);
    float mu = s * (1.0f/128.0f);
    float q = (v0.x-mu)*(v0.x-mu) + (v0.y-mu)*(v0.y-mu)
            + (v1.x-mu)*(v1.x-mu) + (v1.y-mu)*(v1.y-mu);
#pragma unroll
    for (int o = 16; o; o >>= 1) q += __shfl_xor_sync(0xffffffffu, q, o);
    float inv = rsqrtf(q * (1.0f/128.0f) + 1e-5f);
    float2* yr = (float2*)(g_qzn + (size_t)w * DD);
    uint32_t* yh = (uint32_t*)(g_qzn_h + (size_t)w * DD);
    uint32_t* yl = (uint32_t*)(g_qzn_l + (size_t)w * DD);
#pragma unroll
    for (int j = 0; j < 2; j++) {
        float2 v = j ? v1 : v0;
        int dp = lane + 32*j;
        float y0 = (v.x-mu)*inv*gw[2*dp]   + gb[2*dp];
        float y1 = (v.y-mu)*inv*gw[2*dp+1] + gb[2*dp+1];
        yr[dp] = make_float2(y0, y1);
        uint32_t hp, lp;
        split2(y0, y1, hp, lp);
        yh[dp] = hp; yl[dp] = lp;
    }
}

// ---------------- K1b: split/convert static GEMM operands -------------------
#define N2_BIN (BB*GG*DD/2)
#define N2_W   (BB*DD*DD/2)
#define N2_MW  (DD*DD/2)
#define N2_TOT (N2_BIN + 4*N2_W)
__global__ __launch_bounds__(256) void k_split_all(const float* __restrict__ bin,
                                                   const float* __restrict__ tu,
                                                   const float* __restrict__ tv,
                                                   const float* __restrict__ cu,
                                                   const float* __restrict__ cv) {
    int i = blockIdx.x * 256 + threadIdx.x;
    if (i >= N2_TOT) return;
    const float* src; uint32_t* dh; int off;
    if (i < N2_BIN) {
        src = bin; dh = (uint32_t*)g_binN_h; off = i;
    } else {
        int j = i - N2_BIN, pj = j / N2_W; off = j % N2_W;
        src = (pj == 0) ? tu : (pj == 1) ? tv : (pj == 2) ? cu : cv;
        dh = (uint32_t*)g_wp_h + (size_t)pj * N2_W;
    }
    float2 v = ((const float2*)src)[off];
    dh[off] = hi2(v.x, v.y);
}
__global__ __launch_bounds__(256) void k_split_mw(const float* __restrict__ w1,
                                                  const float* __restrict__ w2) {
    int i = blockIdx.x * 256 + threadIdx.x;
    if (i >= 2*N2_MW) return;
    const float* src = (i < N2_MW) ? w1 : w2;
    uint32_t* dh = (i < N2_MW) ? (uint32_t*)g_w1_h : (uint32_t*)g_w2_h;
    uint32_t* dl = (i < N2_MW) ? (uint32_t*)g_w1_l : (uint32_t*)g_w2_l;
    int off = (i < N2_MW) ? i : i - N2_MW;
    float2 v = ((const float2*)src)[off];
    uint32_t hp, lp; split2(v.x, v.y, hp, lp);
    dh[off] = hp; dl[off] = lp;
}

// ---------------- K1c: transpose topic_binary -> g_binT_h [b][d][g] ---------
#define TSTR 129
__global__ __launch_bounds__(256) void k_binT(const float* __restrict__ bin) {
    extern __shared__ float smf[];
    int gt = blockIdx.x, b = blockIdx.y;
    int tid = threadIdx.x;
    const float* src = bin + ((size_t)b * GG + (size_t)gt * 128) * DD;
    for (int i = tid; i < 128*128; i += 256) {
        int g = i >> 7, d = i & 127;
        smf[g*TSTR + d] = src[i];
    }
    __syncthreads();
    uint32_t* oh = (uint32_t*)(g_binT_h + (size_t)b * DD * GG + (size_t)gt * 128);
    for (int i = tid; i < 128*64; i += 256) {
        int d = i >> 6, gp = i & 63;
        float v0 = smf[(2*gp)*TSTR + d], v1 = smf[(2*gp+1)*TSTR + d];
        size_t o = ((size_t)d * GG) / 2 + gp;
        oh[o] = hi2(v0, v1);
    }
}

// ---------------- K2: projection GEMMs (2-product), 3 CTAs/SM --------------
// grid (192 token tiles, 4 proj, 8 b)
__global__ __launch_bounds__(256, 3) void k_gemm1() {
    extern __shared__ char sm[];
    uint32_t smb = smem_u32(sm);
    int tid = threadIdx.x, wid = tid >> 5, lane = tid & 31;
    int wm = wid & 1, wn = wid >> 1;
    int tile = blockIdx.x, pj = blockIdx.y, b = blockIdx.z;
    size_t tokbase = (size_t)b * TPB + (size_t)tile * 64;
    copy_rows((const uint32_t*)(g_qzn_h + tokbase * DD),
              (const uint32_t*)(g_qzn_l + tokbase * DD),
              64, 64, sm + O64_AH, sm + O64_AL, tid);
    const uint32_t* bh = (const uint32_t*)g_wp_h + ((size_t)pj * BB + b) * (DD*DD/2);
    copy_rows1(bh, 128, 64, sm + O64_BH, tid);
    __syncthreads();
    float acc[2][4][4];
#pragma unroll
    for (int mt = 0; mt < 2; mt++)
#pragma unroll
        for (int nt = 0; nt < 4; nt++)
#pragma unroll
            for (int j = 0; j < 4; j++) acc[mt][nt][j] = 0.f;
    mm64_2p(smb + O64_AH, smb + O64_AL, smb + O64_BH, lane, wm, wn, acc);
    float* y = (pj == 0) ? g_qut : (pj == 1) ? g_qvt : (pj == 2) ? g_quc : g_qvc;
#pragma unroll
    for (int mt = 0; mt < 2; mt++)
#pragma unroll
        for (int h = 0; h < 2; h++) {
            int row = wm*32 + mt*16 + (lane >> 2) + 8*h;
            float* yr = y + (tokbase + row) * DD;
#pragma unroll
            for (int nt = 0; nt < 4; nt++) {
                int col = wn*32 + nt*8 + (lane & 3)*2;
                *(float2*)&yr[col] = make_float2(acc[mt][nt][2*h], acc[mt][nt][2*h+1]);
            }
        }
}

// ---------------- K4: fused topic (S GEMM + normalize GEMM) + combine -------
// grid (192 token tiles, 8 b)
__global__ __launch_bounds__(256, 2) void k_topic(const float* __restrict__ un,
                                                  const float* __restrict__ old,
                                                  float* __restrict__ out) {
    extern __shared__ char sm[];
    uint32_t smb = smem_u32(sm);
    float* rs = (float*)(sm + OT_SL + A64);
    int tid = threadIdx.x, wid = tid >> 5, lane = tid & 31;
    int wm = wid & 1, wn = wid >> 1;
    int tile = blockIdx.x, b = blockIdx.y;
    size_t btok = (size_t)b * TPB + (size_t)tile * 64;
    copy_rows((const uint32_t*)(g_qzn_h + btok * DD),
              (const uint32_t*)(g_qzn_l + btok * DD),
              64, 64, sm + O64_AH, sm + O64_AL, tid);
    if (tid < 64) rs[tid] = 0.f;

    float acc2[2][4][4];
#pragma unroll
    for (int mt = 0; mt < 2; mt++)
#pragma unroll
        for (int nt = 0; nt < 4; nt++)
#pragma unroll
            for (int j = 0; j < 4; j++) acc2[mt][nt][j] = 0.f;

    for (int gc = 0; gc < 4; gc++) {
        __syncthreads();   // BH free (prev GEMM2 done); A/rs ready on first iter
        copy_rows1((const uint32_t*)g_binN_h + ((size_t)b * GG + (size_t)gc * 128) * (DD/2),
                   128, 64, sm + O64_BH, tid);
        __syncthreads();
        // GEMM1: S = qzn @ binN_gc^T
        float acc1[2][4][4];
#pragma unroll
        for (int mt = 0; mt < 2; mt++)
#pragma unroll
            for (int nt = 0; nt < 4; nt++)
#pragma unroll
                for (int j = 0; j < 4; j++) acc1[mt][nt][j] = 0.f;
        mm64_2p(smb + O64_AH, smb + O64_AL, smb + O64_BH, lane, wm, wn, acc1);
        __syncthreads();   // BH free before overwrite with binT
        // relu + split into S tiles + rowsum
#pragma unroll
        for (int mt = 0; mt < 2; mt++)
#pragma unroll
            for (int h = 0; h < 2; h++) {
                int row = wm*32 + mt*16 + (lane >> 2) + 8*h;
                float part = 0.f;
#pragma unroll
                for (int nt = 0; nt < 4; nt++) {
                    int col = wn*32 + nt*8 + (lane & 3)*2;
                    float f0 = fmaxf(acc1[mt][nt][2*h], 0.f);
                    float f1 = fmaxf(acc1[mt][nt][2*h+1], 0.f);
                    part += f0 + f1;
                    uint32_t hp, lp;
                    split2(f0, f1, hp, lp);
                    *(uint32_t*)(sm + OT_SH + row*RSB + 2*col) = hp;
                    *(uint32_t*)(sm + OT_SL + row*RSB + 2*col) = lp;
                }
                atomicAdd(&rs[row], part);
            }
        copy_rows1((const uint32_t*)g_binT_h + (size_t)b * (DD*GG/2) + gc*64,
                   128, GG/2, sm + O64_BH, tid);
        __syncthreads();   // S tiles + binT visible
        // GEMM2: msg += S_gc @ binT_gc
        mm64_2p(smb + OT_SH, smb + OT_SL, smb + O64_BH, lane, wm, wn, acc2);
    }
    __syncthreads();
#pragma unroll
    for (int mt = 0; mt < 2; mt++)
#pragma unroll
        for (int h = 0; h < 2; h++) {
            int row = wm*32 + mt*16 + (lane >> 2) + 8*h;
            float inv = 1.0f / fmaxf(rs[row], 1e-6f);
            size_t rbase = (btok + row) * DD;
#pragma unroll
            for (int nt = 0; nt < 4; nt++) {
                int col = wn*32 + nt*8 + (lane & 3)*2;
                float2 m = *(const float2*)&g_msg[rbase + col];
                float2 u = *(const float2*)&un[rbase + col];
                float2 o = *(const float2*)&old[rbase + col];
                float2 r;
                r.x = 0.5f*(u.x + o.x + m.x + acc2[mt][nt][2*h]   * inv);
                r.y = 0.5f*(u.y + o.y + m.y + acc2[mt][nt][2*h+1] * inv);
                *(float2*)&out[rbase + col] = r;
            }
        }
}

// ---------------- K5: time attention (head-sum folded, poly exp) ------------
#define SM_TATTN ((3*96*PSTR + 96*ASTR)*4)
__global__ __launch_bounds__(256) void k_tattn() {
    extern __shared__ float smf[];
    float* Xs = smf;
    float* Qu = Xs + 96*PSTR;
    float* Qv = Qu + 96*PSTR;
    float* As = Qv + 96*PSTR;
    int tid = threadIdx.x, lane = tid & 31, wg = tid >> 5;
    size_t base = (size_t)blockIdx.x * PP * DD;
    for (int i = tid; i < PP*DD; i += 256) {
        int r = i >> 7, d = i & 127;
        Xs[r*PSTR+d] = g_qzn[base + i];
        Qu[r*PSTR+d] = g_qut[base + i];
        Qv[r*PSTR+d] = g_qvt[base + i];
    }
#pragma unroll
    for (int k = 0; k < 12; k++)
#pragma unroll
        for (int j = 0; j < 3; j++)
            As[(wg + 8*k)*ASTR + lane + 32*j] = 0.f;
    __syncthreads();

    for (int h = 0; h < HH; h++) {
        int ho = h * 16;
#pragma unroll 1
        for (int pr = 0; pr < 12; pr++) {
            int p = wg + 8*pr;
            u64 qu2[8];
#pragma unroll
            for (int r = 0; r < 8; r++) qu2[r] = *(const u64*)&Qu[p*PSTR + ho + 2*r];
            float lg[3];
#pragma unroll
            for (int qi = 0; qi < 3; qi++) {
                int q = lane + 32*qi;
                u64 s2 = 0ull;
#pragma unroll
                for (int r = 0; r < 8; r++) {
                    u64 qv2 = *(const u64*)&Qv[q*PSTR + ho + 2*r];
                    s2 = fma2(qu2[r], qv2, s2);
                }
                float2 sp = up2(s2);
                lg[qi] = (sp.x + sp.y) * 0.25f;
            }
            float e0 = fexp(lg[0]), e1 = fexp(lg[1]), e2 = fexp(lg[2]);
            float ssum = e0 + e1 + e2;
#pragma unroll
            for (int o = 16; o; o >>= 1) ssum += __shfl_xor_sync(0xffffffffu, ssum, o);
            float inv = 0.125f / ssum;
            As[p*ASTR + lane]      += e0 * inv;
            As[p*ASTR + lane + 32] += e1 * inv;
            As[p*ASTR + lane + 64] += e2 * inv;
        }
    }
    __syncthreads();

    u64 acc[12][2];
#pragma unroll
    for (int k = 0; k < 12; k++) { acc[k][0] = 0ull; acc[k][1] = 0ull; }
#pragma unroll 2
    for (int q = 0; q < PP; q++) {
        ulonglong2 xA = *(const ulonglong2*)&Xs[q*PSTR + 4*lane];
#pragma unroll
        for (int k = 0; k < 12; k++) {
            u64 ap = pk2(As[(wg + 8*k)*ASTR + q]);
            acc[k][0] = fma2(ap, xA.x, acc[k][0]);
            acc[k][1] = fma2(ap, xA.y, acc[k][1]);
        }
    }
#pragma unroll
    for (int k = 0; k < 12; k++) {
        int p = wg + 8*k;
        float2 p0 = up2(acc[k][0]), p1 = up2(acc[k][1]);
        *(float4*)&g_msg[base + (size_t)p*DD + 4*lane] = make_float4(p0.x, p0.y, p1.x, p1.y);
    }
}

// ---------------- K6: channel attention (poly exp) -> g_msg += ----------------
#define SM_CATTN (3*128*PSTR*4)
__global__ __launch_bounds__(256) void k_cattn() {
    extern __shared__ float smf[];
    float* Qu = smf;
    float* Qv = Qu + 128*PSTR;
    float* Ac = Qv + 128*PSTR;
    int b = blockIdx.x / PP, p = blockIdx.x % PP;
    int tid = threadIdx.x, lane = tid & 31, wg = tid >> 5;
    for (int i = tid; i < CC*DD; i += 256) {
        int c = i >> 7, d = i & 127;
        size_t gi = (((size_t)b*CC + c)*PP + p)*DD + d;
        Qu[c*PSTR+d] = g_quc[gi];
        Qv[c*PSTR+d] = g_qvc[gi];
        Ac[c*PSTR+d] = 0.f;
    }
    __syncthreads();
    for (int h = 0; h < HH; h++) {
        int ho = h*16;
#pragma unroll 1
        for (int cr = 0; cr < 16; cr++) {
            int c = wg + 8*cr;
            u64 qu2[8];
#pragma unroll
            for (int r = 0; r < 8; r++) qu2[r] = *(const u64*)&Qu[c*PSTR + ho + 2*r];
            float lg[4];
#pragma unroll
            for (int j = 0; j < 4; j++) {
                int d = lane + 32*j;
                u64 s2 = 0ull;
#pragma unroll
                for (int r = 0; r < 8; r++) {
                    u64 qv2 = *(const u64*)&Qv[d*PSTR + ho + 2*r];
                    s2 = fma2(qu2[r], qv2, s2);
                }
                float2 sp = up2(s2);
                lg[j] = (sp.x + sp.y) * 0.25f;
            }
            float e[4], ssum = 0.f;
#pragma unroll
            for (int j = 0; j < 4; j++) { e[j] = fexp(lg[j]); ssum += e[j]; }
#pragma unroll
            for (int o = 16; o; o >>= 1) ssum += __shfl_xor_sync(0xffffffffu, ssum, o);
            float inv = 0.125f / ssum;
#pragma unroll
            for (int j = 0; j < 4; j++) Ac[c*PSTR + lane + 32*j] += e[j] * inv;
        }
    }
#pragma unroll
    for (int cr = 0; cr < 16; cr++) {
        int c = wg + 8*cr;
#pragma unroll
        for (int j = 0; j < 4; j++) {
            int d = lane + 32*j;
            size_t gi = (((size_t)b*CC + c)*PP + p)*DD + d;
            g_msg[gi] += Ac[c*PSTR+d] * g_qzn[gi];
        }
    }
}

// ---------------- K7: fused MLP: LN + GEMM1 + gelu + GEMM2 + residual -------
// grid (NTOK/64). smem: A hi/lo + W hi/lo (W1 then W2 in-place). 2 CTAs/SM.
__global__ __launch_bounds__(256, 2) void k_mlp(float* __restrict__ io,
                                                const float* __restrict__ gw,
                                                const float* __restrict__ gb,
                                                const float* __restrict__ b1,
                                                const float* __restrict__ b2) {
    extern __shared__ char sm[];
    uint32_t smb = smem_u32(sm);
    int tid = threadIdx.x, wid = tid >> 5, lane = tid & 31;
    int wm = wid & 1, wn = wid >> 1;
    size_t tokbase = (size_t)blockIdx.x * 64;
    copy_rows((const uint32_t*)g_w1_h, (const uint32_t*)g_w1_l,
              128, 64, sm + OM_BH, sm + OM_BL, tid);
    // LN: 8 warps x 8 tokens -> A hi/lo
#pragma unroll 1
    for (int it = 0; it < 8; it++) {
        int t = wid + 8*it;
        const float2* xr = (const float2*)(io + (tokbase + t) * DD);
        float2 v0 = xr[lane], v1 = xr[lane + 32];
        float s = v0.x + v0.y + v1.x + v1.y;
#pragma unroll
        for (int o = 16; o; o >>= 1) s += __shfl_xor_sync(0xffffffffu, s, o);
        float mu = s * (1.0f/128.0f);
        float q = (v0.x-mu)*(v0.x-mu) + (v0.y-mu)*(v0.y-mu)
                + (v1.x-mu)*(v1.x-mu) + (v1.y-mu)*(v1.y-mu);
#pragma unroll
        for (int o = 16; o; o >>= 1) q += __shfl_xor_sync(0xffffffffu, q, o);
        float inv = rsqrtf(q * (1.0f/128.0f) + 1e-5f);
#pragma unroll
        for (int j = 0; j < 2; j++) {
            float2 v = j ? v1 : v0;
            int dp = lane + 32*j;
            float y0 = (v.x-mu)*inv*gw[2*dp]   + gb[2*dp];
            float y1 = (v.y-mu)*inv*gw[2*dp+1] + gb[2*dp+1];
            uint32_t hp, lp;
            split2(y0, y1, hp, lp);
            *(uint32_t*)(sm + O64_AH + t*RSB + 4*dp) = hp;
            *(uint32_t*)(sm + O64_AL + t*RSB + 4*dp) = lp;
        }
    }
    __syncthreads();
    // GEMM1
    float acc[2][4][4];
#pragma unroll
    for (int mt = 0; mt < 2; mt++)
#pragma unroll
        for (int nt = 0; nt < 4; nt++)
#pragma unroll
            for (int j = 0; j < 4; j++) acc[mt][nt][j] = 0.f;
    mm64(smb + O64_AH, smb + O64_AL, smb + OM_BH, smb + OM_BL, lane, wm, wn, acc);
    __syncthreads();   // everyone done with A + W1 tiles
    // gelu frags -> A tiles; W2 -> W tiles
#pragma unroll
    for (int mt = 0; mt < 2; mt++)
#pragma unroll
        for (int h = 0; h < 2; h++) {
            int row = wm*32 + mt*16 + (lane >> 2) + 8*h;
#pragma unroll
            for (int nt = 0; nt < 4; nt++) {
                int col = wn*32 + nt*8 + (lane & 3)*2;
                float2 bv = *(const float2*)&b1[col];
                float x0 = acc[mt][nt][2*h]   + bv.x;
                float x1 = acc[mt][nt][2*h+1] + bv.y;
                float g0 = 0.5f * x0 * (1.0f + erff(x0 * 0.70710678118654752f));
                float g1 = 0.5f * x1 * (1.0f + erff(x1 * 0.70710678118654752f));
                uint32_t hp, lp;
                split2(g0, g1, hp, lp);
                *(uint32_t*)(sm + O64_AH + row*RSB + 2*col) = hp;
                *(uint32_t*)(sm + O64_AL + row*RSB + 2*col) = lp;
            }
        }
    copy_rows((const uint32_t*)g_w2_h, (const uint32_t*)g_w2_l,
              128, 64, sm + OM_BH, sm + OM_BL, tid);
    __syncthreads();
    // GEMM2 + residual
    float acc2[2][4][4];
#pragma unroll
    for (int mt = 0; mt < 2; mt++)
#pragma unroll
        for (int nt = 0; nt < 4; nt++)
#pragma unroll
            for (int j = 0; j < 4; j++) acc2[mt][nt][j] = 0.f;
    mm64(smb + O64_AH, smb + O64_AL, smb + OM_BH, smb + OM_BL, lane, wm, wn, acc2);
#pragma unroll
    for (int mt = 0; mt < 2; mt++)
#pragma unroll
        for (int h = 0; h < 2; h++) {
            int row = wm*32 + mt*16 + (lane >> 2) + 8*h;
            float* ir = io + (tokbase + row) * DD;
#pragma unroll
            for (int nt = 0; nt < 4; nt++) {
                int col = wn*32 + nt*8 + (lane & 3)*2;
                float2 bv = *(const float2*)&b2[col];
                float2 v = *(float2*)&ir[col];
                v.x += acc2[mt][nt][2*h]   + bv.x;
                v.y += acc2[mt][nt][2*h+1] + bv.y;
                *(float2*)&ir[col] = v;
            }
        }
}

// ---------------- host launcher ----------------
extern "C" void kernel_launch(void* const* d_in, const int* in_sizes, int n_in,
                              void* d_out, int out_size) {
    (void)in_sizes; (void)n_in; (void)out_size;
    const float* qz  = (const float*)d_in[0];
    const float* un  = (const float*)d_in[1];
    const float* tu  = (const float*)d_in[2];
    const float* tv  = (const float*)d_in[3];
    const float* cu  = (const float*)d_in[4];
    const float* cv  = (const float*)d_in[5];
    const float* bin = (const float*)d_in[6];
    const float* lng = (const float*)d_in[7];
    const float* lnb = (const float*)d_in[8];
    const float* w1  = (const float*)d_in[9];
    const float* b1  = (const float*)d_in[10];
    const float* w2  = (const float*)d_in[11];
    const float* b2  = (const float*)d_in[12];
    float* out = (float*)d_out;

    cudaFuncSetAttribute(k_binT,  cudaFuncAttributeMaxDynamicSharedMemorySize, 128*TSTR*4);
    cudaFuncSetAttribute(k_gemm1, cudaFuncAttributeMaxDynamicSharedMemorySize, SM_G2);
    cudaFuncSetAttribute(k_topic, cudaFuncAttributeMaxDynamicSharedMemorySize, SM_TOPIC);
    cudaFuncSetAttribute(k_tattn, cudaFuncAttributeMaxDynamicSharedMemorySize, SM_TATTN);
    cudaFuncSetAttribute(k_cattn, cudaFuncAttributeMaxDynamicSharedMemorySize, SM_CATTN);
    cudaFuncSetAttribute(k_mlp,   cudaFuncAttributeMaxDynamicSharedMemorySize, SM_MLP);

    k_ln<<<(NTOK*32)/256, 256>>>(qz, lng, lnb);
    k_split_all<<<(N2_TOT + 255)/256, 256>>>(bin, tu, tv, cu, cv);
    k_split_mw<<<(2*N2_MW + 255)/256, 256>>>(w1, w2);
    k_binT<<<dim3(4, BB), 256, 128*TSTR*4>>>(bin);

    dim3 g1(TPB/64, 4, BB);
    k_gemm1<<<g1, 256, SM_G2>>>();

    k_tattn<<<BB*CC, 256, SM_TATTN>>>();
    k_cattn<<<BB*PP, 256, SM_CATTN>>>();

    dim3 og(TPB/64, BB);
    k_topic<<<og, 256, SM_TOPIC>>>(un, qz, out);

    k_mlp<<<NTOK/64, 256, SM_MLP>>>(out, lng, lnb, b1, b2);
}

// round 17
// speedup vs baseline: 2.5472x; 1.0379x over previous
#include <cuda_runtime.h>
#include <cuda_bf16.h>
#include <math.h>
#include <stdint.h>

#define BB 8
#define CC 128
#define PP 96
#define DD 128
#define HH 8
#define GG 512
#define TPB (CC*PP)          // 12288 tokens per batch
#define NTOK (BB*TPB)        // 98304
#define NELEM (NTOK*DD)      // 12582912

#define PSTR 132
#define ASTR 98
#define RSB 272              // smem bf16 tile row stride in BYTES

typedef unsigned long long u64;

__device__ __forceinline__ u64 pk2(float x) {
    u64 r; asm("mov.b64 %0,{%1,%1};" : "=l"(r) : "f"(x)); return r;
}
__device__ __forceinline__ u64 fma2(u64 a, u64 b, u64 c) {
    asm("fma.rn.f32x2 %0,%1,%2,%0;" : "+l"(c) : "l"(a), "l"(b)); return c;
}
__device__ __forceinline__ float2 up2(u64 v) {
    float2 f; asm("mov.b64 {%0,%1},%2;" : "=f"(f.x), "=f"(f.y) : "l"(v)); return f;
}

// fast exp on fma/alu pipes only (no MUFU). valid for |x| < ~80.
__device__ __forceinline__ float fexp(float x) {
    float t = x * 1.4426950408889634f;
    float fi = floorf(t);
    float f = t - fi;
    float p = 0.0018775767f;
    p = p * f + 0.0089893397f;
    p = p * f + 0.0558186204f;
    p = p * f + 0.2402301537f;
    p = p * f + 0.6931469188f;
    p = p * f + 1.0f;
    int ei = (int)fi;
    return p * __int_as_float((ei + 127) << 23);
}

// ---------------- scratch (device globals: allocation-free) ----------------
__device__ __align__(16) float g_qzn[NELEM];
__device__ __align__(16) __nv_bfloat16 g_qzn_h[NELEM];
__device__ __align__(16) __nv_bfloat16 g_qzn_l[NELEM];
__device__ __align__(16) float g_qut[NELEM];
__device__ __align__(16) float g_qvt[NELEM];
__device__ __align__(16) float g_quc[NELEM];
__device__ __align__(16) float g_qvc[NELEM];
__device__ __align__(16) float g_msg[NELEM];
__device__ __align__(16) __nv_bfloat16 g_binN_h[(size_t)BB * GG * DD];
__device__ __align__(16) __nv_bfloat16 g_binT_h[(size_t)BB * DD * GG];
__device__ __align__(16) __nv_bfloat16 g_wp_h[(size_t)4 * BB * DD * DD];
__device__ __align__(16) __nv_bfloat16 g_w1_h[DD*DD], g_w1_l[DD*DD];
__device__ __align__(16) __nv_bfloat16 g_w2_h[DD*DD], g_w2_l[DD*DD];

// ================= mma.sync helpers =================
__device__ __forceinline__ uint32_t smem_u32(const void* p) {
    uint32_t a;
    asm("{ .reg .u64 t; cvta.to.shared.u64 t, %1; cvt.u32.u64 %0, t; }" : "=r"(a) : "l"(p));
    return a;
}

#define LDSM4(R, addr) \
    asm volatile("ldmatrix.sync.aligned.m8n8.x4.shared.b16 {%0,%1,%2,%3}, [%4];" \
        : "=r"((R)[0]), "=r"((R)[1]), "=r"((R)[2]), "=r"((R)[3]) : "r"(addr))

#define MMA16816(C, A, b0, b1) \
    asm volatile("mma.sync.aligned.m16n8k16.row.col.f32.bf16.bf16.f32 " \
        "{%0,%1,%2,%3},{%4,%5,%6,%7},{%8,%9},{%0,%1,%2,%3};" \
        : "+f"((C)[0]), "+f"((C)[1]), "+f"((C)[2]), "+f"((C)[3]) \
        : "r"((A)[0]), "r"((A)[1]), "r"((A)[2]), "r"((A)[3]), "r"(b0), "r"(b1))

__device__ __forceinline__ void split2(float x0, float x1, uint32_t& hp, uint32_t& lp) {
    __nv_bfloat16 h0 = __float2bfloat16(x0), h1 = __float2bfloat16(x1);
    __nv_bfloat16 l0 = __float2bfloat16(x0 - __bfloat162float(h0));
    __nv_bfloat16 l1 = __float2bfloat16(x1 - __bfloat162float(h1));
    hp = ((uint32_t)__bfloat16_as_ushort(h1) << 16) | __bfloat16_as_ushort(h0);
    lp = ((uint32_t)__bfloat16_as_ushort(l1) << 16) | __bfloat16_as_ushort(l0);
}
__device__ __forceinline__ uint32_t hi2(float x0, float x1) {
    __nv_bfloat16 h0 = __float2bfloat16(x0), h1 = __float2bfloat16(x1);
    return ((uint32_t)__bfloat16_as_ushort(h1) << 16) | __bfloat16_as_ushort(h0);
}

// copy pre-split hi/lo global rows into smem tiles
__device__ __forceinline__ void copy_rows(const uint32_t* gh, const uint32_t* gl,
                                          int rows, int stride_u32,
                                          char* smH, char* smL, int tid) {
    for (int i = tid; i < rows*16; i += 256) {
        int row = i >> 4, c = i & 15;
        *(uint4*)(smH + row*RSB + 16*c) = *(const uint4*)(gh + row*stride_u32 + 4*c);
        *(uint4*)(smL + row*RSB + 16*c) = *(const uint4*)(gl + row*stride_u32 + 4*c);
    }
}
__device__ __forceinline__ void copy_rows1(const uint32_t* gh,
                                           int rows, int stride_u32,
                                           char* smH, int tid) {
    for (int i = tid; i < rows*16; i += 256) {
        int row = i >> 4, c = i & 15;
        *(uint4*)(smH + row*RSB + 16*c) = *(const uint4*)(gh + row*stride_u32 + 4*c);
    }
}

// ---- M=64 3-product mainloop, double-buffered LDSM ----
__device__ __forceinline__ void mm64(uint32_t ah, uint32_t al,
                                     uint32_t bh, uint32_t bl,
                                     int lane, int wm, int wn,
                                     float acc[2][4][4]) {
    int r16 = lane & 15;
    uint32_t aoff = (uint32_t)(wm*32 + r16)*RSB + ((lane >> 4) << 4);
    uint32_t boff = (uint32_t)(wn*32 + r16)*RSB + ((lane >> 4) << 4);
    uint32_t Ah[2][2][4], Al[2][2][4], Bh[2][2][4], Bl[2][2][4];
    LDSM4(Ah[0][0], ah + aoff); LDSM4(Ah[0][1], ah + aoff + 16*RSB);
    LDSM4(Al[0][0], al + aoff); LDSM4(Al[0][1], al + aoff + 16*RSB);
    LDSM4(Bh[0][0], bh + boff); LDSM4(Bh[0][1], bh + boff + 16*RSB);
    LDSM4(Bl[0][0], bl + boff); LDSM4(Bl[0][1], bl + boff + 16*RSB);
#pragma unroll
    for (int ks = 0; ks < 8; ks++) {
        int cur = ks & 1, nxt = cur ^ 1;
        if (ks < 7) {
            uint32_t ko = (uint32_t)(ks + 1) * 32;
            LDSM4(Ah[nxt][0], ah + aoff + ko); LDSM4(Ah[nxt][1], ah + aoff + 16*RSB + ko);
            LDSM4(Al[nxt][0], al + aoff + ko); LDSM4(Al[nxt][1], al + aoff + 16*RSB + ko);
            LDSM4(Bh[nxt][0], bh + boff + ko); LDSM4(Bh[nxt][1], bh + boff + 16*RSB + ko);
            LDSM4(Bl[nxt][0], bl + boff + ko); LDSM4(Bl[nxt][1], bl + boff + 16*RSB + ko);
        }
#pragma unroll
        for (int mt = 0; mt < 2; mt++)
#pragma unroll
            for (int bt = 0; bt < 2; bt++) {
                MMA16816(acc[mt][2*bt],   Ah[cur][mt], Bh[cur][bt][0], Bh[cur][bt][2]);
                MMA16816(acc[mt][2*bt+1], Ah[cur][mt], Bh[cur][bt][1], Bh[cur][bt][3]);
                MMA16816(acc[mt][2*bt],   Ah[cur][mt], Bl[cur][bt][0], Bl[cur][bt][2]);
                MMA16816(acc[mt][2*bt+1], Ah[cur][mt], Bl[cur][bt][1], Bl[cur][bt][3]);
                MMA16816(acc[mt][2*bt],   Al[cur][mt], Bh[cur][bt][0], Bh[cur][bt][2]);
                MMA16816(acc[mt][2*bt+1], Al[cur][mt], Bh[cur][bt][1], Bh[cur][bt][3]);
            }
    }
}

// ---- M=64 2-product mainloop (B hi only): C = (Ah+Al)·Bh ----
__device__ __forceinline__ void mm64_2p(uint32_t ah, uint32_t al, uint32_t bh,
                                        int lane, int wm, int wn,
                                        float acc[2][4][4]) {
    int r16 = lane & 15;
    uint32_t aoff = (uint32_t)(wm*32 + r16)*RSB + ((lane >> 4) << 4);
    uint32_t boff = (uint32_t)(wn*32 + r16)*RSB + ((lane >> 4) << 4);
    uint32_t Ah[2][2][4], Al[2][2][4], Bh[2][2][4];
    LDSM4(Ah[0][0], ah + aoff); LDSM4(Ah[0][1], ah + aoff + 16*RSB);
    LDSM4(Al[0][0], al + aoff); LDSM4(Al[0][1], al + aoff + 16*RSB);
    LDSM4(Bh[0][0], bh + boff); LDSM4(Bh[0][1], bh + boff + 16*RSB);
#pragma unroll
    for (int ks = 0; ks < 8; ks++) {
        int cur = ks & 1, nxt = cur ^ 1;
        if (ks < 7) {
            uint32_t ko = (uint32_t)(ks + 1) * 32;
            LDSM4(Ah[nxt][0], ah + aoff + ko); LDSM4(Ah[nxt][1], ah + aoff + 16*RSB + ko);
            LDSM4(Al[nxt][0], al + aoff + ko); LDSM4(Al[nxt][1], al + aoff + 16*RSB + ko);
            LDSM4(Bh[nxt][0], bh + boff + ko); LDSM4(Bh[nxt][1], bh + boff + 16*RSB + ko);
        }
#pragma unroll
        for (int mt = 0; mt < 2; mt++)
#pragma unroll
            for (int bt = 0; bt < 2; bt++) {
                MMA16816(acc[mt][2*bt],   Ah[cur][mt], Bh[cur][bt][0], Bh[cur][bt][2]);
                MMA16816(acc[mt][2*bt+1], Ah[cur][mt], Bh[cur][bt][1], Bh[cur][bt][3]);
                MMA16816(acc[mt][2*bt],   Al[cur][mt], Bh[cur][bt][0], Bh[cur][bt][2]);
                MMA16816(acc[mt][2*bt+1], Al[cur][mt], Bh[cur][bt][1], Bh[cur][bt][3]);
            }
    }
}

#define A64 (64*RSB)         // 17408
#define TILE_B (128*RSB)     // 34816
#define O64_AH 0
#define O64_AL A64
#define O64_BH (2*A64)
#define SM_G2 (2*A64 + TILE_B)           // 69632 -> 3 CTAs/SM
#define OT_SH (2*A64 + TILE_B)
#define OT_SL (OT_SH + A64)
#define SM_TOPIC (OT_SL + A64 + 256)     // 104704 -> 2 CTAs/SM
#define OM_BH (2*A64)
#define OM_BL (2*A64 + TILE_B)
#define SM_MLP (2*A64 + 2*TILE_B)        // 104448 -> 2 CTAs/SM

// ---------------- K1: layernorm -> g_qzn fp32 + hi/lo bf16 ----------------
__global__ __launch_bounds__(256) void k_ln(const float* __restrict__ x,
                                            const float* __restrict__ gw,
                                            const float* __restrict__ gb) {
    int w = (blockIdx.x * 256 + threadIdx.x) >> 5;
    int lane = threadIdx.x & 31;
    if (w >= NTOK) return;
    const float2* xr = (const float2*)(x + (size_t)w * DD);
    float2 v0 = xr[lane], v1 = xr[lane + 32];
    float s = v0.x + v0.y + v1.x + v1.y;
#pragma unroll
    for (int o = 16; o; o >>= 1) s += __shfl_xor_sync(0xffffffffu, s, o);
    float mu = s * (1.0f/128.0f);
    float q = (v0.x-mu)*(v0.x-mu) + (v0.y-mu)*(v0.y-mu)
            + (v1.x-mu)*(v1.x-mu) + (v1.y-mu)*(v1.y-mu);
#pragma unroll
    for (int o = 16; o; o >>= 1) q += __shfl_xor_sync(0xffffffffu, q, o);
    float inv = rsqrtf(q * (1.0f/128.0f) + 1e-5f);
    float2* yr = (float2*)(g_qzn + (size_t)w * DD);
    uint32_t* yh = (uint32_t*)(g_qzn_h + (size_t)w * DD);
    uint32_t* yl = (uint32_t*)(g_qzn_l + (size_t)w * DD);
#pragma unroll
    for (int j = 0; j < 2; j++) {
        float2 v = j ? v1 : v0;
        int dp = lane + 32*j;
        float y0 = (v.x-mu)*inv*gw[2*dp]   + gb[2*dp];
        float y1 = (v.y-mu)*inv*gw[2*dp+1] + gb[2*dp+1];
        yr[dp] = make_float2(y0, y1);
        uint32_t hp, lp;
        split2(y0, y1, hp, lp);
        yh[dp] = hp; yl[dp] = lp;
    }
}

// ---------------- K1b: split/convert static GEMM operands -------------------
#define N2_BIN (BB*GG*DD/2)
#define N2_W   (BB*DD*DD/2)
#define N2_MW  (DD*DD/2)
#define N2_TOT (N2_BIN + 4*N2_W)
__global__ __launch_bounds__(256) void k_split_all(const float* __restrict__ bin,
                                                   const float* __restrict__ tu,
                                                   const float* __restrict__ tv,
                                                   const float* __restrict__ cu,
                                                   const float* __restrict__ cv) {
    int i = blockIdx.x * 256 + threadIdx.x;
    if (i >= N2_TOT) return;
    const float* src; uint32_t* dh; int off;
    if (i < N2_BIN) {
        src = bin; dh = (uint32_t*)g_binN_h; off = i;
    } else {
        int j = i - N2_BIN, pj = j / N2_W; off = j % N2_W;
        src = (pj == 0) ? tu : (pj == 1) ? tv : (pj == 2) ? cu : cv;
        dh = (uint32_t*)g_wp_h + (size_t)pj * N2_W;
    }
    float2 v = ((const float2*)src)[off];
    dh[off] = hi2(v.x, v.y);
}
__global__ __launch_bounds__(256) void k_split_mw(const float* __restrict__ w1,
                                                  const float* __restrict__ w2) {
    int i = blockIdx.x * 256 + threadIdx.x;
    if (i >= 2*N2_MW) return;
    const float* src = (i < N2_MW) ? w1 : w2;
    uint32_t* dh = (i < N2_MW) ? (uint32_t*)g_w1_h : (uint32_t*)g_w2_h;
    uint32_t* dl = (i < N2_MW) ? (uint32_t*)g_w1_l : (uint32_t*)g_w2_l;
    int off = (i < N2_MW) ? i : i - N2_MW;
    float2 v = ((const float2*)src)[off];
    uint32_t hp, lp; split2(v.x, v.y, hp, lp);
    dh[off] = hp; dl[off] = lp;
}

// ---------------- K1c: transpose topic_binary -> g_binT_h [b][d][g] ---------
#define TSTR 129
__global__ __launch_bounds__(256) void k_binT(const float* __restrict__ bin) {
    extern __shared__ float smf[];
    int gt = blockIdx.x, b = blockIdx.y;
    int tid = threadIdx.x;
    const float* src = bin + ((size_t)b * GG + (size_t)gt * 128) * DD;
    for (int i = tid; i < 128*128; i += 256) {
        int g = i >> 7, d = i & 127;
        smf[g*TSTR + d] = src[i];
    }
    __syncthreads();
    uint32_t* oh = (uint32_t*)(g_binT_h + (size_t)b * DD * GG + (size_t)gt * 128);
    for (int i = tid; i < 128*64; i += 256) {
        int d = i >> 6, gp = i & 63;
        float v0 = smf[(2*gp)*TSTR + d], v1 = smf[(2*gp+1)*TSTR + d];
        size_t o = ((size_t)d * GG) / 2 + gp;
        oh[o] = hi2(v0, v1);
    }
}

// ---------------- K2: projection GEMMs (2-product), 3 CTAs/SM --------------
__global__ __launch_bounds__(256, 3) void k_gemm1() {
    extern __shared__ char sm[];
    uint32_t smb = smem_u32(sm);
    int tid = threadIdx.x, wid = tid >> 5, lane = tid & 31;
    int wm = wid & 1, wn = wid >> 1;
    int tile = blockIdx.x, pj = blockIdx.y, b = blockIdx.z;
    size_t tokbase = (size_t)b * TPB + (size_t)tile * 64;
    copy_rows((const uint32_t*)(g_qzn_h + tokbase * DD),
              (const uint32_t*)(g_qzn_l + tokbase * DD),
              64, 64, sm + O64_AH, sm + O64_AL, tid);
    const uint32_t* bh = (const uint32_t*)g_wp_h + ((size_t)pj * BB + b) * (DD*DD/2);
    copy_rows1(bh, 128, 64, sm + O64_BH, tid);
    __syncthreads();
    float acc[2][4][4];
#pragma unroll
    for (int mt = 0; mt < 2; mt++)
#pragma unroll
        for (int nt = 0; nt < 4; nt++)
#pragma unroll
            for (int j = 0; j < 4; j++) acc[mt][nt][j] = 0.f;
    mm64_2p(smb + O64_AH, smb + O64_AL, smb + O64_BH, lane, wm, wn, acc);
    float* y = (pj == 0) ? g_qut : (pj == 1) ? g_qvt : (pj == 2) ? g_quc : g_qvc;
#pragma unroll
    for (int mt = 0; mt < 2; mt++)
#pragma unroll
        for (int h = 0; h < 2; h++) {
            int row = wm*32 + mt*16 + (lane >> 2) + 8*h;
            float* yr = y + (tokbase + row) * DD;
#pragma unroll
            for (int nt = 0; nt < 4; nt++) {
                int col = wn*32 + nt*8 + (lane & 3)*2;
                *(float2*)&yr[col] = make_float2(acc[mt][nt][2*h], acc[mt][nt][2*h+1]);
            }
        }
}

// ---------------- K4: fused topic (S GEMM + normalize GEMM) + combine -------
__global__ __launch_bounds__(256, 2) void k_topic(const float* __restrict__ un,
                                                  const float* __restrict__ old,
                                                  float* __restrict__ out) {
    extern __shared__ char sm[];
    uint32_t smb = smem_u32(sm);
    float* rs = (float*)(sm + OT_SL + A64);
    int tid = threadIdx.x, wid = tid >> 5, lane = tid & 31;
    int wm = wid & 1, wn = wid >> 1;
    int tile = blockIdx.x, b = blockIdx.y;
    size_t btok = (size_t)b * TPB + (size_t)tile * 64;
    copy_rows((const uint32_t*)(g_qzn_h + btok * DD),
              (const uint32_t*)(g_qzn_l + btok * DD),
              64, 64, sm + O64_AH, sm + O64_AL, tid);
    if (tid < 64) rs[tid] = 0.f;

    float acc2[2][4][4];
#pragma unroll
    for (int mt = 0; mt < 2; mt++)
#pragma unroll
        for (int nt = 0; nt < 4; nt++)
#pragma unroll
            for (int j = 0; j < 4; j++) acc2[mt][nt][j] = 0.f;

    for (int gc = 0; gc < 4; gc++) {
        __syncthreads();
        copy_rows1((const uint32_t*)g_binN_h + ((size_t)b * GG + (size_t)gc * 128) * (DD/2),
                   128, 64, sm + O64_BH, tid);
        __syncthreads();
        float acc1[2][4][4];
#pragma unroll
        for (int mt = 0; mt < 2; mt++)
#pragma unroll
            for (int nt = 0; nt < 4; nt++)
#pragma unroll
                for (int j = 0; j < 4; j++) acc1[mt][nt][j] = 0.f;
        mm64_2p(smb + O64_AH, smb + O64_AL, smb + O64_BH, lane, wm, wn, acc1);
        __syncthreads();
#pragma unroll
        for (int mt = 0; mt < 2; mt++)
#pragma unroll
            for (int h = 0; h < 2; h++) {
                int row = wm*32 + mt*16 + (lane >> 2) + 8*h;
                float part = 0.f;
#pragma unroll
                for (int nt = 0; nt < 4; nt++) {
                    int col = wn*32 + nt*8 + (lane & 3)*2;
                    float f0 = fmaxf(acc1[mt][nt][2*h], 0.f);
                    float f1 = fmaxf(acc1[mt][nt][2*h+1], 0.f);
                    part += f0 + f1;
                    uint32_t hp, lp;
                    split2(f0, f1, hp, lp);
                    *(uint32_t*)(sm + OT_SH + row*RSB + 2*col) = hp;
                    *(uint32_t*)(sm + OT_SL + row*RSB + 2*col) = lp;
                }
                atomicAdd(&rs[row], part);
            }
        copy_rows1((const uint32_t*)g_binT_h + (size_t)b * (DD*GG/2) + gc*64,
                   128, GG/2, sm + O64_BH, tid);
        __syncthreads();
        mm64_2p(smb + OT_SH, smb + OT_SL, smb + O64_BH, lane, wm, wn, acc2);
    }
    __syncthreads();
#pragma unroll
    for (int mt = 0; mt < 2; mt++)
#pragma unroll
        for (int h = 0; h < 2; h++) {
            int row = wm*32 + mt*16 + (lane >> 2) + 8*h;
            float inv = 1.0f / fmaxf(rs[row], 1e-6f);
            size_t rbase = (btok + row) * DD;
#pragma unroll
            for (int nt = 0; nt < 4; nt++) {
                int col = wn*32 + nt*8 + (lane & 3)*2;
                float2 m = *(const float2*)&g_msg[rbase + col];
                float2 u = *(const float2*)&un[rbase + col];
                float2 o = *(const float2*)&old[rbase + col];
                float2 r;
                r.x = 0.5f*(u.x + o.x + m.x + acc2[mt][nt][2*h]   * inv);
                r.y = 0.5f*(u.y + o.y + m.y + acc2[mt][nt][2*h+1] * inv);
                *(float2*)&out[rbase + col] = r;
            }
        }
}

// ---------------- K5: tensorized time attention -----------------------------
// Logits via mma.sync per head (3-product) -> L smem -> softmax (poly exp)
// accumulating sum_h probs in fp32 As -> split -> AV via mma.sync (3-product).
#define XTSTR 208
#define LSTR 100
#define T2_QUH 0
#define T2_QUL 26112
#define T2_QVH 52224
#define T2_QVL 78848
#define T2_L   105472
#define T2_AS  143872
#define SM_TATTN2 181504
#define T2_ASH T2_QUH
#define T2_ASL T2_QUL
#define T2_XTH T2_QVH
#define T2_XTL T2_QVL

__global__ __launch_bounds__(256, 1) void k_tattn() {
    extern __shared__ char sm[];
    uint32_t smb = smem_u32(sm);
    float* L  = (float*)(sm + T2_L);
    float* As = (float*)(sm + T2_AS);
    int tid = threadIdx.x, wid = tid >> 5, lane = tid & 31;
    int wm = wid & 1, wn = wid >> 1;
    int r16 = lane & 15;
    size_t base = (size_t)blockIdx.x * PP * DD;

    // fill Qu hi/lo + Qv hi/lo bf16 tiles
    for (int i = tid; i < PP*64; i += 256) {
        int p = i >> 6, c = i & 63;
        float2 u = *(const float2*)&g_qut[base + (size_t)p*DD + 2*c];
        float2 v = *(const float2*)&g_qvt[base + (size_t)p*DD + 2*c];
        uint32_t hp, lp;
        split2(u.x, u.y, hp, lp);
        *(uint32_t*)(sm + T2_QUH + p*RSB + 4*c) = hp;
        *(uint32_t*)(sm + T2_QUL + p*RSB + 4*c) = lp;
        split2(v.x, v.y, hp, lp);
        *(uint32_t*)(sm + T2_QVH + p*RSB + 4*c) = hp;
        *(uint32_t*)(sm + T2_QVL + p*RSB + 4*c) = lp;
    }
    // zero As (thread-owned cells)
#pragma unroll
    for (int k = 0; k < 12; k++)
#pragma unroll
        for (int j = 0; j < 3; j++)
            As[(wid + 8*k)*ASTR + lane + 32*j] = 0.f;

    for (int h = 0; h < HH; h++) {
        __syncthreads();   // fills visible / prev softmax reads of L done
        if (wn < 3) {
            uint32_t ko = (uint32_t)h*32 + ((lane >> 4) << 4);
            uint32_t Ah[3][4], Al[3][4], Bh[2][4], Bl[2][4];
#pragma unroll
            for (int mt = 0; mt < 3; mt++) {
                uint32_t ar = (uint32_t)(wm*48 + mt*16 + r16)*RSB + ko;
                LDSM4(Ah[mt], smb + T2_QUH + ar);
                LDSM4(Al[mt], smb + T2_QUL + ar);
            }
#pragma unroll
            for (int bt = 0; bt < 2; bt++) {
                uint32_t br = (uint32_t)(wn*32 + bt*16 + r16)*RSB + ko;
                LDSM4(Bh[bt], smb + T2_QVH + br);
                LDSM4(Bl[bt], smb + T2_QVL + br);
            }
            float acc[3][4][4];
#pragma unroll
            for (int mt = 0; mt < 3; mt++)
#pragma unroll
                for (int nt = 0; nt < 4; nt++)
#pragma unroll
                    for (int j = 0; j < 4; j++) acc[mt][nt][j] = 0.f;
#pragma unroll
            for (int mt = 0; mt < 3; mt++)
#pragma unroll
                for (int bt = 0; bt < 2; bt++) {
                    MMA16816(acc[mt][2*bt],   Ah[mt], Bh[bt][0], Bh[bt][2]);
                    MMA16816(acc[mt][2*bt+1], Ah[mt], Bh[bt][1], Bh[bt][3]);
                    MMA16816(acc[mt][2*bt],   Ah[mt], Bl[bt][0], Bl[bt][2]);
                    MMA16816(acc[mt][2*bt+1], Ah[mt], Bl[bt][1], Bl[bt][3]);
                    MMA16816(acc[mt][2*bt],   Al[mt], Bh[bt][0], Bh[bt][2]);
                    MMA16816(acc[mt][2*bt+1], Al[mt], Bh[bt][1], Bh[bt][3]);
                }
#pragma unroll
            for (int mt = 0; mt < 3; mt++)
#pragma unroll
                for (int hh = 0; hh < 2; hh++) {
                    int row = wm*48 + mt*16 + (lane >> 2) + 8*hh;
#pragma unroll
                    for (int nt = 0; nt < 4; nt++) {
                        int col = wn*32 + nt*8 + (lane & 3)*2;
                        *(float2*)&L[row*LSTR + col] =
                            make_float2(acc[mt][nt][2*hh], acc[mt][nt][2*hh+1]);
                    }
                }
        }
        __syncthreads();   // L complete
        // softmax: warp wid owns rows wid+8*pr
#pragma unroll 1
        for (int pr = 0; pr < 12; pr++) {
            int p = wid + 8*pr;
            float lg0 = L[p*LSTR + lane]      * 0.25f;
            float lg1 = L[p*LSTR + lane + 32] * 0.25f;
            float lg2 = L[p*LSTR + lane + 64] * 0.25f;
            float e0 = fexp(lg0), e1 = fexp(lg1), e2 = fexp(lg2);
            float ssum = e0 + e1 + e2;
#pragma unroll
            for (int o = 16; o; o >>= 1) ssum += __shfl_xor_sync(0xffffffffu, ssum, o);
            float inv = 0.125f / ssum;
            As[p*ASTR + lane]      += e0 * inv;
            As[p*ASTR + lane + 32] += e1 * inv;
            As[p*ASTR + lane + 64] += e2 * inv;
        }
    }
    __syncthreads();   // As complete; Qu/Qv/L regions free

    // As -> hi/lo bf16 tiles (over old Qu tiles)
    for (int i = tid; i < PP*48; i += 256) {
        int p = i / 48, c2 = i % 48;
        float a0 = As[p*ASTR + 2*c2], a1 = As[p*ASTR + 2*c2 + 1];
        uint32_t hp, lp;
        split2(a0, a1, hp, lp);
        *(uint32_t*)(sm + T2_ASH + p*RSB + 4*c2) = hp;
        *(uint32_t*)(sm + T2_ASL + p*RSB + 4*c2) = lp;
    }
    // X^T hi/lo tiles [d][q] (over old Qv tiles)
    for (int i = tid; i < PP*64; i += 256) {
        int q = i >> 6, c = i & 63;
        float2 x = *(const float2*)&g_qzn[base + (size_t)q*DD + 2*c];
        uint32_t hp, lp;
        split2(x.x, x.y, hp, lp);
        *(unsigned short*)(sm + T2_XTH + (2*c)*XTSTR + 2*q)   = (unsigned short)(hp & 0xffff);
        *(unsigned short*)(sm + T2_XTH + (2*c+1)*XTSTR + 2*q) = (unsigned short)(hp >> 16);
        *(unsigned short*)(sm + T2_XTL + (2*c)*XTSTR + 2*q)   = (unsigned short)(lp & 0xffff);
        *(unsigned short*)(sm + T2_XTL + (2*c+1)*XTSTR + 2*q) = (unsigned short)(lp >> 16);
    }
    __syncthreads();

    // AV: C[96,128] = As[96,96] @ X[96,128]; B = X^T tiles, 6 k-steps
    float acc[3][4][4];
#pragma unroll
    for (int mt = 0; mt < 3; mt++)
#pragma unroll
        for (int nt = 0; nt < 4; nt++)
#pragma unroll
            for (int j = 0; j < 4; j++) acc[mt][nt][j] = 0.f;
    uint32_t klane = (lane >> 4) << 4;
#pragma unroll
    for (int ks = 0; ks < 6; ks++) {
        uint32_t ko = (uint32_t)ks*32 + klane;
        uint32_t Ah[3][4], Al[3][4], Bh[2][4], Bl[2][4];
#pragma unroll
        for (int mt = 0; mt < 3; mt++) {
            uint32_t ar = (uint32_t)(wm*48 + mt*16 + r16)*RSB + ko;
            LDSM4(Ah[mt], smb + T2_ASH + ar);
            LDSM4(Al[mt], smb + T2_ASL + ar);
        }
#pragma unroll
        for (int bt = 0; bt < 2; bt++) {
            uint32_t br = (uint32_t)(wn*32 + bt*16 + r16)*XTSTR + ko;
            LDSM4(Bh[bt], smb + T2_XTH + br);
            LDSM4(Bl[bt], smb + T2_XTL + br);
        }
#pragma unroll
        for (int mt = 0; mt < 3; mt++)
#pragma unroll
            for (int bt = 0; bt < 2; bt++) {
                MMA16816(acc[mt][2*bt],   Ah[mt], Bh[bt][0], Bh[bt][2]);
                MMA16816(acc[mt][2*bt+1], Ah[mt], Bh[bt][1], Bh[bt][3]);
                MMA16816(acc[mt][2*bt],   Ah[mt], Bl[bt][0], Bl[bt][2]);
                MMA16816(acc[mt][2*bt+1], Ah[mt], Bl[bt][1], Bl[bt][3]);
                MMA16816(acc[mt][2*bt],   Al[mt], Bh[bt][0], Bh[bt][2]);
                MMA16816(acc[mt][2*bt+1], Al[mt], Bh[bt][1], Bh[bt][3]);
            }
    }
#pragma unroll
    for (int mt = 0; mt < 3; mt++)
#pragma unroll
        for (int hh = 0; hh < 2; hh++) {
            int row = wm*48 + mt*16 + (lane >> 2) + 8*hh;
            float* mr = g_msg + base + (size_t)row*DD;
#pragma unroll
            for (int nt = 0; nt < 4; nt++) {
                int col = wn*32 + nt*8 + (lane & 3)*2;
                *(float2*)&mr[col] = make_float2(acc[mt][nt][2*hh], acc[mt][nt][2*hh+1]);
            }
        }
}

// ---------------- K6: channel attention (poly exp) -> g_msg += ----------------
#define SM_CATTN (3*128*PSTR*4)
__global__ __launch_bounds__(256) void k_cattn() {
    extern __shared__ float smf[];
    float* Qu = smf;
    float* Qv = Qu + 128*PSTR;
    float* Ac = Qv + 128*PSTR;
    int b = blockIdx.x / PP, p = blockIdx.x % PP;
    int tid = threadIdx.x, lane = tid & 31, wg = tid >> 5;
    for (int i = tid; i < CC*DD; i += 256) {
        int c = i >> 7, d = i & 127;
        size_t gi = (((size_t)b*CC + c)*PP + p)*DD + d;
        Qu[c*PSTR+d] = g_quc[gi];
        Qv[c*PSTR+d] = g_qvc[gi];
        Ac[c*PSTR+d] = 0.f;
    }
    __syncthreads();
    for (int h = 0; h < HH; h++) {
        int ho = h*16;
#pragma unroll 1
        for (int cr = 0; cr < 16; cr++) {
            int c = wg + 8*cr;
            u64 qu2[8];
#pragma unroll
            for (int r = 0; r < 8; r++) qu2[r] = *(const u64*)&Qu[c*PSTR + ho + 2*r];
            float lg[4];
#pragma unroll
            for (int j = 0; j < 4; j++) {
                int d = lane + 32*j;
                u64 s2 = 0ull;
#pragma unroll
                for (int r = 0; r < 8; r++) {
                    u64 qv2 = *(const u64*)&Qv[d*PSTR + ho + 2*r];
                    s2 = fma2(qu2[r], qv2, s2);
                }
                float2 sp = up2(s2);
                lg[j] = (sp.x + sp.y) * 0.25f;
            }
            float e[4], ssum = 0.f;
#pragma unroll
            for (int j = 0; j < 4; j++) { e[j] = fexp(lg[j]); ssum += e[j]; }
#pragma unroll
            for (int o = 16; o; o >>= 1) ssum += __shfl_xor_sync(0xffffffffu, ssum, o);
            float inv = 0.125f / ssum;
#pragma unroll
            for (int j = 0; j < 4; j++) Ac[c*PSTR + lane + 32*j] += e[j] * inv;
        }
    }
#pragma unroll
    for (int cr = 0; cr < 16; cr++) {
        int c = wg + 8*cr;
#pragma unroll
        for (int j = 0; j < 4; j++) {
            int d = lane + 32*j;
            size_t gi = (((size_t)b*CC + c)*PP + p)*DD + d;
            g_msg[gi] += Ac[c*PSTR+d] * g_qzn[gi];
        }
    }
}

// ---------------- K7: fused MLP: LN + GEMM1 + gelu + GEMM2 + residual -------
__global__ __launch_bounds__(256, 2) void k_mlp(float* __restrict__ io,
                                                const float* __restrict__ gw,
                                                const float* __restrict__ gb,
                                                const float* __restrict__ b1,
                                                const float* __restrict__ b2) {
    extern __shared__ char sm[];
    uint32_t smb = smem_u32(sm);
    int tid = threadIdx.x, wid = tid >> 5, lane = tid & 31;
    int wm = wid & 1, wn = wid >> 1;
    size_t tokbase = (size_t)blockIdx.x * 64;
    copy_rows((const uint32_t*)g_w1_h, (const uint32_t*)g_w1_l,
              128, 64, sm + OM_BH, sm + OM_BL, tid);
#pragma unroll 1
    for (int it = 0; it < 8; it++) {
        int t = wid + 8*it;
        const float2* xr = (const float2*)(io + (tokbase + t) * DD);
        float2 v0 = xr[lane], v1 = xr[lane + 32];
        float s = v0.x + v0.y + v1.x + v1.y;
#pragma unroll
        for (int o = 16; o; o >>= 1) s += __shfl_xor_sync(0xffffffffu, s, o);
        float mu = s * (1.0f/128.0f);
        float q = (v0.x-mu)*(v0.x-mu) + (v0.y-mu)*(v0.y-mu)
                + (v1.x-mu)*(v1.x-mu) + (v1.y-mu)*(v1.y-mu);
#pragma unroll
        for (int o = 16; o; o >>= 1) q += __shfl_xor_sync(0xffffffffu, q, o);
        float inv = rsqrtf(q * (1.0f/128.0f) + 1e-5f);
#pragma unroll
        for (int j = 0; j < 2; j++) {
            float2 v = j ? v1 : v0;
            int dp = lane + 32*j;
            float y0 = (v.x-mu)*inv*gw[2*dp]   + gb[2*dp];
            float y1 = (v.y-mu)*inv*gw[2*dp+1] + gb[2*dp+1];
            uint32_t hp, lp;
            split2(y0, y1, hp, lp);
            *(uint32_t*)(sm + O64_AH + t*RSB + 4*dp) = hp;
            *(uint32_t*)(sm + O64_AL + t*RSB + 4*dp) = lp;
        }
    }
    __syncthreads();
    float acc[2][4][4];
#pragma unroll
    for (int mt = 0; mt < 2; mt++)
#pragma unroll
        for (int nt = 0; nt < 4; nt++)
#pragma unroll
            for (int j = 0; j < 4; j++) acc[mt][nt][j] = 0.f;
    mm64(smb + O64_AH, smb + O64_AL, smb + OM_BH, smb + OM_BL, lane, wm, wn, acc);
    __syncthreads();
#pragma unroll
    for (int mt = 0; mt < 2; mt++)
#pragma unroll
        for (int h = 0; h < 2; h++) {
            int row = wm*32 + mt*16 + (lane >> 2) + 8*h;
#pragma unroll
            for (int nt = 0; nt < 4; nt++) {
                int col = wn*32 + nt*8 + (lane & 3)*2;
                float2 bv = *(const float2*)&b1[col];
                float x0 = acc[mt][nt][2*h]   + bv.x;
                float x1 = acc[mt][nt][2*h+1] + bv.y;
                float g0 = 0.5f * x0 * (1.0f + erff(x0 * 0.70710678118654752f));
                float g1 = 0.5f * x1 * (1.0f + erff(x1 * 0.70710678118654752f));
                uint32_t hp, lp;
                split2(g0, g1, hp, lp);
                *(uint32_t*)(sm + O64_AH + row*RSB + 2*col) = hp;
                *(uint32_t*)(sm + O64_AL + row*RSB + 2*col) = lp;
            }
        }
    copy_rows((const uint32_t*)g_w2_h, (const uint32_t*)g_w2_l,
              128, 64, sm + OM_BH, sm + OM_BL, tid);
    __syncthreads();
    float acc2[2][4][4];
#pragma unroll
    for (int mt = 0; mt < 2; mt++)
#pragma unroll
        for (int nt = 0; nt < 4; nt++)
#pragma unroll
            for (int j = 0; j < 4; j++) acc2[mt][nt][j] = 0.f;
    mm64(smb + O64_AH, smb + O64_AL, smb + OM_BH, smb + OM_BL, lane, wm, wn, acc2);
#pragma unroll
    for (int mt = 0; mt < 2; mt++)
#pragma unroll
        for (int h = 0; h < 2; h++) {
            int row = wm*32 + mt*16 + (lane >> 2) + 8*h;
            float* ir = io + (tokbase + row) * DD;
#pragma unroll
            for (int nt = 0; nt < 4; nt++) {
                int col = wn*32 + nt*8 + (lane & 3)*2;
                float2 bv = *(const float2*)&b2[col];
                float2 v = *(float2*)&ir[col];
                v.x += acc2[mt][nt][2*h]   + bv.x;
                v.y += acc2[mt][nt][2*h+1] + bv.y;
                *(float2*)&ir[col] = v;
            }
        }
}

// ---------------- host launcher ----------------
extern "C" void kernel_launch(void* const* d_in, const int* in_sizes, int n_in,
                              void* d_out, int out_size) {
    (void)in_sizes; (void)n_in; (void)out_size;
    const float* qz  = (const float*)d_in[0];
    const float* un  = (const float*)d_in[1];
    const float* tu  = (const float*)d_in[2];
    const float* tv  = (const float*)d_in[3];
    const float* cu  = (const float*)d_in[4];
    const float* cv  = (const float*)d_in[5];
    const float* bin = (const float*)d_in[6];
    const float* lng = (const float*)d_in[7];
    const float* lnb = (const float*)d_in[8];
    const float* w1  = (const float*)d_in[9];
    const float* b1  = (const float*)d_in[10];
    const float* w2  = (const float*)d_in[11];
    const float* b2  = (const float*)d_in[12];
    float* out = (float*)d_out;

    cudaFuncSetAttribute(k_binT,  cudaFuncAttributeMaxDynamicSharedMemorySize, 128*TSTR*4);
    cudaFuncSetAttribute(k_gemm1, cudaFuncAttributeMaxDynamicSharedMemorySize, SM_G2);
    cudaFuncSetAttribute(k_topic, cudaFuncAttributeMaxDynamicSharedMemorySize, SM_TOPIC);
    cudaFuncSetAttribute(k_tattn, cudaFuncAttributeMaxDynamicSharedMemorySize, SM_TATTN2);
    cudaFuncSetAttribute(k_cattn, cudaFuncAttributeMaxDynamicSharedMemorySize, SM_CATTN);
    cudaFuncSetAttribute(k_mlp,   cudaFuncAttributeMaxDynamicSharedMemorySize, SM_MLP);

    k_ln<<<(NTOK*32)/256, 256>>>(qz, lng, lnb);
    k_split_all<<<(N2_TOT + 255)/256, 256>>>(bin, tu, tv, cu, cv);
    k_split_mw<<<(2*N2_MW + 255)/256, 256>>>(w1, w2);
    k_binT<<<dim3(4, BB), 256, 128*TSTR*4>>>(bin);

    dim3 g1(TPB/64, 4, BB);
    k_gemm1<<<g1, 256, SM_G2>>>();

    k_tattn<<<BB*CC, 256, SM_TATTN2>>>();
    k_cattn<<<BB*PP, 256, SM_CATTN>>>();

    dim3 og(TPB/64, BB);
    k_topic<<<og, 256, SM_TOPIC>>>(un, qz, out);

    k_mlp<<<NTOK/64, 256, SM_MLP>>>(out, lng, lnb, b1, b2);
}